// round 5
// baseline (speedup 1.0000x reference)
#include <cuda_runtime.h>
#include <cstddef>

// Problem constants
#define B_     16
#define C_     256
#define HID    128
#define NH     4
#define DH     32
#define NP     4096       // 64*64 spatial positions
#define QKV_CH 384

// Scratch (device globals: allocation-free rule)
__device__ float  g_qkv[(size_t)B_ * QKV_CH * NP];   // ~100.7 MB: qkv = w_qkv @ x
__device__ float2 g_kstat[B_ * HID];                  // per (b,h,d) k-row: (max, 1/sumexp)
__device__ float  g_ctxp[16 * 64 * 1024];             // context partials over 16 n-chunks
__device__ float  g_ctx [64 * 1024];                  // context [b*4+h][d][e]

// ---------------------------------------------------------------------------
// K1: qkv[b][o][p] = sum_c w_qkv[o][c] * x[b][c][p]
// SGEMM: M=384, N=4096, K=256 per batch. BM=128, BN=64, BK=16, 256 thr, 8x4/thr.
// ---------------------------------------------------------------------------
__global__ __launch_bounds__(256) void k_qkv_gemm(
    const float* __restrict__ x, const float* __restrict__ w)
{
    __shared__ float As[16][132];   // [k][m], padded
    __shared__ float Bs[16][64];    // [k][n]
    const int tid = threadIdx.x;
    const int ty = tid >> 4, tx = tid & 15;
    const int n0 = blockIdx.x * 64;
    const int m0 = blockIdx.y * 128;
    const int b  = blockIdx.z;
    const float* xb = x + (size_t)b * C_ * NP;
    float* outb = g_qkv + (size_t)b * QKV_CH * NP;

    float acc[8][4];
    #pragma unroll
    for (int i = 0; i < 8; i++)
        #pragma unroll
        for (int j = 0; j < 4; j++) acc[i][j] = 0.f;

    const int a_c4 = tid & 3;          // A: which float4 along k
    const int a_r  = (tid >> 2) * 2;   // A: base row (m)
    const int b_r  = tid >> 4;         // B: row (k)
    const int b_c4 = tid & 15;         // B: which float4 along n

    for (int k0 = 0; k0 < C_; k0 += 16) {
        #pragma unroll
        for (int i = 0; i < 2; i++) {
            const float4 a = *(const float4*)(w + (size_t)(m0 + a_r + i) * C_ + k0 + a_c4 * 4);
            As[a_c4 * 4 + 0][a_r + i] = a.x;
            As[a_c4 * 4 + 1][a_r + i] = a.y;
            As[a_c4 * 4 + 2][a_r + i] = a.z;
            As[a_c4 * 4 + 3][a_r + i] = a.w;
        }
        {
            const float4 v = *(const float4*)(xb + (size_t)(k0 + b_r) * NP + n0 + b_c4 * 4);
            *(float4*)&Bs[b_r][b_c4 * 4] = v;
        }
        __syncthreads();
        #pragma unroll
        for (int kk = 0; kk < 16; kk++) {
            const float4 a0 = *(const float4*)&As[kk][ty * 8];
            const float4 a1 = *(const float4*)&As[kk][ty * 8 + 4];
            const float4 bb = *(const float4*)&Bs[kk][tx * 4];
            const float av[8] = {a0.x, a0.y, a0.z, a0.w, a1.x, a1.y, a1.z, a1.w};
            const float bv[4] = {bb.x, bb.y, bb.z, bb.w};
            #pragma unroll
            for (int i = 0; i < 8; i++)
                #pragma unroll
                for (int j = 0; j < 4; j++) acc[i][j] += av[i] * bv[j];
        }
        __syncthreads();
    }
    #pragma unroll
    for (int i = 0; i < 8; i++) {
        *(float4*)(outb + (size_t)(m0 + ty * 8 + i) * NP + n0 + tx * 4) =
            make_float4(acc[i][0], acc[i][1], acc[i][2], acc[i][3]);
    }
}

// ---------------------------------------------------------------------------
// K2: per k-row (b, h*32+d): rowmax and 1/sum(exp(k - max)) over n=4096.
// One block per row (2048 rows), 256 threads x 16 values.
// ---------------------------------------------------------------------------
__global__ __launch_bounds__(256) void k_kstats()
{
    __shared__ float red[256];
    const int row = blockIdx.x;              // b*128 + (h*32+d)
    const int b = row >> 7, ko = row & 127;
    const float* base = g_qkv + (size_t)b * QKV_CH * NP + (size_t)(HID + ko) * NP;
    const int t = threadIdx.x;
    float vals[16];
    #pragma unroll
    for (int j = 0; j < 4; j++) {
        const float4 v = *(const float4*)(base + (j * 256 + t) * 4);
        vals[j * 4 + 0] = v.x; vals[j * 4 + 1] = v.y;
        vals[j * 4 + 2] = v.z; vals[j * 4 + 3] = v.w;
    }
    float m = vals[0];
    #pragma unroll
    for (int i = 1; i < 16; i++) m = fmaxf(m, vals[i]);
    red[t] = m; __syncthreads();
    for (int off = 128; off > 0; off >>= 1) {
        if (t < off) red[t] = fmaxf(red[t], red[t + off]);
        __syncthreads();
    }
    m = red[0];
    __syncthreads();
    float s = 0.f;
    #pragma unroll
    for (int i = 0; i < 16; i++) s += __expf(vals[i] - m);
    red[t] = s; __syncthreads();
    for (int off = 128; off > 0; off >>= 1) {
        if (t < off) red[t] += red[t + off];
        __syncthreads();
    }
    if (t == 0) g_kstat[row] = make_float2(m, 1.f / red[0]);
}

// ---------------------------------------------------------------------------
// K3: context partials. ctx[b,h][d][e] = sum_n softmax_n(k)[d,n] * (v[e,n]/4096)
// Grid (16 n-chunks of 256, 64 bh). 256 thr, 2x2 micro-tile over (d,e).
// ---------------------------------------------------------------------------
__global__ __launch_bounds__(256) void k_context()
{
    __shared__ float ks[32][65];
    __shared__ float vs[32][65];
    const int ch = blockIdx.x;     // 0..15
    const int z  = blockIdx.y;     // 0..63 = b*4+h
    const int b = z >> 2, h = z & 3;
    const float* kbase = g_qkv + (size_t)b * QKV_CH * NP + (size_t)(HID + h * DH) * NP;
    const float* vbase = g_qkv + (size_t)b * QKV_CH * NP + (size_t)(2 * HID + h * DH) * NP;
    const int t = threadIdx.x;
    const int lrow = t >> 3;            // 0..31: smem row this thread loads
    const int lc0  = (t & 7) * 4;
    const float2 st = g_kstat[b * HID + h * DH + lrow];
    const float kmax = st.x, kinv = st.y;
    const int ty = t >> 4, tx = t & 15;
    const int d0 = ty * 2, e0 = tx * 2;
    float a00 = 0, a01 = 0, a10 = 0, a11 = 0;

    for (int tile = 0; tile < 4; tile++) {
        const int n0 = ch * 256 + tile * 64;
        #pragma unroll
        for (int jj = 0; jj < 2; jj++) {
            const int c = lc0 + jj * 32;
            const float4 kv = *(const float4*)(kbase + (size_t)lrow * NP + n0 + c);
            ks[lrow][c + 0] = __expf(kv.x - kmax) * kinv;
            ks[lrow][c + 1] = __expf(kv.y - kmax) * kinv;
            ks[lrow][c + 2] = __expf(kv.z - kmax) * kinv;
            ks[lrow][c + 3] = __expf(kv.w - kmax) * kinv;
            const float4 vv = *(const float4*)(vbase + (size_t)lrow * NP + n0 + c);
            vs[lrow][c + 0] = vv.x * (1.f / 4096.f);
            vs[lrow][c + 1] = vv.y * (1.f / 4096.f);
            vs[lrow][c + 2] = vv.z * (1.f / 4096.f);
            vs[lrow][c + 3] = vv.w * (1.f / 4096.f);
        }
        __syncthreads();
        #pragma unroll
        for (int nn = 0; nn < 64; nn++) {
            const float k0v = ks[d0][nn], k1v = ks[d0 + 1][nn];
            const float v0  = vs[e0][nn], v1  = vs[e0 + 1][nn];
            a00 += k0v * v0; a01 += k0v * v1;
            a10 += k1v * v0; a11 += k1v * v1;
        }
        __syncthreads();
    }
    float* o = g_ctxp + ((size_t)ch * 64 + z) * 1024;
    o[d0 * 32 + e0]           = a00;
    o[d0 * 32 + e0 + 1]       = a01;
    o[(d0 + 1) * 32 + e0]     = a10;
    o[(d0 + 1) * 32 + e0 + 1] = a11;
}

// Deterministic reduce of the 16 chunk partials.
__global__ void k_ctx_reduce()
{
    const int i = blockIdx.x * 256 + threadIdx.x;   // 0..65535
    float s = 0.f;
    #pragma unroll
    for (int ch = 0; ch < 16; ch++) s += g_ctxp[(size_t)ch * 65536 + i];
    g_ctx[i] = s;
}

// ---------------------------------------------------------------------------
// K4: fused final stage, per (b, 16-position tile):
//   q-softmax over d (local) * SCALE -> attn = ctx^T @ q -> y = w_out@attn + b
//   -> channel LayerNorm over 256 -> * g -> out.
// 256 threads; conv GEMM M=256 N=16 K=128 with 8x2 micro-tile.
// ---------------------------------------------------------------------------
__global__ __launch_bounds__(256) void k_out_fused(
    const float* __restrict__ w_out, const float* __restrict__ b_out,
    const float* __restrict__ g, float* __restrict__ out)
{
    __shared__ float sc[4][32][32];     // ctx for 4 heads
    __shared__ float sq[128][17];       // q (then softmaxed)
    __shared__ float sa[128][18];       // attn hidden activations
    __shared__ float sw[256][9];        // w_out tile [o][k-chunk of 8]
    __shared__ float redS[8][8][2];
    __shared__ float redQ[8][8][2];
    __shared__ float smu[16], srs[16];

    const int t  = threadIdx.x;
    const int p0 = blockIdx.x * 16;
    const int b  = blockIdx.y;
    const float* qb = g_qkv + (size_t)b * QKV_CH * NP;

    // load ctx (4096 floats)
    {
        const float* cb = g_ctx + (size_t)b * NH * 1024;
        float* scf = &sc[0][0][0];
        #pragma unroll
        for (int i = 0; i < 16; i++) scf[t + i * 256] = cb[t + i * 256];
    }
    // load raw q for these 16 positions: rows = h*32+d (128), cols = p (16)
    {
        const int row = t >> 1;
        const int c4b = (t & 1) * 2;
        #pragma unroll
        for (int jj = 0; jj < 2; jj++) {
            const float4 v = *(const float4*)(qb + (size_t)row * NP + p0 + (c4b + jj) * 4);
            const int c = (c4b + jj) * 4;
            sq[row][c] = v.x; sq[row][c + 1] = v.y; sq[row][c + 2] = v.z; sq[row][c + 3] = v.w;
        }
    }
    __syncthreads();

    // q softmax over d (32) per (h, p); fold in SCALE = 32^-0.5
    if (t < 64) {
        const int h = t >> 4, p = t & 15;
        float m = -3.402823e38f;
        #pragma unroll
        for (int d = 0; d < 32; d++) m = fmaxf(m, sq[h * 32 + d][p]);
        float s = 0.f;
        #pragma unroll
        for (int d = 0; d < 32; d++) s += __expf(sq[h * 32 + d][p] - m);
        const float inv = 0.17677669529663687f / s;
        #pragma unroll
        for (int d = 0; d < 32; d++) sq[h * 32 + d][p] = __expf(sq[h * 32 + d][p] - m) * inv;
    }
    __syncthreads();

    // attn[c=h*32+e][p] = sum_d ctx[h][d][e] * qs[h*32+d][p]
    {
        const int p = t & 15, cg = t >> 4;     // cg: 8 consecutive channels
        const int h  = cg >> 2;
        const int e0 = (cg & 3) * 8;
        float acc[8];
        #pragma unroll
        for (int i = 0; i < 8; i++) acc[i] = 0.f;
        #pragma unroll
        for (int d = 0; d < 32; d++) {
            const float qv = sq[h * 32 + d][p];
            #pragma unroll
            for (int i = 0; i < 8; i++) acc[i] += sc[h][d][e0 + i] * qv;
        }
        #pragma unroll
        for (int i = 0; i < 8; i++) sa[cg * 8 + i][p] = acc[i];
    }
    __syncthreads();

    // y[o][p] = sum_c w_out[o][c] * sa[c][p]
    const int ty = t >> 3, tx = t & 7;          // o rows ty*8.., p cols tx*2..
    float y[8][2];
    #pragma unroll
    for (int i = 0; i < 8; i++) { y[i][0] = 0.f; y[i][1] = 0.f; }
    for (int k0 = 0; k0 < 128; k0 += 8) {
        const float4 wa  = *(const float4*)(w_out + (size_t)t * HID + k0);
        const float4 wb2 = *(const float4*)(w_out + (size_t)t * HID + k0 + 4);
        sw[t][0] = wa.x;  sw[t][1] = wa.y;  sw[t][2] = wa.z;  sw[t][3] = wa.w;
        sw[t][4] = wb2.x; sw[t][5] = wb2.y; sw[t][6] = wb2.z; sw[t][7] = wb2.w;
        __syncthreads();
        #pragma unroll
        for (int kk = 0; kk < 8; kk++) {
            const int c = k0 + kk;
            const float b0 = sa[c][tx * 2], b1 = sa[c][tx * 2 + 1];
            #pragma unroll
            for (int i = 0; i < 8; i++) {
                const float a = sw[ty * 8 + i][kk];
                y[i][0] += a * b0;
                y[i][1] += a * b1;
            }
        }
        __syncthreads();
    }
    // bias
    #pragma unroll
    for (int i = 0; i < 8; i++) {
        const float bo = b_out[ty * 8 + i];
        y[i][0] += bo; y[i][1] += bo;
    }
    // LayerNorm stats over the 256 channels per position
    float s0 = 0, s1 = 0, q0 = 0, q1 = 0;
    #pragma unroll
    for (int i = 0; i < 8; i++) {
        s0 += y[i][0]; q0 += y[i][0] * y[i][0];
        s1 += y[i][1]; q1 += y[i][1] * y[i][1];
    }
    #pragma unroll
    for (int off = 8; off < 32; off <<= 1) {     // combine the 4 ty'-lanes per tx
        s0 += __shfl_xor_sync(0xffffffffu, s0, off);
        s1 += __shfl_xor_sync(0xffffffffu, s1, off);
        q0 += __shfl_xor_sync(0xffffffffu, q0, off);
        q1 += __shfl_xor_sync(0xffffffffu, q1, off);
    }
    const int warp = t >> 5, lane = t & 31;
    if (lane < 8) {
        redS[warp][lane][0] = s0; redS[warp][lane][1] = s1;
        redQ[warp][lane][0] = q0; redQ[warp][lane][1] = q1;
    }
    __syncthreads();
    if (t < 16) {   // p index = t; tx = t>>1, slot = t&1
        float s = 0, q = 0;
        #pragma unroll
        for (int w2 = 0; w2 < 8; w2++) {
            s += redS[w2][t >> 1][t & 1];
            q += redQ[w2][t >> 1][t & 1];
        }
        const float mu  = s * (1.f / 256.f);
        const float var = q * (1.f / 256.f) - mu * mu;
        smu[t] = mu;
        srs[t] = rsqrtf(var + 1e-5f);
    }
    __syncthreads();

    float* ob = out + (size_t)b * C_ * NP;
    #pragma unroll
    for (int i = 0; i < 8; i++) {
        const int o = ty * 8 + i;
        const float gg = g[o];
        const int pa = tx * 2;
        const float2 r = make_float2(
            (y[i][0] - smu[pa])     * srs[pa]     * gg,
            (y[i][1] - smu[pa + 1]) * srs[pa + 1] * gg);
        *(float2*)(ob + (size_t)o * NP + p0 + pa) = r;
    }
}

// ---------------------------------------------------------------------------
extern "C" void kernel_launch(void* const* d_in, const int* in_sizes, int n_in,
                              void* d_out, int out_size)
{
    const float* x     = (const float*)d_in[0];
    const float* w_qkv = (const float*)d_in[1];
    const float* w_out = (const float*)d_in[2];
    const float* b_out = (const float*)d_in[3];
    const float* g     = (const float*)d_in[4];
    float* out = (float*)d_out;
    (void)in_sizes; (void)n_in; (void)out_size;

    k_qkv_gemm<<<dim3(64, 3, 16), 256>>>(x, w_qkv);
    k_kstats<<<2048, 256>>>();
    k_context<<<dim3(16, 64), 256>>>();
    k_ctx_reduce<<<256, 256>>>();
    k_out_fused<<<dim3(256, 16), 256>>>(w_out, b_out, g, out);
}

// round 7
// speedup vs baseline: 1.2320x; 1.2320x over previous
#include <cuda_runtime.h>
#include <cuda_bf16.h>
#include <cstdint>
#include <cstddef>

// Problem constants
#define B_     16
#define C_     256
#define HID    128
#define NH     4
#define DH     32
#define NP     4096       // 64*64 spatial positions
#define QKV_CH 384
#define KB3    768        // split-K bf16: [hi(256) | lo(256) | hi(256)] for A, [hi|hi|lo] for B

// Scratch (device globals: allocation-free rule)
__device__ float  g_qkv[(size_t)B_ * QKV_CH * NP];   // qkv = w_qkv @ x (fp32)
__device__ float2 g_kstat[B_ * HID];
__device__ float  g_ctxp[16 * 64 * 1024];
__device__ float  g_ctx [64 * 1024];
__device__ __nv_bfloat16 g_wb[(size_t)QKV_CH * KB3];    // w_qkv split bf16, K-major
__device__ __nv_bfloat16 g_xb[(size_t)B_ * NP * KB3];   // x^T split bf16, K-major (~100MB)

// ---------------------------------------------------------------------------
// Portable PTX helpers (sm_80+ features only — NO tcgen05/TMEM: the harness
// lowers through compute_103 (non-'a'), which rejects arch-specific PTX).
// ---------------------------------------------------------------------------
__device__ __forceinline__ uint32_t smem_u32(const void* p) {
    uint32_t a;
    asm("{ .reg .u64 t; cvta.to.shared.u64 t, %1; cvt.u32.u64 %0, t; }" : "=r"(a) : "l"(p));
    return a;
}
__device__ __forceinline__ void cp16(uint32_t s, const void* g) {
    asm volatile("cp.async.cg.shared.global [%0], [%1], 16;" :: "r"(s), "l"(g));
}
__device__ __forceinline__ void cp_commit() {
    asm volatile("cp.async.commit_group;" ::: "memory");
}
__device__ __forceinline__ void cp_wait_all() {
    asm volatile("cp.async.wait_group 0;" ::: "memory");
}
__device__ __forceinline__ void ldmatrix_x4(uint32_t& r0, uint32_t& r1,
                                            uint32_t& r2, uint32_t& r3, uint32_t addr) {
    asm volatile("ldmatrix.sync.aligned.m8n8.x4.shared.b16 {%0,%1,%2,%3}, [%4];"
                 : "=r"(r0), "=r"(r1), "=r"(r2), "=r"(r3) : "r"(addr));
}
__device__ __forceinline__ void mma_bf16(float* d, const uint32_t* a, const uint32_t* b) {
    asm volatile(
        "mma.sync.aligned.m16n8k16.row.col.f32.bf16.bf16.f32 "
        "{%0,%1,%2,%3}, {%4,%5,%6,%7}, {%8,%9}, {%0,%1,%2,%3};"
        : "+f"(d[0]), "+f"(d[1]), "+f"(d[2]), "+f"(d[3])
        : "r"(a[0]), "r"(a[1]), "r"(a[2]), "r"(a[3]), "r"(b[0]), "r"(b[1]));
}

// ---------------------------------------------------------------------------
// K0a: w_qkv [384][256] fp32 -> g_wb [o][768] = [hi | lo | hi]
// ---------------------------------------------------------------------------
__global__ __launch_bounds__(256) void k_conv_w(const float* __restrict__ w)
{
    const int i = blockIdx.x * 256 + threadIdx.x;    // < 98304
    const float v = w[i];
    const int o = i >> 8, c = i & 255;
    const __nv_bfloat16 hi = __float2bfloat16(v);
    const __nv_bfloat16 lo = __float2bfloat16(v - __bfloat162float(hi));
    __nv_bfloat16* row = g_wb + (size_t)o * KB3;
    row[c]       = hi;
    row[256 + c] = lo;
    row[512 + c] = hi;
}

// ---------------------------------------------------------------------------
// K0b: x [b][256][4096] fp32 -> g_xb [b*4096 + p][768] = [hi | hi | lo]
// 32(c) x 32(p) transpose tiles via smem.
// ---------------------------------------------------------------------------
__global__ __launch_bounds__(256) void k_conv_x(const float* __restrict__ x)
{
    __shared__ float tile[32][33];
    const int b  = blockIdx.z;
    const int c0 = blockIdx.y * 32;
    const int p0 = blockIdx.x * 32;
    const int tp = threadIdx.x & 31, tc = threadIdx.x >> 5;   // tc 0..7
    #pragma unroll
    for (int j = 0; j < 4; j++) {
        const int c = tc + j * 8;
        tile[c][tp] = x[((size_t)b * C_ + c0 + c) * NP + p0 + tp];
    }
    __syncthreads();
    #pragma unroll
    for (int j = 0; j < 4; j++) {
        const int p = tc + j * 8;
        const float v = tile[tp][p];            // channel c0+tp, position p0+p
        const __nv_bfloat16 hi = __float2bfloat16(v);
        const __nv_bfloat16 lo = __float2bfloat16(v - __bfloat162float(hi));
        __nv_bfloat16* row = g_xb + ((size_t)b * NP + p0 + p) * KB3;
        row[c0 + tp]       = hi;
        row[256 + c0 + tp] = hi;
        row[512 + c0 + tp] = lo;
    }
}

// ---------------------------------------------------------------------------
// K1: qkv GEMM via mma.sync bf16 (HMMA). Per CTA: M=128, N=128, K'=768.
// BK=32, double-buffered cp.async, 8 warps as 4(m) x 2(n), warp tile 32x64.
// smem rows padded to 40 bf16 (80B) -> conflict-free ldmatrix.
// ---------------------------------------------------------------------------
__global__ __launch_bounds__(256) void k_qkv_mma()
{
    __shared__ __nv_bfloat16 sA[2][128][40];
    __shared__ __nv_bfloat16 sB[2][128][40];
    const int tid  = threadIdx.x;
    const int wid  = tid >> 5, lane = tid & 31;
    const int n0 = blockIdx.x * 128;
    const int m0 = blockIdx.y * 128;
    const int b  = blockIdx.z;
    const int warp_m = wid >> 1, warp_n = wid & 1;

    const __nv_bfloat16* __restrict__ Ag = g_wb + (size_t)m0 * KB3;
    const __nv_bfloat16* __restrict__ Bg = g_xb + ((size_t)b * NP + n0) * KB3;

    const uint32_t aBase = smem_u32(&sA[0][0][0]);
    const uint32_t bBase = smem_u32(&sB[0][0][0]);
    const uint32_t BUFB = 128 * 40 * 2;   // 10240 bytes per buffer

    // Load geometry: 512 16B-chunks per tile; thread t handles chunks t, t+256.
    const int lr = tid >> 2;          // rows 0..63 (and +64)
    const int ls = tid & 3;           // 16B sub-chunk within 64B row slice
    const uint32_t so0 = (uint32_t)lr * 80 + ls * 16;
    const uint32_t so1 = (uint32_t)(lr + 64) * 80 + ls * 16;
    const size_t   gi0 = (size_t)lr * KB3 + ls * 8;
    const size_t   gi1 = (size_t)(lr + 64) * KB3 + ls * 8;

    // ldmatrix element coords (byte offsets within a buffer)
    const int aRowL = warp_m * 32 + (lane & 15);          // + mf*16
    const int aColL = (lane >> 4) * 8;                    // + kk
    const int bg = lane >> 3, blr = lane & 7;
    const int bRowL = warp_n * 64 + (bg >> 1) * 8 + blr;  // + nf2*16
    const int bColL = (bg & 1) * 8;                       // + kk

    float d[2][8][4];
    #pragma unroll
    for (int mf = 0; mf < 2; mf++)
        #pragma unroll
        for (int nf = 0; nf < 8; nf++)
            #pragma unroll
            for (int r = 0; r < 4; r++) d[mf][nf][r] = 0.f;

    // Prologue: load stage 0
    {
        cp16(aBase + so0, Ag + gi0);
        cp16(aBase + so1, Ag + gi1);
        cp16(bBase + so0, Bg + gi0);
        cp16(bBase + so1, Bg + gi1);
        cp_commit();
    }

    const int NIT = KB3 / 32;    // 24
    int buf = 0;
    for (int it = 0; it < NIT; it++) {
        cp_wait_all();
        __syncthreads();
        if (it + 1 < NIT) {
            const uint32_t db = (buf ^ 1) * BUFB;
            const int k0 = (it + 1) * 32;
            cp16(aBase + db + so0, Ag + gi0 + k0);
            cp16(aBase + db + so1, Ag + gi1 + k0);
            cp16(bBase + db + so0, Bg + gi0 + k0);
            cp16(bBase + db + so1, Bg + gi1 + k0);
            cp_commit();
        }
        const uint32_t ab = aBase + buf * BUFB;
        const uint32_t bb = bBase + buf * BUFB;
        #pragma unroll
        for (int ks = 0; ks < 2; ks++) {
            const int kk = ks * 16;
            uint32_t ra[2][4];
            #pragma unroll
            for (int mf = 0; mf < 2; mf++) {
                const uint32_t addr = ab + (uint32_t)((aRowL + mf * 16) * 40 + kk + aColL) * 2;
                ldmatrix_x4(ra[mf][0], ra[mf][1], ra[mf][2], ra[mf][3], addr);
            }
            uint32_t rb[8][2];
            #pragma unroll
            for (int nf2 = 0; nf2 < 4; nf2++) {
                uint32_t r0, r1, r2, r3;
                const uint32_t addr = bb + (uint32_t)((bRowL + nf2 * 16) * 40 + kk + bColL) * 2;
                ldmatrix_x4(r0, r1, r2, r3, addr);
                rb[nf2 * 2][0] = r0; rb[nf2 * 2][1] = r1;
                rb[nf2 * 2 + 1][0] = r2; rb[nf2 * 2 + 1][1] = r3;
            }
            #pragma unroll
            for (int mf = 0; mf < 2; mf++)
                #pragma unroll
                for (int nf = 0; nf < 8; nf++)
                    mma_bf16(d[mf][nf], ra[mf], rb[nf]);
        }
        __syncthreads();
        buf ^= 1;
    }

    // Epilogue: d0,d1 -> (m = base + lane/4, n pair); d2,d3 -> m+8.
    const int mBase = m0 + warp_m * 32 + (lane >> 2);
    const int nBase = n0 + warp_n * 64 + (lane & 3) * 2;
    float* outb = g_qkv + (size_t)b * QKV_CH * NP;
    #pragma unroll
    for (int mf = 0; mf < 2; mf++) {
        #pragma unroll
        for (int nf = 0; nf < 8; nf++) {
            const int m = mBase + mf * 16;
            const int n = nBase + nf * 8;
            *(float2*)(outb + (size_t)m * NP + n)       = make_float2(d[mf][nf][0], d[mf][nf][1]);
            *(float2*)(outb + (size_t)(m + 8) * NP + n) = make_float2(d[mf][nf][2], d[mf][nf][3]);
        }
    }
}

// ---------------------------------------------------------------------------
// K2: per k-row (b, h*32+d): rowmax and 1/sum(exp(k - max)) over n=4096.
// ---------------------------------------------------------------------------
__global__ __launch_bounds__(256) void k_kstats()
{
    __shared__ float red[256];
    const int row = blockIdx.x;
    const int b = row >> 7, ko = row & 127;
    const float* base = g_qkv + (size_t)b * QKV_CH * NP + (size_t)(HID + ko) * NP;
    const int t = threadIdx.x;
    float vals[16];
    #pragma unroll
    for (int j = 0; j < 4; j++) {
        const float4 v = *(const float4*)(base + (j * 256 + t) * 4);
        vals[j * 4 + 0] = v.x; vals[j * 4 + 1] = v.y;
        vals[j * 4 + 2] = v.z; vals[j * 4 + 3] = v.w;
    }
    float m = vals[0];
    #pragma unroll
    for (int i = 1; i < 16; i++) m = fmaxf(m, vals[i]);
    red[t] = m; __syncthreads();
    for (int off = 128; off > 0; off >>= 1) {
        if (t < off) red[t] = fmaxf(red[t], red[t + off]);
        __syncthreads();
    }
    m = red[0];
    __syncthreads();
    float s = 0.f;
    #pragma unroll
    for (int i = 0; i < 16; i++) s += __expf(vals[i] - m);
    red[t] = s; __syncthreads();
    for (int off = 128; off > 0; off >>= 1) {
        if (t < off) red[t] += red[t + off];
        __syncthreads();
    }
    if (t == 0) g_kstat[row] = make_float2(m, 1.f / red[0]);
}

// ---------------------------------------------------------------------------
// K3: context partials. ctx[b,h][d][e] = sum_n softmax_n(k)[d,n] * (v[e,n]/4096)
// ---------------------------------------------------------------------------
__global__ __launch_bounds__(256) void k_context()
{
    __shared__ float ks[32][65];
    __shared__ float vs[32][65];
    const int ch = blockIdx.x;
    const int z  = blockIdx.y;
    const int b = z >> 2, h = z & 3;
    const float* kbase = g_qkv + (size_t)b * QKV_CH * NP + (size_t)(HID + h * DH) * NP;
    const float* vbase = g_qkv + (size_t)b * QKV_CH * NP + (size_t)(2 * HID + h * DH) * NP;
    const int t = threadIdx.x;
    const int lrow = t >> 3;
    const int lc0  = (t & 7) * 4;
    const float2 st = g_kstat[b * HID + h * DH + lrow];
    const float kmax = st.x, kinv = st.y;
    const int ty = t >> 4, tx = t & 15;
    const int d0 = ty * 2, e0 = tx * 2;
    float a00 = 0, a01 = 0, a10 = 0, a11 = 0;

    for (int tile = 0; tile < 4; tile++) {
        const int n0 = ch * 256 + tile * 64;
        #pragma unroll
        for (int jj = 0; jj < 2; jj++) {
            const int c = lc0 + jj * 32;
            const float4 kv = *(const float4*)(kbase + (size_t)lrow * NP + n0 + c);
            ks[lrow][c + 0] = __expf(kv.x - kmax) * kinv;
            ks[lrow][c + 1] = __expf(kv.y - kmax) * kinv;
            ks[lrow][c + 2] = __expf(kv.z - kmax) * kinv;
            ks[lrow][c + 3] = __expf(kv.w - kmax) * kinv;
            const float4 vv = *(const float4*)(vbase + (size_t)lrow * NP + n0 + c);
            vs[lrow][c + 0] = vv.x * (1.f / 4096.f);
            vs[lrow][c + 1] = vv.y * (1.f / 4096.f);
            vs[lrow][c + 2] = vv.z * (1.f / 4096.f);
            vs[lrow][c + 3] = vv.w * (1.f / 4096.f);
        }
        __syncthreads();
        #pragma unroll
        for (int nn = 0; nn < 64; nn++) {
            const float k0v = ks[d0][nn], k1v = ks[d0 + 1][nn];
            const float v0  = vs[e0][nn], v1  = vs[e0 + 1][nn];
            a00 += k0v * v0; a01 += k0v * v1;
            a10 += k1v * v0; a11 += k1v * v1;
        }
        __syncthreads();
    }
    float* o = g_ctxp + ((size_t)ch * 64 + z) * 1024;
    o[d0 * 32 + e0]           = a00;
    o[d0 * 32 + e0 + 1]       = a01;
    o[(d0 + 1) * 32 + e0]     = a10;
    o[(d0 + 1) * 32 + e0 + 1] = a11;
}

__global__ void k_ctx_reduce()
{
    const int i = blockIdx.x * 256 + threadIdx.x;
    float s = 0.f;
    #pragma unroll
    for (int ch = 0; ch < 16; ch++) s += g_ctxp[(size_t)ch * 65536 + i];
    g_ctx[i] = s;
}

// ---------------------------------------------------------------------------
// K4: fused final stage (q-softmax -> ctx^T@q -> w_out conv + bias -> LayerNorm)
// ---------------------------------------------------------------------------
__global__ __launch_bounds__(256) void k_out_fused(
    const float* __restrict__ w_out, const float* __restrict__ b_out,
    const float* __restrict__ g, float* __restrict__ out)
{
    __shared__ float sc[4][32][32];
    __shared__ float sq[128][17];
    __shared__ float sa[128][18];
    __shared__ float sw[256][9];
    __shared__ float redS[8][8][2];
    __shared__ float redQ[8][8][2];
    __shared__ float smu[16], srs[16];

    const int t  = threadIdx.x;
    const int p0 = blockIdx.x * 16;
    const int b  = blockIdx.y;
    const float* qb = g_qkv + (size_t)b * QKV_CH * NP;

    {
        const float* cb = g_ctx + (size_t)b * NH * 1024;
        float* scf = &sc[0][0][0];
        #pragma unroll
        for (int i = 0; i < 16; i++) scf[t + i * 256] = cb[t + i * 256];
    }
    {
        const int row = t >> 1;
        const int c4b = (t & 1) * 2;
        #pragma unroll
        for (int jj = 0; jj < 2; jj++) {
            const float4 v = *(const float4*)(qb + (size_t)row * NP + p0 + (c4b + jj) * 4);
            const int c = (c4b + jj) * 4;
            sq[row][c] = v.x; sq[row][c + 1] = v.y; sq[row][c + 2] = v.z; sq[row][c + 3] = v.w;
        }
    }
    __syncthreads();

    if (t < 64) {
        const int h = t >> 4, p = t & 15;
        float m = -3.402823e38f;
        #pragma unroll
        for (int d = 0; d < 32; d++) m = fmaxf(m, sq[h * 32 + d][p]);
        float s = 0.f;
        #pragma unroll
        for (int d = 0; d < 32; d++) s += __expf(sq[h * 32 + d][p] - m);
        const float inv = 0.17677669529663687f / s;
        #pragma unroll
        for (int d = 0; d < 32; d++) sq[h * 32 + d][p] = __expf(sq[h * 32 + d][p] - m) * inv;
    }
    __syncthreads();

    {
        const int p = t & 15, cg = t >> 4;
        const int h  = cg >> 2;
        const int e0 = (cg & 3) * 8;
        float acc[8];
        #pragma unroll
        for (int i = 0; i < 8; i++) acc[i] = 0.f;
        #pragma unroll
        for (int d = 0; d < 32; d++) {
            const float qv = sq[h * 32 + d][p];
            #pragma unroll
            for (int i = 0; i < 8; i++) acc[i] += sc[h][d][e0 + i] * qv;
        }
        #pragma unroll
        for (int i = 0; i < 8; i++) sa[cg * 8 + i][p] = acc[i];
    }
    __syncthreads();

    const int ty = t >> 3, tx = t & 7;
    float y[8][2];
    #pragma unroll
    for (int i = 0; i < 8; i++) { y[i][0] = 0.f; y[i][1] = 0.f; }
    for (int k0 = 0; k0 < 128; k0 += 8) {
        const float4 wa  = *(const float4*)(w_out + (size_t)t * HID + k0);
        const float4 wb2 = *(const float4*)(w_out + (size_t)t * HID + k0 + 4);
        sw[t][0] = wa.x;  sw[t][1] = wa.y;  sw[t][2] = wa.z;  sw[t][3] = wa.w;
        sw[t][4] = wb2.x; sw[t][5] = wb2.y; sw[t][6] = wb2.z; sw[t][7] = wb2.w;
        __syncthreads();
        #pragma unroll
        for (int kk = 0; kk < 8; kk++) {
            const int c = k0 + kk;
            const float b0 = sa[c][tx * 2], b1 = sa[c][tx * 2 + 1];
            #pragma unroll
            for (int i = 0; i < 8; i++) {
                const float a = sw[ty * 8 + i][kk];
                y[i][0] += a * b0;
                y[i][1] += a * b1;
            }
        }
        __syncthreads();
    }
    #pragma unroll
    for (int i = 0; i < 8; i++) {
        const float bo = b_out[ty * 8 + i];
        y[i][0] += bo; y[i][1] += bo;
    }
    float s0 = 0, s1 = 0, q0 = 0, q1 = 0;
    #pragma unroll
    for (int i = 0; i < 8; i++) {
        s0 += y[i][0]; q0 += y[i][0] * y[i][0];
        s1 += y[i][1]; q1 += y[i][1] * y[i][1];
    }
    #pragma unroll
    for (int off = 8; off < 32; off <<= 1) {
        s0 += __shfl_xor_sync(0xffffffffu, s0, off);
        s1 += __shfl_xor_sync(0xffffffffu, s1, off);
        q0 += __shfl_xor_sync(0xffffffffu, q0, off);
        q1 += __shfl_xor_sync(0xffffffffu, q1, off);
    }
    const int warp = t >> 5, lane = t & 31;
    if (lane < 8) {
        redS[warp][lane][0] = s0; redS[warp][lane][1] = s1;
        redQ[warp][lane][0] = q0; redQ[warp][lane][1] = q1;
    }
    __syncthreads();
    if (t < 16) {
        float s = 0, q = 0;
        #pragma unroll
        for (int w2 = 0; w2 < 8; w2++) {
            s += redS[w2][t >> 1][t & 1];
            q += redQ[w2][t >> 1][t & 1];
        }
        const float mu  = s * (1.f / 256.f);
        const float var = q * (1.f / 256.f) - mu * mu;
        smu[t] = mu;
        srs[t] = rsqrtf(var + 1e-5f);
    }
    __syncthreads();

    float* ob = out + (size_t)b * C_ * NP;
    #pragma unroll
    for (int i = 0; i < 8; i++) {
        const int o = ty * 8 + i;
        const float gg = g[o];
        const int pa = tx * 2;
        const float2 r = make_float2(
        (y[i][0] - smu[pa])     * srs[pa]     * gg,
        (y[i][1] - smu[pa + 1]) * srs[pa + 1] * gg);
        *(float2*)(ob + (size_t)o * NP + p0 + pa) = r;
    }
}

// ---------------------------------------------------------------------------
extern "C" void kernel_launch(void* const* d_in, const int* in_sizes, int n_in,
                              void* d_out, int out_size)
{
    const float* x     = (const float*)d_in[0];
    const float* w_qkv = (const float*)d_in[1];
    const float* w_out = (const float*)d_in[2];
    const float* b_out = (const float*)d_in[3];
    const float* g     = (const float*)d_in[4];
    float* out = (float*)d_out;
    (void)in_sizes; (void)n_in; (void)out_size;

    k_conv_w<<<384, 256>>>(w_qkv);
    k_conv_x<<<dim3(NP / 32, C_ / 32, B_), 256>>>(x);
    k_qkv_mma<<<dim3(32, 3, 16), 256>>>();
    k_kstats<<<2048, 256>>>();
    k_context<<<dim3(16, 64), 256>>>();
    k_ctx_reduce<<<256, 256>>>();
    k_out_fused<<<dim3(256, 16), 256>>>(w_out, b_out, g, out);
}

// round 8
// speedup vs baseline: 1.6650x; 1.3515x over previous
#include <cuda_runtime.h>
#include <cuda_bf16.h>
#include <cstdint>
#include <cstddef>

// Problem constants
#define B_     16
#define C_     256
#define HID    128
#define NH     4
#define DH     32
#define NP     4096       // 64*64 spatial positions
#define QKV_CH 384
#define KB3    768        // split-K bf16 for qkv GEMM: A=[hi|lo|hi], B=[hi|hi|lo]
#define KO3    384        // split-K bf16 for out GEMM: A=w_out [hi|lo|hi], B=attn [hi|hi|lo]

// Scratch (device globals: allocation-free rule)
__device__ float  g_qkv[(size_t)B_ * QKV_CH * NP];   // qkv = w_qkv @ x (fp32)
__device__ float2 g_kstat[B_ * HID];
__device__ float  g_ctxp[16 * 64 * 1024];
__device__ float  g_ctx [64 * 1024];
__device__ __nv_bfloat16 g_wb [(size_t)QKV_CH * KB3];   // w_qkv split bf16, K-major
__device__ __nv_bfloat16 g_xb [(size_t)B_ * NP * KB3];  // x^T split bf16, K-major (~100MB)
__device__ __nv_bfloat16 g_wob[(size_t)C_ * KO3];       // w_out split bf16
__device__ __nv_bfloat16 g_ab [(size_t)B_ * NP * KO3];  // attn hidden split bf16 (~50MB)

// ---------------------------------------------------------------------------
// Portable PTX helpers (sm_80+ only — harness lowers via compute_103 (non-'a'))
// ---------------------------------------------------------------------------
__device__ __forceinline__ uint32_t smem_u32(const void* p) {
    uint32_t a;
    asm("{ .reg .u64 t; cvta.to.shared.u64 t, %1; cvt.u32.u64 %0, t; }" : "=r"(a) : "l"(p));
    return a;
}
__device__ __forceinline__ void cp16(uint32_t s, const void* g) {
    asm volatile("cp.async.cg.shared.global [%0], [%1], 16;" :: "r"(s), "l"(g));
}
__device__ __forceinline__ void cp_commit() {
    asm volatile("cp.async.commit_group;" ::: "memory");
}
__device__ __forceinline__ void cp_wait_all() {
    asm volatile("cp.async.wait_group 0;" ::: "memory");
}
__device__ __forceinline__ void cp_wait1() {
    asm volatile("cp.async.wait_group 1;" ::: "memory");
}
__device__ __forceinline__ void ldmatrix_x4(uint32_t& r0, uint32_t& r1,
                                            uint32_t& r2, uint32_t& r3, uint32_t addr) {
    asm volatile("ldmatrix.sync.aligned.m8n8.x4.shared.b16 {%0,%1,%2,%3}, [%4];"
                 : "=r"(r0), "=r"(r1), "=r"(r2), "=r"(r3) : "r"(addr));
}
__device__ __forceinline__ void mma_bf16(float* d, const uint32_t* a, const uint32_t* b) {
    asm volatile(
        "mma.sync.aligned.m16n8k16.row.col.f32.bf16.bf16.f32 "
        "{%0,%1,%2,%3}, {%4,%5,%6,%7}, {%8,%9}, {%0,%1,%2,%3};"
        : "+f"(d[0]), "+f"(d[1]), "+f"(d[2]), "+f"(d[3])
        : "r"(a[0]), "r"(a[1]), "r"(a[2]), "r"(a[3]), "r"(b[0]), "r"(b[1]));
}

// ---------------------------------------------------------------------------
// K0a: w_qkv [384][256] fp32 -> g_wb [o][768] = [hi | lo | hi]
// ---------------------------------------------------------------------------
__global__ __launch_bounds__(256) void k_conv_w(const float* __restrict__ w)
{
    const int i = blockIdx.x * 256 + threadIdx.x;
    const float v = w[i];
    const int o = i >> 8, c = i & 255;
    const __nv_bfloat16 hi = __float2bfloat16(v);
    const __nv_bfloat16 lo = __float2bfloat16(v - __bfloat162float(hi));
    __nv_bfloat16* row = g_wb + (size_t)o * KB3;
    row[c]       = hi;
    row[256 + c] = lo;
    row[512 + c] = hi;
}

// K0c: w_out [256][128] fp32 -> g_wob [o][384] = [hi | lo | hi]
__global__ __launch_bounds__(256) void k_conv_wo(const float* __restrict__ w)
{
    const int i = blockIdx.x * 256 + threadIdx.x;    // < 32768
    const float v = w[i];
    const int o = i >> 7, c = i & 127;
    const __nv_bfloat16 hi = __float2bfloat16(v);
    const __nv_bfloat16 lo = __float2bfloat16(v - __bfloat162float(hi));
    __nv_bfloat16* row = g_wob + (size_t)o * KO3;
    row[c]       = hi;
    row[128 + c] = lo;
    row[256 + c] = hi;
}

// ---------------------------------------------------------------------------
// K0b: x [b][256][4096] fp32 -> g_xb [b*4096+p][768] = [hi | hi | lo]
// 32(c) x 32(p) transpose tiles; writers emit full-sector 32B chunks.
// ---------------------------------------------------------------------------
__global__ __launch_bounds__(256) void k_conv_x(const float* __restrict__ x)
{
    __shared__ float tile[32][33];
    const int b  = blockIdx.z;
    const int c0 = blockIdx.y * 32;
    const int p0 = blockIdx.x * 32;
    const int tp = threadIdx.x & 31, tc = threadIdx.x >> 5;
    #pragma unroll
    for (int j = 0; j < 4; j++) {
        const int c = tc + j * 8;
        tile[c][tp] = x[((size_t)b * C_ + c0 + c) * NP + p0 + tp];
    }
    __syncthreads();
    // Writers: p = tid&31, s = tid>>5. 6 tasks: {hi-seg0, hi-seg1, lo-seg2} x 2 halves.
    const int p = threadIdx.x & 31, s = threadIdx.x >> 5;
    if (s < 6) {
        const int h2  = s & 1;     // 16-channel half
        const int dst = s >> 1;    // 0,1 = hi segments; 2 = lo segment
        union { __nv_bfloat16 h[16]; uint4 u[2]; } vbuf;
        #pragma unroll
        for (int j = 0; j < 16; j++) {
            const float v = tile[h2 * 16 + j][p];
            const __nv_bfloat16 hi = __float2bfloat16(v);
            vbuf.h[j] = (dst == 2) ? __float2bfloat16(v - __bfloat162float(hi)) : hi;
        }
        __nv_bfloat16* row = g_xb + ((size_t)b * NP + p0 + p) * KB3 + dst * 256 + c0 + h2 * 16;
        ((uint4*)row)[0] = vbuf.u[0];
        ((uint4*)row)[1] = vbuf.u[1];
    }
}

// ---------------------------------------------------------------------------
// K1: qkv GEMM via mma.sync bf16. M=128, N=128, K'=768. BK=32, 3-stage
// cp.async pipeline, 8 warps (4m x 2n), warp tile 32x64. Rows padded to 40.
// ---------------------------------------------------------------------------
__global__ __launch_bounds__(256) void k_qkv_mma()
{
    __shared__ __nv_bfloat16 sA[3][128][40];
    __shared__ __nv_bfloat16 sB[3][128][40];
    const int tid  = threadIdx.x;
    const int wid  = tid >> 5, lane = tid & 31;
    const int n0 = blockIdx.x * 128;
    const int m0 = blockIdx.y * 128;
    const int b  = blockIdx.z;
    const int warp_m = wid >> 1, warp_n = wid & 1;

    const __nv_bfloat16* __restrict__ Ag = g_wb + (size_t)m0 * KB3;
    const __nv_bfloat16* __restrict__ Bg = g_xb + ((size_t)b * NP + n0) * KB3;

    const uint32_t aBase = smem_u32(&sA[0][0][0]);
    const uint32_t bBase = smem_u32(&sB[0][0][0]);
    const uint32_t BUFB = 128 * 40 * 2;   // 10240 B per stage buffer

    const int lr = tid >> 2;
    const int ls = tid & 3;
    const uint32_t so0 = (uint32_t)lr * 80 + ls * 16;
    const uint32_t so1 = (uint32_t)(lr + 64) * 80 + ls * 16;
    const size_t   gi0 = (size_t)lr * KB3 + ls * 8;
    const size_t   gi1 = (size_t)(lr + 64) * KB3 + ls * 8;

    const int aRowL = warp_m * 32 + (lane & 15);
    const int aColL = (lane >> 4) * 8;
    const int bg = lane >> 3, blr = lane & 7;
    const int bRowL = warp_n * 64 + (bg >> 1) * 8 + blr;
    const int bColL = (bg & 1) * 8;

    float d[2][8][4];
    #pragma unroll
    for (int mf = 0; mf < 2; mf++)
        #pragma unroll
        for (int nf = 0; nf < 8; nf++)
            #pragma unroll
            for (int r = 0; r < 4; r++) d[mf][nf][r] = 0.f;

    const int NIT = KB3 / 32;    // 24

    // Prologue: stages 0, 1
    #pragma unroll
    for (int s = 0; s < 2; s++) {
        const uint32_t db = s * BUFB;
        const int k0 = s * 32;
        cp16(aBase + db + so0, Ag + gi0 + k0);
        cp16(aBase + db + so1, Ag + gi1 + k0);
        cp16(bBase + db + so0, Bg + gi0 + k0);
        cp16(bBase + db + so1, Bg + gi1 + k0);
        cp_commit();
    }

    int buf = 0;
    for (int it = 0; it < NIT; it++) {
        cp_wait1();            // stage 'it' complete; 'it+1' may be in flight
        __syncthreads();
        if (it + 2 < NIT) {
            int nb = buf + 2; if (nb >= 3) nb -= 3;
            const uint32_t db = (uint32_t)nb * BUFB;
            const int k0 = (it + 2) * 32;
            cp16(aBase + db + so0, Ag + gi0 + k0);
            cp16(aBase + db + so1, Ag + gi1 + k0);
            cp16(bBase + db + so0, Bg + gi0 + k0);
            cp16(bBase + db + so1, Bg + gi1 + k0);
        }
        cp_commit();           // commit every iter (possibly empty) to keep group counts aligned
        const uint32_t ab = aBase + (uint32_t)buf * BUFB;
        const uint32_t bb = bBase + (uint32_t)buf * BUFB;
        #pragma unroll
        for (int ks = 0; ks < 2; ks++) {
            const int kk = ks * 16;
            uint32_t ra[2][4];
            #pragma unroll
            for (int mf = 0; mf < 2; mf++) {
                const uint32_t addr = ab + (uint32_t)((aRowL + mf * 16) * 40 + kk + aColL) * 2;
                ldmatrix_x4(ra[mf][0], ra[mf][1], ra[mf][2], ra[mf][3], addr);
            }
            uint32_t rb[8][2];
            #pragma unroll
            for (int nf2 = 0; nf2 < 4; nf2++) {
                uint32_t r0, r1, r2, r3;
                const uint32_t addr = bb + (uint32_t)((bRowL + nf2 * 16) * 40 + kk + bColL) * 2;
                ldmatrix_x4(r0, r1, r2, r3, addr);
                rb[nf2 * 2][0] = r0;     rb[nf2 * 2][1] = r1;
                rb[nf2 * 2 + 1][0] = r2; rb[nf2 * 2 + 1][1] = r3;
            }
            #pragma unroll
            for (int mf = 0; mf < 2; mf++)
                #pragma unroll
                for (int nf = 0; nf < 8; nf++)
                    mma_bf16(d[mf][nf], ra[mf], rb[nf]);
        }
        buf++; if (buf == 3) buf = 0;
    }

    const int mBase = m0 + warp_m * 32 + (lane >> 2);
    const int nBase = n0 + warp_n * 64 + (lane & 3) * 2;
    float* outb = g_qkv + (size_t)b * QKV_CH * NP;
    #pragma unroll
    for (int mf = 0; mf < 2; mf++) {
        #pragma unroll
        for (int nf = 0; nf < 8; nf++) {
            const int m = mBase + mf * 16;
            const int n = nBase + nf * 8;
            *(float2*)(outb + (size_t)m * NP + n)       = make_float2(d[mf][nf][0], d[mf][nf][1]);
            *(float2*)(outb + (size_t)(m + 8) * NP + n) = make_float2(d[mf][nf][2], d[mf][nf][3]);
        }
    }
}

// ---------------------------------------------------------------------------
// K2: per k-row (b, h*32+d): rowmax and 1/sum(exp(k - max)) over n=4096.
// ---------------------------------------------------------------------------
__global__ __launch_bounds__(256) void k_kstats()
{
    __shared__ float red[256];
    const int row = blockIdx.x;
    const int b = row >> 7, ko = row & 127;
    const float* base = g_qkv + (size_t)b * QKV_CH * NP + (size_t)(HID + ko) * NP;
    const int t = threadIdx.x;
    float vals[16];
    #pragma unroll
    for (int j = 0; j < 4; j++) {
        const float4 v = *(const float4*)(base + (j * 256 + t) * 4);
        vals[j * 4 + 0] = v.x; vals[j * 4 + 1] = v.y;
        vals[j * 4 + 2] = v.z; vals[j * 4 + 3] = v.w;
    }
    float m = vals[0];
    #pragma unroll
    for (int i = 1; i < 16; i++) m = fmaxf(m, vals[i]);
    red[t] = m; __syncthreads();
    for (int off = 128; off > 0; off >>= 1) {
        if (t < off) red[t] = fmaxf(red[t], red[t + off]);
        __syncthreads();
    }
    m = red[0];
    __syncthreads();
    float s = 0.f;
    #pragma unroll
    for (int i = 0; i < 16; i++) s += __expf(vals[i] - m);
    red[t] = s; __syncthreads();
    for (int off = 128; off > 0; off >>= 1) {
        if (t < off) red[t] += red[t + off];
        __syncthreads();
    }
    if (t == 0) g_kstat[row] = make_float2(m, 1.f / red[0]);
}

// ---------------------------------------------------------------------------
// K3: context partials. ctx[b,h][d][e] = sum_n softmax_n(k)[d,n] * (v[e,n]/4096)
// ---------------------------------------------------------------------------
__global__ __launch_bounds__(256) void k_context()
{
    __shared__ float ks[32][65];
    __shared__ float vs[32][65];
    const int ch = blockIdx.x;
    const int z  = blockIdx.y;
    const int b = z >> 2, h = z & 3;
    const float* kbase = g_qkv + (size_t)b * QKV_CH * NP + (size_t)(HID + h * DH) * NP;
    const float* vbase = g_qkv + (size_t)b * QKV_CH * NP + (size_t)(2 * HID + h * DH) * NP;
    const int t = threadIdx.x;
    const int lrow = t >> 3;
    const int lc0  = (t & 7) * 4;
    const float2 st = g_kstat[b * HID + h * DH + lrow];
    const float kmax = st.x, kinv = st.y;
    const int ty = t >> 4, tx = t & 15;
    const int d0 = ty * 2, e0 = tx * 2;
    float a00 = 0, a01 = 0, a10 = 0, a11 = 0;

    for (int tile = 0; tile < 4; tile++) {
        const int n0 = ch * 256 + tile * 64;
        #pragma unroll
        for (int jj = 0; jj < 2; jj++) {
            const int c = lc0 + jj * 32;
            const float4 kv = *(const float4*)(kbase + (size_t)lrow * NP + n0 + c);
            ks[lrow][c + 0] = __expf(kv.x - kmax) * kinv;
            ks[lrow][c + 1] = __expf(kv.y - kmax) * kinv;
            ks[lrow][c + 2] = __expf(kv.z - kmax) * kinv;
            ks[lrow][c + 3] = __expf(kv.w - kmax) * kinv;
            const float4 vv = *(const float4*)(vbase + (size_t)lrow * NP + n0 + c);
            vs[lrow][c + 0] = vv.x * (1.f / 4096.f);
            vs[lrow][c + 1] = vv.y * (1.f / 4096.f);
            vs[lrow][c + 2] = vv.z * (1.f / 4096.f);
            vs[lrow][c + 3] = vv.w * (1.f / 4096.f);
        }
        __syncthreads();
        #pragma unroll
        for (int nn = 0; nn < 64; nn++) {
            const float k0v = ks[d0][nn], k1v = ks[d0 + 1][nn];
            const float v0  = vs[e0][nn], v1  = vs[e0 + 1][nn];
            a00 += k0v * v0; a01 += k0v * v1;
            a10 += k1v * v0; a11 += k1v * v1;
        }
        __syncthreads();
    }
    float* o = g_ctxp + ((size_t)ch * 64 + z) * 1024;
    o[d0 * 32 + e0]           = a00;
    o[d0 * 32 + e0 + 1]       = a01;
    o[(d0 + 1) * 32 + e0]     = a10;
    o[(d0 + 1) * 32 + e0 + 1] = a11;
}

__global__ void k_ctx_reduce()
{
    const int i = blockIdx.x * 256 + threadIdx.x;
    float s = 0.f;
    #pragma unroll
    for (int ch = 0; ch < 16; ch++) s += g_ctxp[(size_t)ch * 65536 + i];
    g_ctx[i] = s;
}

// ---------------------------------------------------------------------------
// K4a: q-softmax + attn = ctx^T @ qs, emitted as bf16 hi/lo split rows
// g_ab[(b*4096+p)][384] = [hi(128) | hi(128) | lo(128)].
// Grid (128 p-tiles of 32, 16 b), 256 threads.
// ---------------------------------------------------------------------------
__global__ __launch_bounds__(256) void k_attn()
{
    __shared__ float sq[128][36];        // q (rows) -> later reused as attn [c][p]
    __shared__ float sctx[4][32][33];
    const int t  = threadIdx.x;
    const int p0 = blockIdx.x * 32;
    const int b  = blockIdx.y;
    const float* qb = g_qkv + (size_t)b * QKV_CH * NP;

    {   // load q rows 0..127 for 32 positions
        const int row = t >> 1, hf = (t & 1) * 16;
        #pragma unroll
        for (int j = 0; j < 4; j++) {
            const float4 v = *(const float4*)(qb + (size_t)row * NP + p0 + hf + j * 4);
            const int c = hf + j * 4;
            sq[row][c] = v.x; sq[row][c + 1] = v.y; sq[row][c + 2] = v.z; sq[row][c + 3] = v.w;
        }
    }
    {   // load ctx
        const float* cb = g_ctx + (size_t)b * NH * 1024;
        #pragma unroll
        for (int i = 0; i < 16; i++) {
            const int idx = t + i * 256;
            sctx[idx >> 10][(idx >> 5) & 31][idx & 31] = cb[idx];
        }
    }
    __syncthreads();

    // softmax over d per (h,p); fold SCALE
    if (t < 128) {
        const int h = t >> 5, p = t & 31;
        float m = -3.402823e38f;
        #pragma unroll
        for (int d = 0; d < 32; d++) m = fmaxf(m, sq[h * 32 + d][p]);
        float s = 0.f;
        #pragma unroll
        for (int d = 0; d < 32; d++) s += __expf(sq[h * 32 + d][p] - m);
        const float inv = 0.17677669529663687f / s;
        #pragma unroll
        for (int d = 0; d < 32; d++) sq[h * 32 + d][p] = __expf(sq[h * 32 + d][p] - m) * inv;
    }
    __syncthreads();

    // attn[c][p] = sum_d ctx[h][d][e] * qs[h*32+d][p], thread: c = t>>1, 16 p
    float acc[16];
    const int c  = t >> 1;
    const int ph = (t & 1) * 16;
    {
        const int h = c >> 5, e = c & 31;
        #pragma unroll
        for (int i = 0; i < 16; i++) acc[i] = 0.f;
        #pragma unroll
        for (int d = 0; d < 32; d++) {
            const float cv = sctx[h][d][e];
            #pragma unroll
            for (int j = 0; j < 4; j++) {
                const float4 qv = *(const float4*)&sq[h * 32 + d][ph + j * 4];
                acc[j * 4 + 0] += cv * qv.x;
                acc[j * 4 + 1] += cv * qv.y;
                acc[j * 4 + 2] += cv * qv.z;
                acc[j * 4 + 3] += cv * qv.w;
            }
        }
    }
    __syncthreads();
    #pragma unroll
    for (int i = 0; i < 16; i++) sq[c][ph + i] = acc[i];   // reuse sq as attn [c][p]
    __syncthreads();

    // write split rows: p = t&31, s = t>>5 handles channels 16s..16s+15
    {
        const int p = t & 31, s = t >> 5;
        union { __nv_bfloat16 h[16]; uint4 u[2]; } hi, lo;
        #pragma unroll
        for (int j = 0; j < 16; j++) {
            const float v = sq[s * 16 + j][p];
            const __nv_bfloat16 vh = __float2bfloat16(v);
            hi.h[j] = vh;
            lo.h[j] = __float2bfloat16(v - __bfloat162float(vh));
        }
        __nv_bfloat16* row = g_ab + ((size_t)b * NP + p0 + p) * KO3 + s * 16;
        ((uint4*)row)[0] = hi.u[0];          ((uint4*)row)[1] = hi.u[1];
        ((uint4*)(row + 128))[0] = hi.u[0];  ((uint4*)(row + 128))[1] = hi.u[1];
        ((uint4*)(row + 256))[0] = lo.u[0];  ((uint4*)(row + 256))[1] = lo.u[1];
    }
}

// ---------------------------------------------------------------------------
// K4b: out = LN(w_out @ attn + b_out) * g via HMMA. M=256 (full channel dim
// in one CTA -> LN fused in epilogue), BN=32, K'=384, BK=32 double-buffered.
// 8 warps (4m x 2n), warp tile 64x16. Grid (128 n-tiles, 16 b).
// ---------------------------------------------------------------------------
__global__ __launch_bounds__(256) void k_out_mma(
    const float* __restrict__ b_out, const float* __restrict__ g, float* __restrict__ out)
{
    __shared__ char smem_raw[46080];
    __nv_bfloat16* sA = (__nv_bfloat16*)smem_raw;              // [2][256][40]
    __nv_bfloat16* sB = (__nv_bfloat16*)(smem_raw + 40960);    // [2][32][40]
    float* ys   = (float*)smem_raw;                            // epilogue: [256][33]
    float* redS = (float*)(smem_raw + 33792);                  // [8][32]
    float* redQ = redS + 256;
    float* smu  = redQ + 256;                                  // [32]
    float* srs  = smu + 32;

    const int tid  = threadIdx.x;
    const int wid  = tid >> 5, lane = tid & 31;
    const int n0 = blockIdx.x * 32;
    const int b  = blockIdx.y;
    const int warp_m = wid >> 1, warp_n = wid & 1;

    const uint32_t aBase = smem_u32(sA);
    const uint32_t bBase = smem_u32(sB);
    const uint32_t ABUF = 256 * 40 * 2;   // 20480
    const uint32_t BBUF = 32 * 40 * 2;    // 2560

    // A loads: 4 chunks/thread
    const int a_ls = tid & 3;
    const int a_r0 = tid >> 2;            // + i*64
    // B loads: threads < 128
    const int b_r = tid >> 2, b_ls = tid & 3;
    const __nv_bfloat16* __restrict__ Bg = g_ab + ((size_t)b * NP + n0) * KO3;

    const int aRowL = warp_m * 64 + (lane & 15);
    const int aColL = (lane >> 4) * 8;
    const int bg = lane >> 3, blr = lane & 7;
    const int bRowL = warp_n * 16 + (bg >> 1) * 8 + blr;
    const int bColL = (bg & 1) * 8;

    float d[4][2][4];
    #pragma unroll
    for (int mf = 0; mf < 4; mf++)
        #pragma unroll
        for (int nf = 0; nf < 2; nf++)
            #pragma unroll
            for (int r = 0; r < 4; r++) d[mf][nf][r] = 0.f;

    const int NIT = KO3 / 32;   // 12

    // Prologue
    {
        #pragma unroll
        for (int i = 0; i < 4; i++) {
            const int row = a_r0 + i * 64;
            cp16(aBase + (uint32_t)row * 80 + a_ls * 16, g_wob + (size_t)row * KO3 + a_ls * 8);
        }
        if (tid < 128)
            cp16(bBase + (uint32_t)b_r * 80 + b_ls * 16, Bg + (size_t)b_r * KO3 + b_ls * 8);
        cp_commit();
    }

    int buf = 0;
    for (int it = 0; it < NIT; it++) {
        cp_wait_all();
        __syncthreads();
        if (it + 1 < NIT) {
            const int k0 = (it + 1) * 32;
            const uint32_t da = (buf ^ 1) * ABUF;
            const uint32_t db = (buf ^ 1) * BBUF;
            #pragma unroll
            for (int i = 0; i < 4; i++) {
                const int row = a_r0 + i * 64;
                cp16(aBase + da + (uint32_t)row * 80 + a_ls * 16,
                     g_wob + (size_t)row * KO3 + k0 + a_ls * 8);
            }
            if (tid < 128)
                cp16(bBase + db + (uint32_t)b_r * 80 + b_ls * 16,
                     Bg + (size_t)b_r * KO3 + k0 + b_ls * 8);
            cp_commit();
        }
        const uint32_t ab = aBase + (uint32_t)buf * ABUF;
        const uint32_t bb = bBase + (uint32_t)buf * BBUF;
        #pragma unroll
        for (int ks = 0; ks < 2; ks++) {
            const int kk = ks * 16;
            uint32_t ra[4][4];
            #pragma unroll
            for (int mf = 0; mf < 4; mf++) {
                const uint32_t addr = ab + (uint32_t)((aRowL + mf * 16) * 40 + kk + aColL) * 2;
                ldmatrix_x4(ra[mf][0], ra[mf][1], ra[mf][2], ra[mf][3], addr);
            }
            uint32_t rb[2][2];
            {
                uint32_t r0, r1, r2, r3;
                const uint32_t addr = bb + (uint32_t)(bRowL * 40 + kk + bColL) * 2;
                ldmatrix_x4(r0, r1, r2, r3, addr);
                rb[0][0] = r0; rb[0][1] = r1;
                rb[1][0] = r2; rb[1][1] = r3;
            }
            #pragma unroll
            for (int mf = 0; mf < 4; mf++)
                #pragma unroll
                for (int nf = 0; nf < 2; nf++)
                    mma_bf16(d[mf][nf], ra[mf], rb[nf]);
        }
        __syncthreads();
        buf ^= 1;
    }

    // Epilogue: bias -> smem ys[m][n] -> LN stats over 256 channels -> write
    const int mB = warp_m * 64 + (lane >> 2);
    const int nB = warp_n * 16 + (lane & 3) * 2;
    #pragma unroll
    for (int mf = 0; mf < 4; mf++) {
        #pragma unroll
        for (int nf = 0; nf < 2; nf++) {
            const int m = mB + mf * 16;
            const int n = nB + nf * 8;
            const float bo0 = b_out[m], bo1 = b_out[m + 8];
            ys[m * 33 + n]           = d[mf][nf][0] + bo0;
            ys[m * 33 + n + 1]       = d[mf][nf][1] + bo0;
            ys[(m + 8) * 33 + n]     = d[mf][nf][2] + bo1;
            ys[(m + 8) * 33 + n + 1] = d[mf][nf][3] + bo1;
        }
    }
    __syncthreads();
    {   // warp w sums channels [w*32, w*32+32) for position n = lane
        float s = 0.f, q = 0.f;
        #pragma unroll
        for (int c = 0; c < 32; c++) {
            const float v = ys[(wid * 32 + c) * 33 + lane];
            s += v; q += v * v;
        }
        redS[wid * 32 + lane] = s;
        redQ[wid * 32 + lane] = q;
    }
    __syncthreads();
    if (tid < 32) {
        float s = 0.f, q = 0.f;
        #pragma unroll
        for (int w = 0; w < 8; w++) { s += redS[w * 32 + tid]; q += redQ[w * 32 + tid]; }
        const float mu  = s * (1.f / 256.f);
        const float var = q * (1.f / 256.f) - mu * mu;
        smu[tid] = mu;
        srs[tid] = rsqrtf(var + 1e-5f);
    }
    __syncthreads();
    {
        const int n2 = tid & 31;
        const float mu = smu[n2], rs = srs[n2];
        float* ob = out + (size_t)b * C_ * NP + n0 + n2;
        for (int o = tid >> 5; o < C_; o += 8) {
            ob[(size_t)o * NP] = (ys[o * 33 + n2] - mu) * rs * g[o];
        }
    }
}

// ---------------------------------------------------------------------------
extern "C" void kernel_launch(void* const* d_in, const int* in_sizes, int n_in,
                              void* d_out, int out_size)
{
    const float* x     = (const float*)d_in[0];
    const float* w_qkv = (const float*)d_in[1];
    const float* w_out = (const float*)d_in[2];
    const float* b_out = (const float*)d_in[3];
    const float* g     = (const float*)d_in[4];
    float* out = (float*)d_out;
    (void)in_sizes; (void)n_in; (void)out_size;

    k_conv_w<<<384, 256>>>(w_qkv);
    k_conv_wo<<<128, 256>>>(w_out);
    k_conv_x<<<dim3(NP / 32, C_ / 32, B_), 256>>>(x);
    k_qkv_mma<<<dim3(32, 3, 16), 256>>>();
    k_kstats<<<2048, 256>>>();
    k_context<<<dim3(16, 64), 256>>>();
    k_ctx_reduce<<<256, 256>>>();
    k_attn<<<dim3(NP / 32, B_), 256>>>();
    k_out_mma<<<dim3(NP / 32, B_), 256>>>(b_out, g, out);
}

// round 9
// speedup vs baseline: 2.4350x; 1.4625x over previous
#include <cuda_runtime.h>
#include <cuda_fp16.h>
#include <cstdint>
#include <cstddef>

// Problem constants
#define B_     16
#define C_     256
#define HID    128
#define NH     4
#define DH     32
#define NP     4096       // 64*64 spatial positions
#define QKV_CH 384

// Scratch (device globals: allocation-free rule)
__device__ float  g_qkv[(size_t)B_ * QKV_CH * NP];   // qkv = w_qkv @ x (fp32)
__device__ float2 g_kstat[B_ * HID];
__device__ float  g_ctxp[16 * 64 * 1024];
__device__ float  g_ctx [64 * 1024];
__device__ __half g_wh [(size_t)QKV_CH * 512];       // w_qkv fp16 split: [hi(256)|lo(256)]
__device__ __half g_xh [(size_t)B_ * NP * 256];      // x^T fp16 hi (33MB)
__device__ __half g_woh[(size_t)C_ * 256];           // w_out fp16 split: [hi(128)|lo(128)]
__device__ __half g_ah [(size_t)B_ * NP * 128];      // attn hidden fp16 hi (17MB)

// ---------------------------------------------------------------------------
// Portable PTX helpers (sm_80+ only — harness lowers via compute_103 (non-'a'))
// ---------------------------------------------------------------------------
__device__ __forceinline__ uint32_t smem_u32(const void* p) {
    uint32_t a;
    asm("{ .reg .u64 t; cvta.to.shared.u64 t, %1; cvt.u32.u64 %0, t; }" : "=r"(a) : "l"(p));
    return a;
}
__device__ __forceinline__ void cp16(uint32_t s, const void* g) {
    asm volatile("cp.async.cg.shared.global [%0], [%1], 16;" :: "r"(s), "l"(g));
}
__device__ __forceinline__ void cp_commit() {
    asm volatile("cp.async.commit_group;" ::: "memory");
}
__device__ __forceinline__ void cp_wait_all() {
    asm volatile("cp.async.wait_group 0;" ::: "memory");
}
__device__ __forceinline__ void ldmatrix_x4(uint32_t& r0, uint32_t& r1,
                                            uint32_t& r2, uint32_t& r3, uint32_t addr) {
    asm volatile("ldmatrix.sync.aligned.m8n8.x4.shared.b16 {%0,%1,%2,%3}, [%4];"
                 : "=r"(r0), "=r"(r1), "=r"(r2), "=r"(r3) : "r"(addr));
}
__device__ __forceinline__ void mma_f16(float* d, const uint32_t* a, const uint32_t* b) {
    asm volatile(
        "mma.sync.aligned.m16n8k16.row.col.f32.f16.f16.f32 "
        "{%0,%1,%2,%3}, {%4,%5,%6,%7}, {%8,%9}, {%0,%1,%2,%3};"
        : "+f"(d[0]), "+f"(d[1]), "+f"(d[2]), "+f"(d[3])
        : "r"(a[0]), "r"(a[1]), "r"(a[2]), "r"(a[3]), "r"(b[0]), "r"(b[1]));
}

// ---------------------------------------------------------------------------
// K0a: w_qkv [384][256] fp32 -> g_wh [o][512] = [hi(256) | lo(256)]
// ---------------------------------------------------------------------------
__global__ __launch_bounds__(256) void k_conv_w(const float* __restrict__ w)
{
    const int i = blockIdx.x * 256 + threadIdx.x;    // < 98304
    const float v = w[i];
    const int o = i >> 8, c = i & 255;
    const __half hi = __float2half(v);
    const __half lo = __float2half(v - __half2float(hi));
    g_wh[(size_t)o * 512 + c]       = hi;
    g_wh[(size_t)o * 512 + 256 + c] = lo;
}

// K0c: w_out [256][128] fp32 -> g_woh [o][256] = [hi(128) | lo(128)]
__global__ __launch_bounds__(256) void k_conv_wo(const float* __restrict__ w)
{
    const int i = blockIdx.x * 256 + threadIdx.x;    // < 32768
    const float v = w[i];
    const int o = i >> 7, c = i & 127;
    const __half hi = __float2half(v);
    const __half lo = __float2half(v - __half2float(hi));
    g_woh[(size_t)o * 256 + c]       = hi;
    g_woh[(size_t)o * 256 + 128 + c] = lo;
}

// ---------------------------------------------------------------------------
// K0b: x [b][256][4096] fp32 -> g_xh [b*4096+p][256] fp16 hi. 32x32 transpose.
// ---------------------------------------------------------------------------
__global__ __launch_bounds__(256) void k_conv_x(const float* __restrict__ x)
{
    __shared__ float tile[32][33];
    const int b  = blockIdx.z;
    const int c0 = blockIdx.y * 32;
    const int p0 = blockIdx.x * 32;
    const int tp = threadIdx.x & 31, tc = threadIdx.x >> 5;
    #pragma unroll
    for (int j = 0; j < 4; j++) {
        const int c = tc + j * 8;
        tile[c][tp] = x[((size_t)b * C_ + c0 + c) * NP + p0 + tp];
    }
    __syncthreads();
    if (threadIdx.x < 128) {
        const int p = threadIdx.x >> 2, ch = threadIdx.x & 3;
        union { __half h[8]; uint4 u; } vb;
        #pragma unroll
        for (int j = 0; j < 8; j++) vb.h[j] = __float2half(tile[ch * 8 + j][p]);
        *(uint4*)(g_xh + ((size_t)b * NP + p0 + p) * 256 + c0 + ch * 8) = vb.u;
    }
}

// ---------------------------------------------------------------------------
// K1: qkv GEMM, fp16 2-term split. Per CTA: M=128, N=128, K=256, BK=32,
// 8 iters. Each iter: A brings BOTH segments (hi cols [0,32), lo cols [32,64)
// of smem row); B loaded once per iter and its fragments reused for both
// A segments -> B traffic halved vs duplicated layout.
// ---------------------------------------------------------------------------
__global__ __launch_bounds__(256) void k_qkv_mma()
{
    __shared__ __half sA[2][128][72];   // row: [0:32)=hi seg, [32:64)=lo seg; pad->72 (144B row)
    __shared__ __half sB[2][128][40];   // 32 cols + pad (80B row)
    const int tid  = threadIdx.x;
    const int wid  = tid >> 5, lane = tid & 31;
    const int n0 = blockIdx.x * 128;
    const int m0 = blockIdx.y * 128;
    const int b  = blockIdx.z;
    const int warp_m = wid >> 1, warp_n = wid & 1;

    const __half* __restrict__ Ag = g_wh + (size_t)m0 * 512;
    const __half* __restrict__ Bg = g_xh + ((size_t)b * NP + n0) * 256;

    const uint32_t aBase = smem_u32(&sA[0][0][0]);
    const uint32_t bBase = smem_u32(&sB[0][0][0]);
    const uint32_t ABUF = 128 * 144;   // 18432
    const uint32_t BBUF = 128 * 80;    // 10240

    // A loader: 1024 16B-chunks/stage, 4 per thread.
    uint32_t aso[4]; uint32_t agi[4];
    #pragma unroll
    for (int i = 0; i < 4; i++) {
        const int slot = tid + i * 256;
        const int r = slot >> 3, ch = slot & 7;
        aso[i] = (uint32_t)r * 144 + ch * 16;
        agi[i] = (uint32_t)r * 512 + (ch < 4 ? ch * 8 : 256 + (ch - 4) * 8);
    }
    // B loader: 512 chunks/stage, 2 per thread.
    uint32_t bso[2]; uint32_t bgi[2];
    #pragma unroll
    for (int i = 0; i < 2; i++) {
        const int slot = tid + i * 256;
        const int r = slot >> 2, ch = slot & 3;
        bso[i] = (uint32_t)r * 80 + ch * 16;
        bgi[i] = (uint32_t)r * 256 + ch * 8;
    }

    const int aRowL = warp_m * 32 + (lane & 15);
    const uint32_t aCol16 = (uint32_t)(lane >> 4) * 16;     // bytes
    const int bg = lane >> 3, blr = lane & 7;
    const int bRowL = warp_n * 64 + (bg >> 1) * 8 + blr;
    const uint32_t bCol16 = (uint32_t)(bg & 1) * 16;        // bytes

    float d[2][8][4];
    #pragma unroll
    for (int mf = 0; mf < 2; mf++)
        #pragma unroll
        for (int nf = 0; nf < 8; nf++)
            #pragma unroll
            for (int r = 0; r < 4; r++) d[mf][nf][r] = 0.f;

    // Prologue: stage 0 (k0 = 0)
    #pragma unroll
    for (int i = 0; i < 4; i++) cp16(aBase + aso[i], Ag + agi[i]);
    #pragma unroll
    for (int i = 0; i < 2; i++) cp16(bBase + bso[i], Bg + bgi[i]);
    cp_commit();

    int buf = 0;
    for (int it = 0; it < 8; it++) {
        cp_wait_all();
        __syncthreads();
        if (it + 1 < 8) {
            const uint32_t da = (buf ^ 1) * ABUF;
            const uint32_t db = (buf ^ 1) * BBUF;
            const int k0 = (it + 1) * 32;
            #pragma unroll
            for (int i = 0; i < 4; i++) cp16(aBase + da + aso[i], Ag + agi[i] + k0);
            #pragma unroll
            for (int i = 0; i < 2; i++) cp16(bBase + db + bso[i], Bg + bgi[i] + k0);
            cp_commit();
        }
        const uint32_t ab = aBase + (uint32_t)buf * ABUF;
        const uint32_t bb = bBase + (uint32_t)buf * BBUF;
        #pragma unroll
        for (int ks = 0; ks < 2; ks++) {
            uint32_t rb[8][2];
            #pragma unroll
            for (int nf2 = 0; nf2 < 4; nf2++) {
                uint32_t r0, r1, r2, r3;
                const uint32_t addr = bb + (uint32_t)(bRowL + nf2 * 16) * 80 + ks * 32 + bCol16;
                ldmatrix_x4(r0, r1, r2, r3, addr);
                rb[nf2 * 2][0] = r0;     rb[nf2 * 2][1] = r1;
                rb[nf2 * 2 + 1][0] = r2; rb[nf2 * 2 + 1][1] = r3;
            }
            #pragma unroll
            for (int seg = 0; seg < 2; seg++) {
                uint32_t ra[2][4];
                #pragma unroll
                for (int mf = 0; mf < 2; mf++) {
                    const uint32_t addr = ab + (uint32_t)(aRowL + mf * 16) * 144
                                        + seg * 64 + ks * 32 + aCol16;
                    ldmatrix_x4(ra[mf][0], ra[mf][1], ra[mf][2], ra[mf][3], addr);
                }
                #pragma unroll
                for (int mf = 0; mf < 2; mf++)
                    #pragma unroll
                    for (int nf = 0; nf < 8; nf++)
                        mma_f16(d[mf][nf], ra[mf], rb[nf]);
            }
        }
        buf ^= 1;
    }

    const int mBase = m0 + warp_m * 32 + (lane >> 2);
    const int nBase = n0 + warp_n * 64 + (lane & 3) * 2;
    float* outb = g_qkv + (size_t)b * QKV_CH * NP;
    #pragma unroll
    for (int mf = 0; mf < 2; mf++) {
        #pragma unroll
        for (int nf = 0; nf < 8; nf++) {
            const int m = mBase + mf * 16;
            const int n = nBase + nf * 8;
            *(float2*)(outb + (size_t)m * NP + n)       = make_float2(d[mf][nf][0], d[mf][nf][1]);
            *(float2*)(outb + (size_t)(m + 8) * NP + n) = make_float2(d[mf][nf][2], d[mf][nf][3]);
        }
    }
}

// ---------------------------------------------------------------------------
// K2: per k-row (b, h*32+d): rowmax and 1/sum(exp(k - max)) over n=4096.
// ---------------------------------------------------------------------------
__global__ __launch_bounds__(256) void k_kstats()
{
    __shared__ float red[256];
    const int row = blockIdx.x;
    const int b = row >> 7, ko = row & 127;
    const float* base = g_qkv + (size_t)b * QKV_CH * NP + (size_t)(HID + ko) * NP;
    const int t = threadIdx.x;
    float vals[16];
    #pragma unroll
    for (int j = 0; j < 4; j++) {
        const float4 v = *(const float4*)(base + (j * 256 + t) * 4);
        vals[j * 4 + 0] = v.x; vals[j * 4 + 1] = v.y;
        vals[j * 4 + 2] = v.z; vals[j * 4 + 3] = v.w;
    }
    float m = vals[0];
    #pragma unroll
    for (int i = 1; i < 16; i++) m = fmaxf(m, vals[i]);
    red[t] = m; __syncthreads();
    for (int off = 128; off > 0; off >>= 1) {
        if (t < off) red[t] = fmaxf(red[t], red[t + off]);
        __syncthreads();
    }
    m = red[0];
    __syncthreads();
    float s = 0.f;
    #pragma unroll
    for (int i = 0; i < 16; i++) s += __expf(vals[i] - m);
    red[t] = s; __syncthreads();
    for (int off = 128; off > 0; off >>= 1) {
        if (t < off) red[t] += red[t + off];
        __syncthreads();
    }
    if (t == 0) g_kstat[row] = make_float2(m, 1.f / red[0]);
}

// ---------------------------------------------------------------------------
// K3: context partials. ctx[b,h][d][e] = sum_n softmax_n(k)[d,n] * (v[e,n]/4096)
// ---------------------------------------------------------------------------
__global__ __launch_bounds__(256) void k_context()
{
    __shared__ float ks[32][65];
    __shared__ float vs[32][65];
    const int ch = blockIdx.x;
    const int z  = blockIdx.y;
    const int b = z >> 2, h = z & 3;
    const float* kbase = g_qkv + (size_t)b * QKV_CH * NP + (size_t)(HID + h * DH) * NP;
    const float* vbase = g_qkv + (size_t)b * QKV_CH * NP + (size_t)(2 * HID + h * DH) * NP;
    const int t = threadIdx.x;
    const int lrow = t >> 3;
    const int lc0  = (t & 7) * 4;
    const float2 st = g_kstat[b * HID + h * DH + lrow];
    const float kmax = st.x, kinv = st.y;
    const int ty = t >> 4, tx = t & 15;
    const int d0 = ty * 2, e0 = tx * 2;
    float a00 = 0, a01 = 0, a10 = 0, a11 = 0;

    for (int tile = 0; tile < 4; tile++) {
        const int n0 = ch * 256 + tile * 64;
        #pragma unroll
        for (int jj = 0; jj < 2; jj++) {
            const int c = lc0 + jj * 32;
            const float4 kv = *(const float4*)(kbase + (size_t)lrow * NP + n0 + c);
            ks[lrow][c + 0] = __expf(kv.x - kmax) * kinv;
            ks[lrow][c + 1] = __expf(kv.y - kmax) * kinv;
            ks[lrow][c + 2] = __expf(kv.z - kmax) * kinv;
            ks[lrow][c + 3] = __expf(kv.w - kmax) * kinv;
            const float4 vv = *(const float4*)(vbase + (size_t)lrow * NP + n0 + c);
            vs[lrow][c + 0] = vv.x * (1.f / 4096.f);
            vs[lrow][c + 1] = vv.y * (1.f / 4096.f);
            vs[lrow][c + 2] = vv.z * (1.f / 4096.f);
            vs[lrow][c + 3] = vv.w * (1.f / 4096.f);
        }
        __syncthreads();
        #pragma unroll
        for (int nn = 0; nn < 64; nn++) {
            const float k0v = ks[d0][nn], k1v = ks[d0 + 1][nn];
            const float v0  = vs[e0][nn], v1  = vs[e0 + 1][nn];
            a00 += k0v * v0; a01 += k0v * v1;
            a10 += k1v * v0; a11 += k1v * v1;
        }
        __syncthreads();
    }
    float* o = g_ctxp + ((size_t)ch * 64 + z) * 1024;
    o[d0 * 32 + e0]           = a00;
    o[d0 * 32 + e0 + 1]       = a01;
    o[(d0 + 1) * 32 + e0]     = a10;
    o[(d0 + 1) * 32 + e0 + 1] = a11;
}

__global__ void k_ctx_reduce()
{
    const int i = blockIdx.x * 256 + threadIdx.x;
    float s = 0.f;
    #pragma unroll
    for (int ch = 0; ch < 16; ch++) s += g_ctxp[(size_t)ch * 65536 + i];
    g_ctx[i] = s;
}

// ---------------------------------------------------------------------------
// K4a: q-softmax + attn = ctx^T @ qs, emitted as fp16 hi rows g_ah[(b*4096+p)][128].
// ---------------------------------------------------------------------------
__global__ __launch_bounds__(256) void k_attn()
{
    __shared__ float sq[128][36];
    __shared__ float sctx[4][32][33];
    const int t  = threadIdx.x;
    const int p0 = blockIdx.x * 32;
    const int b  = blockIdx.y;
    const float* qb = g_qkv + (size_t)b * QKV_CH * NP;

    {
        const int row = t >> 1, hf = (t & 1) * 16;
        #pragma unroll
        for (int j = 0; j < 4; j++) {
            const float4 v = *(const float4*)(qb + (size_t)row * NP + p0 + hf + j * 4);
            const int c = hf + j * 4;
            sq[row][c] = v.x; sq[row][c + 1] = v.y; sq[row][c + 2] = v.z; sq[row][c + 3] = v.w;
        }
    }
    {
        const float* cb = g_ctx + (size_t)b * NH * 1024;
        #pragma unroll
        for (int i = 0; i < 16; i++) {
            const int idx = t + i * 256;
            sctx[idx >> 10][(idx >> 5) & 31][idx & 31] = cb[idx];
        }
    }
    __syncthreads();

    if (t < 128) {
        const int h = t >> 5, p = t & 31;
        float m = -3.402823e38f;
        #pragma unroll
        for (int d = 0; d < 32; d++) m = fmaxf(m, sq[h * 32 + d][p]);
        float s = 0.f;
        #pragma unroll
        for (int d = 0; d < 32; d++) s += __expf(sq[h * 32 + d][p] - m);
        const float inv = 0.17677669529663687f / s;
        #pragma unroll
        for (int d = 0; d < 32; d++) sq[h * 32 + d][p] = __expf(sq[h * 32 + d][p] - m) * inv;
    }
    __syncthreads();

    float acc[16];
    const int c  = t >> 1;
    const int ph = (t & 1) * 16;
    {
        const int h = c >> 5, e = c & 31;
        #pragma unroll
        for (int i = 0; i < 16; i++) acc[i] = 0.f;
        #pragma unroll
        for (int d = 0; d < 32; d++) {
            const float cv = sctx[h][d][e];
            #pragma unroll
            for (int j = 0; j < 4; j++) {
                const float4 qv = *(const float4*)&sq[h * 32 + d][ph + j * 4];
                acc[j * 4 + 0] += cv * qv.x;
                acc[j * 4 + 1] += cv * qv.y;
                acc[j * 4 + 2] += cv * qv.z;
                acc[j * 4 + 3] += cv * qv.w;
            }
        }
    }
    __syncthreads();
    #pragma unroll
    for (int i = 0; i < 16; i++) sq[c][ph + i] = acc[i];
    __syncthreads();

    {
        const int p = t & 31, s = t >> 5;    // s: 16-channel group
        union { __half h[16]; uint4 u[2]; } hb;
        #pragma unroll
        for (int j = 0; j < 16; j++) hb.h[j] = __float2half(sq[s * 16 + j][p]);
        __half* row = g_ah + ((size_t)b * NP + p0 + p) * 128 + s * 16;
        ((uint4*)row)[0] = hb.u[0];
        ((uint4*)row)[1] = hb.u[1];
    }
}

// ---------------------------------------------------------------------------
// K4b: out = LN(w_out @ attn + b_out) * g. M=256 (LN fused), N=32, fp16 2-term:
// A = g_woh K'=256 linear [hi|lo], B = g_ah 32x128 FULLY RESIDENT in smem.
// 8 iters of BK=32 over K'; B fragment col = k mod 128.
// ---------------------------------------------------------------------------
__global__ __launch_bounds__(256) void k_out_mma(
    const float* __restrict__ b_out, const float* __restrict__ g, float* __restrict__ out)
{
    __shared__ char smem_raw[49664];
    // GEMM phase: sA 2 stages x 256 rows x 80B at [0, 40960); sB 32 x 272B at [40960, 49664)
    // Epilogue:   ys[256][33] f32 at [0, 33792); redS/redQ/smu/srs at [40960, ...)
    const uint32_t aBase = smem_u32(smem_raw);
    const uint32_t bBase = aBase + 40960;
    float* ys   = (float*)smem_raw;
    float* redS = (float*)(smem_raw + 40960);
    float* redQ = redS + 256;
    float* smu  = redQ + 256;
    float* srs  = smu + 32;

    const int tid  = threadIdx.x;
    const int wid  = tid >> 5, lane = tid & 31;
    const int n0 = blockIdx.x * 32;
    const int b  = blockIdx.y;
    const int warp_m = wid >> 1, warp_n = wid & 1;
    const uint32_t ABUF = 256 * 80;   // 20480

    const __half* __restrict__ Bg = g_ah + ((size_t)b * NP + n0) * 128;

    // A loader: 1024 chunks/stage, 4 per thread
    const int a_r = tid >> 2, a_ch = tid & 3;
    // frag coords
    const int aRowL = warp_m * 64 + (lane & 15);
    const uint32_t aCol16 = (uint32_t)(lane >> 4) * 16;
    const int bg = lane >> 3, blr = lane & 7;
    const int bRowL = warp_n * 16 + (bg >> 1) * 8 + blr;
    const uint32_t bCol16 = (uint32_t)(bg & 1) * 16;

    float d[4][2][4];
    #pragma unroll
    for (int mf = 0; mf < 4; mf++)
        #pragma unroll
        for (int nf = 0; nf < 2; nf++)
            #pragma unroll
            for (int r = 0; r < 4; r++) d[mf][nf][r] = 0.f;

    // Prologue: B fully (512 chunks, 2/thread) + A stage 0
    #pragma unroll
    for (int i = 0; i < 2; i++) {
        const int slot = tid + i * 256;
        const int r = slot >> 4, ch = slot & 15;
        cp16(bBase + (uint32_t)r * 272 + ch * 16, Bg + (size_t)r * 128 + ch * 8);
    }
    #pragma unroll
    for (int i = 0; i < 4; i++) {
        const int row = a_r + i * 64;
        cp16(aBase + (uint32_t)row * 80 + a_ch * 16, g_woh + (size_t)row * 256 + a_ch * 8);
    }
    cp_commit();

    int buf = 0;
    for (int it = 0; it < 8; it++) {
        cp_wait_all();
        __syncthreads();
        if (it + 1 < 8) {
            const uint32_t da = (buf ^ 1) * ABUF;
            const int k0 = (it + 1) * 32;
            #pragma unroll
            for (int i = 0; i < 4; i++) {
                const int row = a_r + i * 64;
                cp16(aBase + da + (uint32_t)row * 80 + a_ch * 16,
                     g_woh + (size_t)row * 256 + k0 + a_ch * 8);
            }
            cp_commit();
        }
        const uint32_t ab = aBase + (uint32_t)buf * ABUF;
        #pragma unroll
        for (int ks = 0; ks < 2; ks++) {
            const int kslot = (it * 2 + ks) & 7;     // B col chunk (k mod 128)
            uint32_t rb[2][2];
            {
                uint32_t r0, r1, r2, r3;
                const uint32_t addr = bBase + (uint32_t)bRowL * 272 + kslot * 32 + bCol16;
                ldmatrix_x4(r0, r1, r2, r3, addr);
                rb[0][0] = r0; rb[0][1] = r1;
                rb[1][0] = r2; rb[1][1] = r3;
            }
            uint32_t ra[4][4];
            #pragma unroll
            for (int mf = 0; mf < 4; mf++) {
                const uint32_t addr = ab + (uint32_t)(aRowL + mf * 16) * 80 + ks * 32 + aCol16;
                ldmatrix_x4(ra[mf][0], ra[mf][1], ra[mf][2], ra[mf][3], addr);
            }
            #pragma unroll
            for (int mf = 0; mf < 4; mf++)
                #pragma unroll
                for (int nf = 0; nf < 2; nf++)
                    mma_f16(d[mf][nf], ra[mf], rb[nf]);
        }
        buf ^= 1;
    }
    __syncthreads();   // GEMM done before smem reuse as ys

    // Epilogue: bias -> ys -> LN over 256 channels -> write
    const int mB = warp_m * 64 + (lane >> 2);
    const int nB = warp_n * 16 + (lane & 3) * 2;
    #pragma unroll
    for (int mf = 0; mf < 4; mf++) {
        #pragma unroll
        for (int nf = 0; nf < 2; nf++) {
            const int m = mB + mf * 16;
            const int n = nB + nf * 8;
            const float bo0 = b_out[m], bo1 = b_out[m + 8];
            ys[m * 33 + n]           = d[mf][nf][0] + bo0;
            ys[m * 33 + n + 1]       = d[mf][nf][1] + bo0;
            ys[(m + 8) * 33 + n]     = d[mf][nf][2] + bo1;
            ys[(m + 8) * 33 + n + 1] = d[mf][nf][3] + bo1;
        }
    }
    __syncthreads();
    {
        float s = 0.f, q = 0.f;
        #pragma unroll
        for (int c = 0; c < 32; c++) {
            const float v = ys[(wid * 32 + c) * 33 + lane];
            s += v; q += v * v;
        }
        redS[wid * 32 + lane] = s;
        redQ[wid * 32 + lane] = q;
    }
    __syncthreads();
    if (tid < 32) {
        float s = 0.f, q = 0.f;
        #pragma unroll
        for (int w = 0; w < 8; w++) { s += redS[w * 32 + tid]; q += redQ[w * 32 + tid]; }
        const float mu  = s * (1.f / 256.f);
        const float var = q * (1.f / 256.f) - mu * mu;
        smu[tid] = mu;
        srs[tid] = rsqrtf(var + 1e-5f);
    }
    __syncthreads();
    {
        const int n2 = tid & 31;
        const float mu = smu[n2], rs = srs[n2];
        float* ob = out + (size_t)b * C_ * NP + n0 + n2;
        for (int o = tid >> 5; o < C_; o += 8) {
            ob[(size_t)o * NP] = (ys[o * 33 + n2] - mu) * rs * g[o];
        }
    }
}

// ---------------------------------------------------------------------------
extern "C" void kernel_launch(void* const* d_in, const int* in_sizes, int n_in,
                              void* d_out, int out_size)
{
    const float* x     = (const float*)d_in[0];
    const float* w_qkv = (const float*)d_in[1];
    const float* w_out = (const float*)d_in[2];
    const float* b_out = (const float*)d_in[3];
    const float* g     = (const float*)d_in[4];
    float* out = (float*)d_out;
    (void)in_sizes; (void)n_in; (void)out_size;

    k_conv_w<<<384, 256>>>(w_qkv);
    k_conv_wo<<<128, 256>>>(w_out);
    k_conv_x<<<dim3(NP / 32, C_ / 32, B_), 256>>>(x);
    k_qkv_mma<<<dim3(32, 3, 16), 256>>>();
    k_kstats<<<2048, 256>>>();
    k_context<<<dim3(16, 64), 256>>>();
    k_ctx_reduce<<<256, 256>>>();
    k_attn<<<dim3(NP / 32, B_), 256>>>();
    k_out_mma<<<dim3(NP / 32, B_), 256>>>(b_out, g, out);
}

// round 10
// speedup vs baseline: 2.4419x; 1.0028x over previous
#include <cuda_runtime.h>
#include <cuda_fp16.h>
#include <cstdint>
#include <cstddef>

// Problem constants
#define B_     16
#define C_     256
#define HID    128
#define NH     4
#define DH     32
#define NP     4096       // 64*64 spatial positions
#define QKV_CH 384

// Scratch (device globals: allocation-free rule)
__device__ float  g_qkv[(size_t)B_ * QKV_CH * NP];   // qkv = w_qkv @ x (fp32)
__device__ float2 g_kstat[B_ * HID];
__device__ float  g_ctxp[8 * 64 * 1024];
__device__ float  g_ctx [64 * 1024];
__device__ __half g_wh [(size_t)QKV_CH * 512];       // w_qkv fp16 split: [hi(256)|lo(256)]
__device__ __half g_xh [(size_t)B_ * NP * 256];      // x^T fp16 hi (33MB)
__device__ __half g_woh[(size_t)C_ * 256];           // w_out fp16 split: [hi(128)|lo(128)]
__device__ __half g_ah [(size_t)B_ * NP * 128];      // attn hidden fp16 hi (17MB)

// ---------------------------------------------------------------------------
// Portable PTX helpers (sm_80+ only — harness lowers via compute_103 (non-'a'))
// ---------------------------------------------------------------------------
__device__ __forceinline__ uint32_t smem_u32(const void* p) {
    uint32_t a;
    asm("{ .reg .u64 t; cvta.to.shared.u64 t, %1; cvt.u32.u64 %0, t; }" : "=r"(a) : "l"(p));
    return a;
}
__device__ __forceinline__ void cp16(uint32_t s, const void* g) {
    asm volatile("cp.async.cg.shared.global [%0], [%1], 16;" :: "r"(s), "l"(g));
}
__device__ __forceinline__ void cp_commit() {
    asm volatile("cp.async.commit_group;" ::: "memory");
}
__device__ __forceinline__ void cp_wait1() {
    asm volatile("cp.async.wait_group 1;" ::: "memory");
}
__device__ __forceinline__ void ldmatrix_x4(uint32_t& r0, uint32_t& r1,
                                            uint32_t& r2, uint32_t& r3, uint32_t addr) {
    asm volatile("ldmatrix.sync.aligned.m8n8.x4.shared.b16 {%0,%1,%2,%3}, [%4];"
                 : "=r"(r0), "=r"(r1), "=r"(r2), "=r"(r3) : "r"(addr));
}
__device__ __forceinline__ void mma_f16(float* d, const uint32_t* a, const uint32_t* b) {
    asm volatile(
        "mma.sync.aligned.m16n8k16.row.col.f32.f16.f16.f32 "
        "{%0,%1,%2,%3}, {%4,%5,%6,%7}, {%8,%9}, {%0,%1,%2,%3};"
        : "+f"(d[0]), "+f"(d[1]), "+f"(d[2]), "+f"(d[3])
        : "r"(a[0]), "r"(a[1]), "r"(a[2]), "r"(a[3]), "r"(b[0]), "r"(b[1]));
}

// ---------------------------------------------------------------------------
// K0a: merged weight conversion.
// blocks [0,384): w_qkv [384][256] -> g_wh [o][512] = [hi|lo]
// blocks [384,512): w_out [256][128] -> g_woh [o][256] = [hi|lo]
// ---------------------------------------------------------------------------
__global__ __launch_bounds__(256) void k_conv_weights(
    const float* __restrict__ wq, const float* __restrict__ wo)
{
    if (blockIdx.x < 384) {
        const int i = blockIdx.x * 256 + threadIdx.x;    // < 98304
        const float v = wq[i];
        const int o = i >> 8, c = i & 255;
        const __half hi = __float2half(v);
        const __half lo = __float2half(v - __half2float(hi));
        g_wh[(size_t)o * 512 + c]       = hi;
        g_wh[(size_t)o * 512 + 256 + c] = lo;
    } else {
        const int i = (blockIdx.x - 384) * 256 + threadIdx.x;   // < 32768
        const float v = wo[i];
        const int o = i >> 7, c = i & 127;
        const __half hi = __float2half(v);
        const __half lo = __float2half(v - __half2float(hi));
        g_woh[(size_t)o * 256 + c]       = hi;
        g_woh[(size_t)o * 256 + 128 + c] = lo;
    }
}

// ---------------------------------------------------------------------------
// K0b: x [b][256][4096] fp32 -> g_xh [b*4096+p][256] fp16 hi. 32x32 transpose.
// ---------------------------------------------------------------------------
__global__ __launch_bounds__(256) void k_conv_x(const float* __restrict__ x)
{
    __shared__ float tile[32][33];
    const int b  = blockIdx.z;
    const int c0 = blockIdx.y * 32;
    const int p0 = blockIdx.x * 32;
    const int tp = threadIdx.x & 31, tc = threadIdx.x >> 5;
    #pragma unroll
    for (int j = 0; j < 4; j++) {
        const int c = tc + j * 8;
        tile[c][tp] = x[((size_t)b * C_ + c0 + c) * NP + p0 + tp];
    }
    __syncthreads();
    if (threadIdx.x < 128) {
        const int p = threadIdx.x >> 2, ch = threadIdx.x & 3;
        union { __half h[8]; uint4 u; } vb;
        #pragma unroll
        for (int j = 0; j < 8; j++) vb.h[j] = __float2half(tile[ch * 8 + j][p]);
        *(uint4*)(g_xh + ((size_t)b * NP + p0 + p) * 256 + c0 + ch * 8) = vb.u;
    }
}

// ---------------------------------------------------------------------------
// K1: qkv GEMM, fp16 2-term split. Per CTA: M=128, N=128, K=256, BK=32,
// 8 iters, 3-stage cp.async pipeline (double buffering left ~900cyc of load
// latency exposed per iter — measured R9). B loaded once per iter, fragments
// reused for both A segments (hi/lo).
// ---------------------------------------------------------------------------
__global__ __launch_bounds__(256) void k_qkv_mma()
{
    __shared__ __half sA[3][128][72];   // row: [0:32)=hi, [32:64)=lo; pad->72 (144B row)
    __shared__ __half sB[3][128][40];   // 32 cols + pad (80B row)
    const int tid  = threadIdx.x;
    const int wid  = tid >> 5, lane = tid & 31;
    const int n0 = blockIdx.x * 128;
    const int m0 = blockIdx.y * 128;
    const int b  = blockIdx.z;
    const int warp_m = wid >> 1, warp_n = wid & 1;

    const __half* __restrict__ Ag = g_wh + (size_t)m0 * 512;
    const __half* __restrict__ Bg = g_xh + ((size_t)b * NP + n0) * 256;

    const uint32_t aBase = smem_u32(&sA[0][0][0]);
    const uint32_t bBase = smem_u32(&sB[0][0][0]);
    const uint32_t ABUF = 128 * 144;   // 18432
    const uint32_t BBUF = 128 * 80;    // 10240

    // A loader: 1024 16B-chunks/stage, 4 per thread.
    uint32_t aso[4]; uint32_t agi[4];
    #pragma unroll
    for (int i = 0; i < 4; i++) {
        const int slot = tid + i * 256;
        const int r = slot >> 3, ch = slot & 7;
        aso[i] = (uint32_t)r * 144 + ch * 16;
        agi[i] = (uint32_t)r * 512 + (ch < 4 ? ch * 8 : 256 + (ch - 4) * 8);
    }
    // B loader: 512 chunks/stage, 2 per thread.
    uint32_t bso[2]; uint32_t bgi[2];
    #pragma unroll
    for (int i = 0; i < 2; i++) {
        const int slot = tid + i * 256;
        const int r = slot >> 2, ch = slot & 3;
        bso[i] = (uint32_t)r * 80 + ch * 16;
        bgi[i] = (uint32_t)r * 256 + ch * 8;
    }

    const int aRowL = warp_m * 32 + (lane & 15);
    const uint32_t aCol16 = (uint32_t)(lane >> 4) * 16;     // bytes
    const int bg = lane >> 3, blr = lane & 7;
    const int bRowL = warp_n * 64 + (bg >> 1) * 8 + blr;
    const uint32_t bCol16 = (uint32_t)(bg & 1) * 16;        // bytes

    float d[2][8][4];
    #pragma unroll
    for (int mf = 0; mf < 2; mf++)
        #pragma unroll
        for (int nf = 0; nf < 8; nf++)
            #pragma unroll
            for (int r = 0; r < 4; r++) d[mf][nf][r] = 0.f;

    // Prologue: stages 0, 1
    #pragma unroll
    for (int s = 0; s < 2; s++) {
        const int k0 = s * 32;
        #pragma unroll
        for (int i = 0; i < 4; i++) cp16(aBase + s * ABUF + aso[i], Ag + agi[i] + k0);
        #pragma unroll
        for (int i = 0; i < 2; i++) cp16(bBase + s * BBUF + bso[i], Bg + bgi[i] + k0);
        cp_commit();
    }

    int buf = 0;
    for (int it = 0; it < 8; it++) {
        cp_wait1();            // stage 'it' complete; 'it+1' may be in flight
        __syncthreads();
        if (it + 2 < 8) {
            int nb = buf + 2; if (nb >= 3) nb -= 3;
            const int k0 = (it + 2) * 32;
            #pragma unroll
            for (int i = 0; i < 4; i++) cp16(aBase + (uint32_t)nb * ABUF + aso[i], Ag + agi[i] + k0);
            #pragma unroll
            for (int i = 0; i < 2; i++) cp16(bBase + (uint32_t)nb * BBUF + bso[i], Bg + bgi[i] + k0);
        }
        cp_commit();           // commit every iter to keep group counts aligned
        const uint32_t ab = aBase + (uint32_t)buf * ABUF;
        const uint32_t bb = bBase + (uint32_t)buf * BBUF;
        #pragma unroll
        for (int ks = 0; ks < 2; ks++) {
            uint32_t rb[8][2];
            #pragma unroll
            for (int nf2 = 0; nf2 < 4; nf2++) {
                uint32_t r0, r1, r2, r3;
                const uint32_t addr = bb + (uint32_t)(bRowL + nf2 * 16) * 80 + ks * 32 + bCol16;
                ldmatrix_x4(r0, r1, r2, r3, addr);
                rb[nf2 * 2][0] = r0;     rb[nf2 * 2][1] = r1;
                rb[nf2 * 2 + 1][0] = r2; rb[nf2 * 2 + 1][1] = r3;
            }
            #pragma unroll
            for (int seg = 0; seg < 2; seg++) {
                uint32_t ra[2][4];
                #pragma unroll
                for (int mf = 0; mf < 2; mf++) {
                    const uint32_t addr = ab + (uint32_t)(aRowL + mf * 16) * 144
                                        + seg * 64 + ks * 32 + aCol16;
                    ldmatrix_x4(ra[mf][0], ra[mf][1], ra[mf][2], ra[mf][3], addr);
                }
                #pragma unroll
                for (int mf = 0; mf < 2; mf++)
                    #pragma unroll
                    for (int nf = 0; nf < 8; nf++)
                        mma_f16(d[mf][nf], ra[mf], rb[nf]);
            }
        }
        buf++; if (buf == 3) buf = 0;
    }

    const int mBase = m0 + warp_m * 32 + (lane >> 2);
    const int nBase = n0 + warp_n * 64 + (lane & 3) * 2;
    float* outb = g_qkv + (size_t)b * QKV_CH * NP;
    #pragma unroll
    for (int mf = 0; mf < 2; mf++) {
        #pragma unroll
        for (int nf = 0; nf < 8; nf++) {
            const int m = mBase + mf * 16;
            const int n = nBase + nf * 8;
            *(float2*)(outb + (size_t)m * NP + n)       = make_float2(d[mf][nf][0], d[mf][nf][1]);
            *(float2*)(outb + (size_t)(m + 8) * NP + n) = make_float2(d[mf][nf][2], d[mf][nf][3]);
        }
    }
}

// ---------------------------------------------------------------------------
// K2: per k-row (b, h*32+d): rowmax and 1/sum(exp(k - max)) over n=4096.
// ---------------------------------------------------------------------------
__global__ __launch_bounds__(256) void k_kstats()
{
    __shared__ float red[256];
    const int row = blockIdx.x;
    const int b = row >> 7, ko = row & 127;
    const float* base = g_qkv + (size_t)b * QKV_CH * NP + (size_t)(HID + ko) * NP;
    const int t = threadIdx.x;
    float vals[16];
    #pragma unroll
    for (int j = 0; j < 4; j++) {
        const float4 v = *(const float4*)(base + (j * 256 + t) * 4);
        vals[j * 4 + 0] = v.x; vals[j * 4 + 1] = v.y;
        vals[j * 4 + 2] = v.z; vals[j * 4 + 3] = v.w;
    }
    float m = vals[0];
    #pragma unroll
    for (int i = 1; i < 16; i++) m = fmaxf(m, vals[i]);
    red[t] = m; __syncthreads();
    for (int off = 128; off > 0; off >>= 1) {
        if (t < off) red[t] = fmaxf(red[t], red[t + off]);
        __syncthreads();
    }
    m = red[0];
    __syncthreads();
    float s = 0.f;
    #pragma unroll
    for (int i = 0; i < 16; i++) s += __expf(vals[i] - m);
    red[t] = s; __syncthreads();
    for (int off = 128; off > 0; off >>= 1) {
        if (t < off) red[t] += red[t + off];
        __syncthreads();
    }
    if (t == 0) g_kstat[row] = make_float2(m, 1.f / red[0]);
}

// ---------------------------------------------------------------------------
// K3: context partials. ctx[b,h][d][e] = sum_n softmax_n(k)[d,n] * (v[e,n]/4096)
// Grid (8 n-chunks of 512, 64 z). 256 thr = 4 sub-blocks of 64; each sub-block
// covers the full 32x32 (d,e) with 4x4 microtiles over its own nn quarter ->
// smem read bytes halved vs 2x2 (was the binding resource at ~30us).
// Stride 133 makes the 4-row k / 4-row v gathers bank-conflict-free.
// ---------------------------------------------------------------------------
__global__ __launch_bounds__(256) void k_context()
{
    __shared__ float ks[32][133];
    __shared__ float vs[32][133];
    __shared__ float red[4][1024];
    const int ch = blockIdx.x;     // 0..7
    const int z  = blockIdx.y;     // b*4+h
    const int b = z >> 2, h = z & 3;
    const float* kbase = g_qkv + ((size_t)b * QKV_CH + HID + h * DH) * NP;
    const float* vbase = g_qkv + ((size_t)b * QKV_CH + 2 * HID + h * DH) * NP;
    const int t = threadIdx.x;
    const int lrow = t >> 3;            // 0..31
    const int lc0  = (t & 7) * 16;      // 16 cols per thread
    const float2 st = g_kstat[b * HID + h * DH + lrow];
    const float kmax = st.x, kinv = st.y;
    const int sub = t >> 6;             // 0..3: nn quarter
    const int s_t = t & 63;
    const int d0 = (s_t >> 3) * 4;
    const int e0 = (s_t & 7) * 4;

    float a[4][4];
    #pragma unroll
    for (int i = 0; i < 4; i++)
        #pragma unroll
        for (int j = 0; j < 4; j++) a[i][j] = 0.f;

    for (int tile = 0; tile < 4; tile++) {
        const int n0 = ch * 512 + tile * 128;
        #pragma unroll
        for (int j = 0; j < 4; j++) {
            const int c = lc0 + j * 4;
            const float4 kv = *(const float4*)(kbase + (size_t)lrow * NP + n0 + c);
            ks[lrow][c + 0] = __expf(kv.x - kmax) * kinv;
            ks[lrow][c + 1] = __expf(kv.y - kmax) * kinv;
            ks[lrow][c + 2] = __expf(kv.z - kmax) * kinv;
            ks[lrow][c + 3] = __expf(kv.w - kmax) * kinv;
            const float4 vv = *(const float4*)(vbase + (size_t)lrow * NP + n0 + c);
            vs[lrow][c + 0] = vv.x * (1.f / 4096.f);
            vs[lrow][c + 1] = vv.y * (1.f / 4096.f);
            vs[lrow][c + 2] = vv.z * (1.f / 4096.f);
            vs[lrow][c + 3] = vv.w * (1.f / 4096.f);
        }
        __syncthreads();
        const int nb = sub * 32;
        #pragma unroll
        for (int nn = 0; nn < 32; nn++) {
            const int n = nb + nn;
            const float k0v = ks[d0][n],     k1v = ks[d0 + 1][n];
            const float k2v = ks[d0 + 2][n], k3v = ks[d0 + 3][n];
            const float v0  = vs[e0][n],     v1  = vs[e0 + 1][n];
            const float v2  = vs[e0 + 2][n], v3  = vs[e0 + 3][n];
            a[0][0] += k0v * v0; a[0][1] += k0v * v1; a[0][2] += k0v * v2; a[0][3] += k0v * v3;
            a[1][0] += k1v * v0; a[1][1] += k1v * v1; a[1][2] += k1v * v2; a[1][3] += k1v * v3;
            a[2][0] += k2v * v0; a[2][1] += k2v * v1; a[2][2] += k2v * v2; a[2][3] += k2v * v3;
            a[3][0] += k3v * v0; a[3][1] += k3v * v1; a[3][2] += k3v * v2; a[3][3] += k3v * v3;
        }
        __syncthreads();
    }
    // Deterministic in-block reduce of the 4 nn-quarter copies.
    #pragma unroll
    for (int i = 0; i < 4; i++)
        #pragma unroll
        for (int j = 0; j < 4; j++)
            red[sub][(d0 + i) * 32 + e0 + j] = a[i][j];
    __syncthreads();
    float* o = g_ctxp + ((size_t)ch * 64 + z) * 1024;
    #pragma unroll
    for (int i = 0; i < 4; i++) {
        const int idx = t * 4 + i;
        o[idx] = red[0][idx] + red[1][idx] + red[2][idx] + red[3][idx];
    }
}

__global__ void k_ctx_reduce()
{
    const int i = blockIdx.x * 256 + threadIdx.x;
    float s = 0.f;
    #pragma unroll
    for (int ch = 0; ch < 8; ch++) s += g_ctxp[(size_t)ch * 65536 + i];
    g_ctx[i] = s;
}

// ---------------------------------------------------------------------------
// K4a: q-softmax + attn = ctx^T @ qs, emitted as fp16 hi rows g_ah[(b*4096+p)][128].
// ---------------------------------------------------------------------------
__global__ __launch_bounds__(256) void k_attn()
{
    __shared__ float sq[128][36];
    __shared__ float sctx[4][32][33];
    const int t  = threadIdx.x;
    const int p0 = blockIdx.x * 32;
    const int b  = blockIdx.y;
    const float* qb = g_qkv + (size_t)b * QKV_CH * NP;

    {
        const int row = t >> 1, hf = (t & 1) * 16;
        #pragma unroll
        for (int j = 0; j < 4; j++) {
            const float4 v = *(const float4*)(qb + (size_t)row * NP + p0 + hf + j * 4);
            const int c = hf + j * 4;
            sq[row][c] = v.x; sq[row][c + 1] = v.y; sq[row][c + 2] = v.z; sq[row][c + 3] = v.w;
        }
    }
    {
        const float* cb = g_ctx + (size_t)b * NH * 1024;
        #pragma unroll
        for (int i = 0; i < 16; i++) {
            const int idx = t + i * 256;
            sctx[idx >> 10][(idx >> 5) & 31][idx & 31] = cb[idx];
        }
    }
    __syncthreads();

    if (t < 128) {
        const int h = t >> 5, p = t & 31;
        float m = -3.402823e38f;
        #pragma unroll
        for (int d = 0; d < 32; d++) m = fmaxf(m, sq[h * 32 + d][p]);
        float s = 0.f;
        #pragma unroll
        for (int d = 0; d < 32; d++) s += __expf(sq[h * 32 + d][p] - m);
        const float inv = 0.17677669529663687f / s;
        #pragma unroll
        for (int d = 0; d < 32; d++) sq[h * 32 + d][p] = __expf(sq[h * 32 + d][p] - m) * inv;
    }
    __syncthreads();

    float acc[16];
    const int c  = t >> 1;
    const int ph = (t & 1) * 16;
    {
        const int h = c >> 5, e = c & 31;
        #pragma unroll
        for (int i = 0; i < 16; i++) acc[i] = 0.f;
        #pragma unroll
        for (int d = 0; d < 32; d++) {
            const float cv = sctx[h][d][e];
            #pragma unroll
            for (int j = 0; j < 4; j++) {
                const float4 qv = *(const float4*)&sq[h * 32 + d][ph + j * 4];
                acc[j * 4 + 0] += cv * qv.x;
                acc[j * 4 + 1] += cv * qv.y;
                acc[j * 4 + 2] += cv * qv.z;
                acc[j * 4 + 3] += cv * qv.w;
            }
        }
    }
    __syncthreads();
    #pragma unroll
    for (int i = 0; i < 16; i++) sq[c][ph + i] = acc[i];
    __syncthreads();

    {
        const int p = t & 31, s = t >> 5;    // s: 16-channel group
        union { __half h[16]; uint4 u[2]; } hb;
        #pragma unroll
        for (int j = 0; j < 16; j++) hb.h[j] = __float2half(sq[s * 16 + j][p]);
        __half* row = g_ah + ((size_t)b * NP + p0 + p) * 128 + s * 16;
        ((uint4*)row)[0] = hb.u[0];
        ((uint4*)row)[1] = hb.u[1];
    }
}

// ---------------------------------------------------------------------------
// K4b: out = LN(w_out @ attn + b_out) * g. M=256 (LN fused), N=32, fp16 2-term:
// A = g_woh K'=256 [hi|lo] with 3-stage pipeline; B = g_ah 32x128 fully
// resident in smem (loaded once).
// ---------------------------------------------------------------------------
__global__ __launch_bounds__(256) void k_out_mma(
    const float* __restrict__ b_out, const float* __restrict__ g, float* __restrict__ out)
{
    __shared__ char smem_raw[70144];
    // GEMM: sA 3 stages x 256 rows x 80B at [0, 61440); sB 32 x 272B at [61440, 70144)
    // Epilogue (after final sync): ys[256][33] f32 at [0, 33792); red at [33792, ...)
    const uint32_t aBase = smem_u32(smem_raw);
    const uint32_t bBase = aBase + 61440;
    float* ys   = (float*)smem_raw;
    float* redS = (float*)(smem_raw + 33792);
    float* redQ = redS + 256;
    float* smu  = redQ + 256;
    float* srs  = smu + 32;

    const int tid  = threadIdx.x;
    const int wid  = tid >> 5, lane = tid & 31;
    const int n0 = blockIdx.x * 32;
    const int b  = blockIdx.y;
    const int warp_m = wid >> 1, warp_n = wid & 1;
    const uint32_t ABUF = 256 * 80;   // 20480

    const __half* __restrict__ Bg = g_ah + ((size_t)b * NP + n0) * 128;

    const int a_r = tid >> 2, a_ch = tid & 3;
    const int aRowL = warp_m * 64 + (lane & 15);
    const uint32_t aCol16 = (uint32_t)(lane >> 4) * 16;
    const int bg = lane >> 3, blr = lane & 7;
    const int bRowL = warp_n * 16 + (bg >> 1) * 8 + blr;
    const uint32_t bCol16 = (uint32_t)(bg & 1) * 16;

    float d[4][2][4];
    #pragma unroll
    for (int mf = 0; mf < 4; mf++)
        #pragma unroll
        for (int nf = 0; nf < 2; nf++)
            #pragma unroll
            for (int r = 0; r < 4; r++) d[mf][nf][r] = 0.f;

    // Prologue: group0 = B (full) + A stage 0; group1 = A stage 1.
    #pragma unroll
    for (int i = 0; i < 2; i++) {
        const int slot = tid + i * 256;
        const int r = slot >> 4, ch = slot & 15;
        cp16(bBase + (uint32_t)r * 272 + ch * 16, Bg + (size_t)r * 128 + ch * 8);
    }
    #pragma unroll
    for (int i = 0; i < 4; i++) {
        const int row = a_r + i * 64;
        cp16(aBase + (uint32_t)row * 80 + a_ch * 16, g_woh + (size_t)row * 256 + a_ch * 8);
    }
    cp_commit();
    #pragma unroll
    for (int i = 0; i < 4; i++) {
        const int row = a_r + i * 64;
        cp16(aBase + ABUF + (uint32_t)row * 80 + a_ch * 16,
             g_woh + (size_t)row * 256 + 32 + a_ch * 8);
    }
    cp_commit();

    int buf = 0;
    for (int it = 0; it < 8; it++) {
        cp_wait1();
        __syncthreads();
        if (it + 2 < 8) {
            int nb = buf + 2; if (nb >= 3) nb -= 3;
            const int k0 = (it + 2) * 32;
            #pragma unroll
            for (int i = 0; i < 4; i++) {
                const int row = a_r + i * 64;
                cp16(aBase + (uint32_t)nb * ABUF + (uint32_t)row * 80 + a_ch * 16,
                     g_woh + (size_t)row * 256 + k0 + a_ch * 8);
            }
        }
        cp_commit();
        const uint32_t ab = aBase + (uint32_t)buf * ABUF;
        #pragma unroll
        for (int ks = 0; ks < 2; ks++) {
            const int kslot = (it * 2 + ks) & 7;     // B col chunk (k mod 128)
            uint32_t rb[2][2];
            {
                uint32_t r0, r1, r2, r3;
                const uint32_t addr = bBase + (uint32_t)bRowL * 272 + kslot * 32 + bCol16;
                ldmatrix_x4(r0, r1, r2, r3, addr);
                rb[0][0] = r0; rb[0][1] = r1;
                rb[1][0] = r2; rb[1][1] = r3;
            }
            uint32_t ra[4][4];
            #pragma unroll
            for (int mf = 0; mf < 4; mf++) {
                const uint32_t addr = ab + (uint32_t)(aRowL + mf * 16) * 80 + ks * 32 + aCol16;
                ldmatrix_x4(ra[mf][0], ra[mf][1], ra[mf][2], ra[mf][3], addr);
            }
            #pragma unroll
            for (int mf = 0; mf < 4; mf++)
                #pragma unroll
                for (int nf = 0; nf < 2; nf++)
                    mma_f16(d[mf][nf], ra[mf], rb[nf]);
        }
        buf++; if (buf == 3) buf = 0;
    }
    __syncthreads();   // GEMM done before smem reuse as ys

    // Epilogue: bias -> ys -> LN over 256 channels -> write
    const int mB = warp_m * 64 + (lane >> 2);
    const int nB = warp_n * 16 + (lane & 3) * 2;
    #pragma unroll
    for (int mf = 0; mf < 4; mf++) {
        #pragma unroll
        for (int nf = 0; nf < 2; nf++) {
            const int m = mB + mf * 16;
            const int n = nB + nf * 8;
            const float bo0 = b_out[m], bo1 = b_out[m + 8];
            ys[m * 33 + n]           = d[mf][nf][0] + bo0;
            ys[m * 33 + n + 1]       = d[mf][nf][1] + bo0;
            ys[(m + 8) * 33 + n]     = d[mf][nf][2] + bo1;
            ys[(m + 8) * 33 + n + 1] = d[mf][nf][3] + bo1;
        }
    }
    __syncthreads();
    {
        float s = 0.f, q = 0.f;
        #pragma unroll
        for (int c = 0; c < 32; c++) {
            const float v = ys[(wid * 32 + c) * 33 + lane];
            s += v; q += v * v;
        }
        redS[wid * 32 + lane] = s;
        redQ[wid * 32 + lane] = q;
    }
    __syncthreads();
    if (tid < 32) {
        float s = 0.f, q = 0.f;
        #pragma unroll
        for (int w = 0; w < 8; w++) { s += redS[w * 32 + tid]; q += redQ[w * 32 + tid]; }
        const float mu  = s * (1.f / 256.f);
        const float var = q * (1.f / 256.f) - mu * mu;
        smu[tid] = mu;
        srs[tid] = rsqrtf(var + 1e-5f);
    }
    __syncthreads();
    {
        const int n2 = tid & 31;
        const float mu = smu[n2], rs = srs[n2];
        float* ob = out + (size_t)b * C_ * NP + n0 + n2;
        for (int o = tid >> 5; o < C_; o += 8) {
            ob[(size_t)o * NP] = (ys[o * 33 + n2] - mu) * rs * g[o];
        }
    }
}

// ---------------------------------------------------------------------------
extern "C" void kernel_launch(void* const* d_in, const int* in_sizes, int n_in,
                              void* d_out, int out_size)
{
    const float* x     = (const float*)d_in[0];
    const float* w_qkv = (const float*)d_in[1];
    const float* w_out = (const float*)d_in[2];
    const float* b_out = (const float*)d_in[3];
    const float* g     = (const float*)d_in[4];
    float* out = (float*)d_out;
    (void)in_sizes; (void)n_in; (void)out_size;

    k_conv_weights<<<512, 256>>>(w_qkv, w_out);
    k_conv_x<<<dim3(NP / 32, C_ / 32, B_), 256>>>(x);
    k_qkv_mma<<<dim3(32, 3, 16), 256>>>();
    k_kstats<<<2048, 256>>>();
    k_context<<<dim3(8, 64), 256>>>();
    k_ctx_reduce<<<256, 256>>>();
    k_attn<<<dim3(NP / 32, B_), 256>>>();
    k_out_mma<<<dim3(NP / 32, B_), 256>>>(b_out, g, out);
}

// round 11
// speedup vs baseline: 2.6001x; 1.0648x over previous
#include <cuda_runtime.h>
#include <cuda_fp16.h>
#include <cstdint>
#include <cstddef>

// Problem constants
#define B_     16
#define C_     256
#define HID    128
#define NH     4
#define DH     32
#define NP     4096       // 64*64 spatial positions
#define QKV_CH 384

// Scratch (device globals: allocation-free rule)
__device__ float  g_qkv[(size_t)B_ * QKV_CH * NP];   // qkv = w_qkv @ x (fp32)
__device__ float2 g_kstat[B_ * HID];
__device__ float  g_ctxp[8 * 64 * 1024];
__device__ float  g_ctx [64 * 1024];
__device__ __half g_wh [(size_t)QKV_CH * 512];       // w_qkv fp16 split: [hi(256)|lo(256)]
__device__ __half g_xh [(size_t)B_ * NP * 256];      // x^T fp16 hi (33MB)
__device__ __half g_woh[(size_t)C_ * 256];           // w_out fp16 split: [hi(128)|lo(128)]

// ---------------------------------------------------------------------------
// Portable PTX helpers (sm_80+ only — harness lowers via compute_103 (non-'a'))
// ---------------------------------------------------------------------------
__device__ __forceinline__ uint32_t smem_u32(const void* p) {
    uint32_t a;
    asm("{ .reg .u64 t; cvta.to.shared.u64 t, %1; cvt.u32.u64 %0, t; }" : "=r"(a) : "l"(p));
    return a;
}
__device__ __forceinline__ void cp16(uint32_t s, const void* g) {
    asm volatile("cp.async.cg.shared.global [%0], [%1], 16;" :: "r"(s), "l"(g));
}
__device__ __forceinline__ void cp_commit() {
    asm volatile("cp.async.commit_group;" ::: "memory");
}
__device__ __forceinline__ void cp_wait1() {
    asm volatile("cp.async.wait_group 1;" ::: "memory");
}
__device__ __forceinline__ void ldmatrix_x4(uint32_t& r0, uint32_t& r1,
                                            uint32_t& r2, uint32_t& r3, uint32_t addr) {
    asm volatile("ldmatrix.sync.aligned.m8n8.x4.shared.b16 {%0,%1,%2,%3}, [%4];"
                 : "=r"(r0), "=r"(r1), "=r"(r2), "=r"(r3) : "r"(addr));
}
__device__ __forceinline__ void mma_f16(float* d, const uint32_t* a, const uint32_t* b) {
    asm volatile(
        "mma.sync.aligned.m16n8k16.row.col.f32.f16.f16.f32 "
        "{%0,%1,%2,%3}, {%4,%5,%6,%7}, {%8,%9}, {%0,%1,%2,%3};"
        : "+f"(d[0]), "+f"(d[1]), "+f"(d[2]), "+f"(d[3])
        : "r"(a[0]), "r"(a[1]), "r"(a[2]), "r"(a[3]), "r"(b[0]), "r"(b[1]));
}

// ---------------------------------------------------------------------------
// K0: ALL input conversions in one launch.
// blocks [0,16384):      x [b][256][4096] -> g_xh [b*4096+p][256] fp16 (32x32 transpose)
// blocks [16384,16768):  w_qkv -> g_wh [o][512] = [hi|lo]
// blocks [16768,16896):  w_out -> g_woh [o][256] = [hi|lo]
// ---------------------------------------------------------------------------
__global__ __launch_bounds__(256) void k_conv_all(
    const float* __restrict__ x, const float* __restrict__ wq, const float* __restrict__ wo)
{
    __shared__ float tile[32][33];
    const int bid = blockIdx.x;
    if (bid < 16384) {
        const int b  = bid >> 10;
        const int c0 = ((bid >> 7) & 7) * 32;
        const int p0 = (bid & 127) * 32;
        const int tp = threadIdx.x & 31, tc = threadIdx.x >> 5;
        #pragma unroll
        for (int j = 0; j < 4; j++) {
            const int c = tc + j * 8;
            tile[c][tp] = x[((size_t)b * C_ + c0 + c) * NP + p0 + tp];
        }
        __syncthreads();
        if (threadIdx.x < 128) {
            const int p = threadIdx.x >> 2, ch = threadIdx.x & 3;
            union { __half h[8]; uint4 u; } vb;
            #pragma unroll
            for (int j = 0; j < 8; j++) vb.h[j] = __float2half(tile[ch * 8 + j][p]);
            *(uint4*)(g_xh + ((size_t)b * NP + p0 + p) * 256 + c0 + ch * 8) = vb.u;
        }
    } else if (bid < 16768) {
        const int i = (bid - 16384) * 256 + threadIdx.x;    // < 98304
        const float v = wq[i];
        const int o = i >> 8, c = i & 255;
        const __half hi = __float2half(v);
        const __half lo = __float2half(v - __half2float(hi));
        g_wh[(size_t)o * 512 + c]       = hi;
        g_wh[(size_t)o * 512 + 256 + c] = lo;
    } else {
        const int i = (bid - 16768) * 256 + threadIdx.x;    // < 32768
        const float v = wo[i];
        const int o = i >> 7, c = i & 127;
        const __half hi = __float2half(v);
        const __half lo = __float2half(v - __half2float(hi));
        g_woh[(size_t)o * 256 + c]       = hi;
        g_woh[(size_t)o * 256 + 128 + c] = lo;
    }
}

// ---------------------------------------------------------------------------
// K1: qkv GEMM, fp16 2-term split (unchanged from R10 — jointly tensor/smem
// bound at ~84us; deeper pipelining measured neutral).
// ---------------------------------------------------------------------------
__global__ __launch_bounds__(256) void k_qkv_mma()
{
    __shared__ __half sA[3][128][72];
    __shared__ __half sB[3][128][40];
    const int tid  = threadIdx.x;
    const int wid  = tid >> 5, lane = tid & 31;
    const int n0 = blockIdx.x * 128;
    const int m0 = blockIdx.y * 128;
    const int b  = blockIdx.z;
    const int warp_m = wid >> 1, warp_n = wid & 1;

    const __half* __restrict__ Ag = g_wh + (size_t)m0 * 512;
    const __half* __restrict__ Bg = g_xh + ((size_t)b * NP + n0) * 256;

    const uint32_t aBase = smem_u32(&sA[0][0][0]);
    const uint32_t bBase = smem_u32(&sB[0][0][0]);
    const uint32_t ABUF = 128 * 144;
    const uint32_t BBUF = 128 * 80;

    uint32_t aso[4]; uint32_t agi[4];
    #pragma unroll
    for (int i = 0; i < 4; i++) {
        const int slot = tid + i * 256;
        const int r = slot >> 3, ch = slot & 7;
        aso[i] = (uint32_t)r * 144 + ch * 16;
        agi[i] = (uint32_t)r * 512 + (ch < 4 ? ch * 8 : 256 + (ch - 4) * 8);
    }
    uint32_t bso[2]; uint32_t bgi[2];
    #pragma unroll
    for (int i = 0; i < 2; i++) {
        const int slot = tid + i * 256;
        const int r = slot >> 2, ch = slot & 3;
        bso[i] = (uint32_t)r * 80 + ch * 16;
        bgi[i] = (uint32_t)r * 256 + ch * 8;
    }

    const int aRowL = warp_m * 32 + (lane & 15);
    const uint32_t aCol16 = (uint32_t)(lane >> 4) * 16;
    const int bg = lane >> 3, blr = lane & 7;
    const int bRowL = warp_n * 64 + (bg >> 1) * 8 + blr;
    const uint32_t bCol16 = (uint32_t)(bg & 1) * 16;

    float d[2][8][4];
    #pragma unroll
    for (int mf = 0; mf < 2; mf++)
        #pragma unroll
        for (int nf = 0; nf < 8; nf++)
            #pragma unroll
            for (int r = 0; r < 4; r++) d[mf][nf][r] = 0.f;

    #pragma unroll
    for (int s = 0; s < 2; s++) {
        const int k0 = s * 32;
        #pragma unroll
        for (int i = 0; i < 4; i++) cp16(aBase + s * ABUF + aso[i], Ag + agi[i] + k0);
        #pragma unroll
        for (int i = 0; i < 2; i++) cp16(bBase + s * BBUF + bso[i], Bg + bgi[i] + k0);
        cp_commit();
    }

    int buf = 0;
    for (int it = 0; it < 8; it++) {
        cp_wait1();
        __syncthreads();
        if (it + 2 < 8) {
            int nb = buf + 2; if (nb >= 3) nb -= 3;
            const int k0 = (it + 2) * 32;
            #pragma unroll
            for (int i = 0; i < 4; i++) cp16(aBase + (uint32_t)nb * ABUF + aso[i], Ag + agi[i] + k0);
            #pragma unroll
            for (int i = 0; i < 2; i++) cp16(bBase + (uint32_t)nb * BBUF + bso[i], Bg + bgi[i] + k0);
        }
        cp_commit();
        const uint32_t ab = aBase + (uint32_t)buf * ABUF;
        const uint32_t bb = bBase + (uint32_t)buf * BBUF;
        #pragma unroll
        for (int ks = 0; ks < 2; ks++) {
            uint32_t rb[8][2];
            #pragma unroll
            for (int nf2 = 0; nf2 < 4; nf2++) {
                uint32_t r0, r1, r2, r3;
                const uint32_t addr = bb + (uint32_t)(bRowL + nf2 * 16) * 80 + ks * 32 + bCol16;
                ldmatrix_x4(r0, r1, r2, r3, addr);
                rb[nf2 * 2][0] = r0;     rb[nf2 * 2][1] = r1;
                rb[nf2 * 2 + 1][0] = r2; rb[nf2 * 2 + 1][1] = r3;
            }
            #pragma unroll
            for (int seg = 0; seg < 2; seg++) {
                uint32_t ra[2][4];
                #pragma unroll
                for (int mf = 0; mf < 2; mf++) {
                    const uint32_t addr = ab + (uint32_t)(aRowL + mf * 16) * 144
                                        + seg * 64 + ks * 32 + aCol16;
                    ldmatrix_x4(ra[mf][0], ra[mf][1], ra[mf][2], ra[mf][3], addr);
                }
                #pragma unroll
                for (int mf = 0; mf < 2; mf++)
                    #pragma unroll
                    for (int nf = 0; nf < 8; nf++)
                        mma_f16(d[mf][nf], ra[mf], rb[nf]);
            }
        }
        buf++; if (buf == 3) buf = 0;
    }

    const int mBase = m0 + warp_m * 32 + (lane >> 2);
    const int nBase = n0 + warp_n * 64 + (lane & 3) * 2;
    float* outb = g_qkv + (size_t)b * QKV_CH * NP;
    #pragma unroll
    for (int mf = 0; mf < 2; mf++) {
        #pragma unroll
        for (int nf = 0; nf < 8; nf++) {
            const int m = mBase + mf * 16;
            const int n = nBase + nf * 8;
            *(float2*)(outb + (size_t)m * NP + n)       = make_float2(d[mf][nf][0], d[mf][nf][1]);
            *(float2*)(outb + (size_t)(m + 8) * NP + n) = make_float2(d[mf][nf][2], d[mf][nf][3]);
        }
    }
}

// ---------------------------------------------------------------------------
// K2: per k-row stats (unchanged).
// ---------------------------------------------------------------------------
__global__ __launch_bounds__(256) void k_kstats()
{
    __shared__ float red[256];
    const int row = blockIdx.x;
    const int b = row >> 7, ko = row & 127;
    const float* base = g_qkv + (size_t)b * QKV_CH * NP + (size_t)(HID + ko) * NP;
    const int t = threadIdx.x;
    float vals[16];
    #pragma unroll
    for (int j = 0; j < 4; j++) {
        const float4 v = *(const float4*)(base + (j * 256 + t) * 4);
        vals[j * 4 + 0] = v.x; vals[j * 4 + 1] = v.y;
        vals[j * 4 + 2] = v.z; vals[j * 4 + 3] = v.w;
    }
    float m = vals[0];
    #pragma unroll
    for (int i = 1; i < 16; i++) m = fmaxf(m, vals[i]);
    red[t] = m; __syncthreads();
    for (int off = 128; off > 0; off >>= 1) {
        if (t < off) red[t] = fmaxf(red[t], red[t + off]);
        __syncthreads();
    }
    m = red[0];
    __syncthreads();
    float s = 0.f;
    #pragma unroll
    for (int i = 0; i < 16; i++) s += __expf(vals[i] - m);
    red[t] = s; __syncthreads();
    for (int off = 128; off > 0; off >>= 1) {
        if (t < off) red[t] += red[t + off];
        __syncthreads();
    }
    if (t == 0) g_kstat[row] = make_float2(m, 1.f / red[0]);
}

// ---------------------------------------------------------------------------
// K3: context partials (unchanged from R10).
// ---------------------------------------------------------------------------
__global__ __launch_bounds__(256) void k_context()
{
    __shared__ float ks[32][133];
    __shared__ float vs[32][133];
    __shared__ float red[4][1024];
    const int ch = blockIdx.x;
    const int z  = blockIdx.y;
    const int b = z >> 2, h = z & 3;
    const float* kbase = g_qkv + ((size_t)b * QKV_CH + HID + h * DH) * NP;
    const float* vbase = g_qkv + ((size_t)b * QKV_CH + 2 * HID + h * DH) * NP;
    const int t = threadIdx.x;
    const int lrow = t >> 3;
    const int lc0  = (t & 7) * 16;
    const float2 st = g_kstat[b * HID + h * DH + lrow];
    const float kmax = st.x, kinv = st.y;
    const int sub = t >> 6;
    const int s_t = t & 63;
    const int d0 = (s_t >> 3) * 4;
    const int e0 = (s_t & 7) * 4;

    float a[4][4];
    #pragma unroll
    for (int i = 0; i < 4; i++)
        #pragma unroll
        for (int j = 0; j < 4; j++) a[i][j] = 0.f;

    for (int tile = 0; tile < 4; tile++) {
        const int n0 = ch * 512 + tile * 128;
        #pragma unroll
        for (int j = 0; j < 4; j++) {
            const int c = lc0 + j * 4;
            const float4 kv = *(const float4*)(kbase + (size_t)lrow * NP + n0 + c);
            ks[lrow][c + 0] = __expf(kv.x - kmax) * kinv;
            ks[lrow][c + 1] = __expf(kv.y - kmax) * kinv;
            ks[lrow][c + 2] = __expf(kv.z - kmax) * kinv;
            ks[lrow][c + 3] = __expf(kv.w - kmax) * kinv;
            const float4 vv = *(const float4*)(vbase + (size_t)lrow * NP + n0 + c);
            vs[lrow][c + 0] = vv.x * (1.f / 4096.f);
            vs[lrow][c + 1] = vv.y * (1.f / 4096.f);
            vs[lrow][c + 2] = vv.z * (1.f / 4096.f);
            vs[lrow][c + 3] = vv.w * (1.f / 4096.f);
        }
        __syncthreads();
        const int nb = sub * 32;
        #pragma unroll
        for (int nn = 0; nn < 32; nn++) {
            const int n = nb + nn;
            const float k0v = ks[d0][n],     k1v = ks[d0 + 1][n];
            const float k2v = ks[d0 + 2][n], k3v = ks[d0 + 3][n];
            const float v0  = vs[e0][n],     v1  = vs[e0 + 1][n];
            const float v2  = vs[e0 + 2][n], v3  = vs[e0 + 3][n];
            a[0][0] += k0v * v0; a[0][1] += k0v * v1; a[0][2] += k0v * v2; a[0][3] += k0v * v3;
            a[1][0] += k1v * v0; a[1][1] += k1v * v1; a[1][2] += k1v * v2; a[1][3] += k1v * v3;
            a[2][0] += k2v * v0; a[2][1] += k2v * v1; a[2][2] += k2v * v2; a[2][3] += k2v * v3;
            a[3][0] += k3v * v0; a[3][1] += k3v * v1; a[3][2] += k3v * v2; a[3][3] += k3v * v3;
        }
        __syncthreads();
    }
    #pragma unroll
    for (int i = 0; i < 4; i++)
        #pragma unroll
        for (int j = 0; j < 4; j++)
            red[sub][(d0 + i) * 32 + e0 + j] = a[i][j];
    __syncthreads();
    float* o = g_ctxp + ((size_t)ch * 64 + z) * 1024;
    #pragma unroll
    for (int i = 0; i < 4; i++) {
        const int idx = t * 4 + i;
        o[idx] = red[0][idx] + red[1][idx] + red[2][idx] + red[3][idx];
    }
}

__global__ void k_ctx_reduce()
{
    const int i = blockIdx.x * 256 + threadIdx.x;
    float s = 0.f;
    #pragma unroll
    for (int ch = 0; ch < 8; ch++) s += g_ctxp[(size_t)ch * 65536 + i];
    g_ctx[i] = s;
}

// ---------------------------------------------------------------------------
// K4: FUSED attn + out-conv + LayerNorm. Grid (64 p-tiles of 64, 16 b).
// Phase 1: q-softmax + attn=ctx^T@qs for 64 positions; thread=(h,p) so ctx
//          smem reads are warp-broadcast. Result -> smem fp16 B tile [64][128].
// Phase 2: HMMA GEMM M=256 (LN fusable), N=64, K'=256 (w_out [hi|lo] 3-stage
//          ring); B never touches global. Epilogue: bias + LN + write.
// ---------------------------------------------------------------------------
__global__ __launch_bounds__(256, 2) void k_attn_out(
    const float* __restrict__ b_out, const float* __restrict__ g, float* __restrict__ out)
{
    __shared__ alignas(128) char smem_raw[83456];
    // [0,61440): A ring 3x20480   (phase1: sq [0,34816) + sctx [34816,53248))
    // [61440,78848): B fp16 [64][136] (272B rows)
    // epilogue: ys[256][66] f32 at [0,67584); red at [78848,...)
    const uint32_t aBase = smem_u32(smem_raw);
    const uint32_t bBase = aBase + 61440;
    float* sq   = (float*)smem_raw;                 // [128][68]
    float* sctx = (float*)(smem_raw + 34816);       // [4][32][36]
    __half* sbh = (__half*)(smem_raw + 61440);      // [64][136]
    float* ys   = (float*)smem_raw;                 // [256][66]
    float* redS = (float*)(smem_raw + 78848);       // [8][64]
    float* redQ = (float*)(smem_raw + 80896);       // [8][64]
    float* smu  = (float*)(smem_raw + 82944);       // [64]
    float* srs  = (float*)(smem_raw + 83200);       // [64]

    const int t  = threadIdx.x;
    const int p0 = blockIdx.x * 64;
    const int b  = blockIdx.y;

    // ---- Phase 1: load q + ctx ----
    {
        const float* qb = g_qkv + (size_t)b * QKV_CH * NP;
        const int row = t >> 1, hf = (t & 1) * 32;
        #pragma unroll
        for (int j = 0; j < 8; j++) {
            const float4 v = *(const float4*)(qb + (size_t)row * NP + p0 + hf + j * 4);
            const int c = hf + j * 4;
            sq[row * 68 + c] = v.x; sq[row * 68 + c + 1] = v.y;
            sq[row * 68 + c + 2] = v.z; sq[row * 68 + c + 3] = v.w;
        }
        const float* cb = g_ctx + (size_t)b * NH * 1024;
        #pragma unroll
        for (int i = 0; i < 16; i++) {
            const int idx = t + i * 256;
            sctx[(idx >> 10) * 1152 + ((idx >> 5) & 31) * 36 + (idx & 31)] = cb[idx];
        }
    }
    __syncthreads();

    const int h1 = t >> 6, p1 = t & 63;   // phase-1 thread identity
    // q softmax over d, fold SCALE; write back
    {
        float m = -3.402823e38f;
        #pragma unroll
        for (int d = 0; d < 32; d++) m = fmaxf(m, sq[(h1 * 32 + d) * 68 + p1]);
        float s = 0.f;
        #pragma unroll
        for (int d = 0; d < 32; d++) s += __expf(sq[(h1 * 32 + d) * 68 + p1] - m);
        const float inv = 0.17677669529663687f / s;
        #pragma unroll
        for (int d = 0; d < 32; d++)
            sq[(h1 * 32 + d) * 68 + p1] = __expf(sq[(h1 * 32 + d) * 68 + p1] - m) * inv;
    }
    __syncthreads();

    // attn[e][p1] for e in 0..31 of head h1 (ctx reads broadcast within warp)
    float acc[32];
    #pragma unroll
    for (int i = 0; i < 32; i++) acc[i] = 0.f;
    #pragma unroll
    for (int d = 0; d < 32; d++) {
        const float qv = sq[(h1 * 32 + d) * 68 + p1];
        const float* cr = sctx + h1 * 1152 + d * 36;
        #pragma unroll
        for (int e4 = 0; e4 < 8; e4++) {
            const float4 cv = *(const float4*)(cr + e4 * 4);
            acc[e4 * 4 + 0] += cv.x * qv;
            acc[e4 * 4 + 1] += cv.y * qv;
            acc[e4 * 4 + 2] += cv.z * qv;
            acc[e4 * 4 + 3] += cv.w * qv;
        }
    }
    __syncthreads();   // all sq/sctx reads done -> A region reusable

    // ---- A prologue (overwrites sq/sctx region via cp.async) + B smem write ----
    const uint32_t ABUF = 20480;
    const int a_r = t >> 2, a_ch = t & 3;
    #pragma unroll
    for (int s = 0; s < 2; s++) {
        const int k0 = s * 32;
        #pragma unroll
        for (int i = 0; i < 4; i++) {
            const int row = a_r + i * 64;
            cp16(aBase + (uint32_t)s * ABUF + (uint32_t)row * 80 + a_ch * 16,
                 g_woh + (size_t)row * 256 + k0 + a_ch * 8);
        }
        cp_commit();
    }
    {   // write attn hi fp16: row p1, cols h1*32..+32 (64B contiguous)
        union { __half h[32]; uint4 u[4]; } hb;
        #pragma unroll
        for (int i = 0; i < 32; i++) hb.h[i] = __float2half(acc[i]);
        uint4* dst = (uint4*)(sbh + p1 * 136 + h1 * 32);
        dst[0] = hb.u[0]; dst[1] = hb.u[1]; dst[2] = hb.u[2]; dst[3] = hb.u[3];
    }

    // ---- Phase 2: GEMM M=256 x N=64 x K'=256 ----
    const int wid = t >> 5, lane = t & 31;
    const int warp_m = wid >> 1, warp_n = wid & 1;
    const int aRowL = warp_m * 64 + (lane & 15);
    const uint32_t aCol16 = (uint32_t)(lane >> 4) * 16;
    const int bg = lane >> 3, blr = lane & 7;
    const int bRowL = warp_n * 32 + (bg >> 1) * 8 + blr;
    const uint32_t bCol16 = (uint32_t)(bg & 1) * 16;

    float d[4][4][4];
    #pragma unroll
    for (int mf = 0; mf < 4; mf++)
        #pragma unroll
        for (int nf = 0; nf < 4; nf++)
            #pragma unroll
            for (int r = 0; r < 4; r++) d[mf][nf][r] = 0.f;

    int buf = 0;
    for (int it = 0; it < 8; it++) {
        cp_wait1();
        __syncthreads();    // also publishes sbh on it==0
        if (it + 2 < 8) {
            int nb = buf + 2; if (nb >= 3) nb -= 3;
            const int k0 = (it + 2) * 32;
            #pragma unroll
            for (int i = 0; i < 4; i++) {
                const int row = a_r + i * 64;
                cp16(aBase + (uint32_t)nb * ABUF + (uint32_t)row * 80 + a_ch * 16,
                     g_woh + (size_t)row * 256 + k0 + a_ch * 8);
            }
        }
        cp_commit();
        const uint32_t ab = aBase + (uint32_t)buf * ABUF;
        #pragma unroll
        for (int ks = 0; ks < 2; ks++) {
            const int kslot = (it * 2 + ks) & 7;     // B col chunk (k mod 128)
            uint32_t rb[4][2];
            #pragma unroll
            for (int nf2 = 0; nf2 < 2; nf2++) {
                uint32_t r0, r1, r2, r3;
                const uint32_t addr = bBase + (uint32_t)(bRowL + nf2 * 16) * 272
                                    + kslot * 32 + bCol16;
                ldmatrix_x4(r0, r1, r2, r3, addr);
                rb[nf2 * 2][0] = r0;     rb[nf2 * 2][1] = r1;
                rb[nf2 * 2 + 1][0] = r2; rb[nf2 * 2 + 1][1] = r3;
            }
            uint32_t ra[4][4];
            #pragma unroll
            for (int mf = 0; mf < 4; mf++) {
                const uint32_t addr = ab + (uint32_t)(aRowL + mf * 16) * 80 + ks * 32 + aCol16;
                ldmatrix_x4(ra[mf][0], ra[mf][1], ra[mf][2], ra[mf][3], addr);
            }
            #pragma unroll
            for (int mf = 0; mf < 4; mf++)
                #pragma unroll
                for (int nf = 0; nf < 4; nf++)
                    mma_f16(d[mf][nf], ra[mf], rb[nf]);
        }
        buf++; if (buf == 3) buf = 0;
    }
    __syncthreads();   // GEMM reads done -> smem reusable as ys

    // ---- Epilogue: bias -> ys -> LN over 256 channels -> write ----
    const int mB = warp_m * 64 + (lane >> 2);
    const int nB = warp_n * 32 + (lane & 3) * 2;
    #pragma unroll
    for (int mf = 0; mf < 4; mf++) {
        #pragma unroll
        for (int nf = 0; nf < 4; nf++) {
            const int m = mB + mf * 16;
            const int n = nB + nf * 8;
            const float bo0 = b_out[m], bo1 = b_out[m + 8];
            ys[m * 66 + n]           = d[mf][nf][0] + bo0;
            ys[m * 66 + n + 1]       = d[mf][nf][1] + bo0;
            ys[(m + 8) * 66 + n]     = d[mf][nf][2] + bo1;
            ys[(m + 8) * 66 + n + 1] = d[mf][nf][3] + bo1;
        }
    }
    __syncthreads();
    {   // warp wid sums channels [wid*32, wid*32+32) for positions lane, lane+32
        float s0 = 0.f, q0 = 0.f, s1 = 0.f, q1 = 0.f;
        #pragma unroll
        for (int c = 0; c < 32; c++) {
            const float v0 = ys[(wid * 32 + c) * 66 + lane];
            const float v1 = ys[(wid * 32 + c) * 66 + lane + 32];
            s0 += v0; q0 += v0 * v0;
            s1 += v1; q1 += v1 * v1;
        }
        redS[wid * 64 + lane] = s0;      redQ[wid * 64 + lane] = q0;
        redS[wid * 64 + lane + 32] = s1; redQ[wid * 64 + lane + 32] = q1;
    }
    __syncthreads();
    if (t < 64) {
        float s = 0.f, q = 0.f;
        #pragma unroll
        for (int w = 0; w < 8; w++) { s += redS[w * 64 + t]; q += redQ[w * 64 + t]; }
        const float mu  = s * (1.f / 256.f);
        const float var = q * (1.f / 256.f) - mu * mu;
        smu[t] = mu;
        srs[t] = rsqrtf(var + 1e-5f);
    }
    __syncthreads();
    {
        const int n2 = t & 63;
        const float mu = smu[n2], rs = srs[n2];
        float* ob = out + (size_t)b * C_ * NP + p0 + n2;
        for (int o = t >> 6; o < C_; o += 4) {
            ob[(size_t)o * NP] = (ys[o * 66 + n2] - mu) * rs * g[o];
        }
    }
}

// ---------------------------------------------------------------------------
extern "C" void kernel_launch(void* const* d_in, const int* in_sizes, int n_in,
                              void* d_out, int out_size)
{
    const float* x     = (const float*)d_in[0];
    const float* w_qkv = (const float*)d_in[1];
    const float* w_out = (const float*)d_in[2];
    const float* b_out = (const float*)d_in[3];
    const float* g     = (const float*)d_in[4];
    float* out = (float*)d_out;
    (void)in_sizes; (void)n_in; (void)out_size;

    k_conv_all<<<16896, 256>>>(x, w_qkv, w_out);
    k_qkv_mma<<<dim3(32, 3, 16), 256>>>();
    k_kstats<<<2048, 256>>>();
    k_context<<<dim3(8, 64), 256>>>();
    k_ctx_reduce<<<256, 256>>>();
    k_attn_out<<<dim3(64, 16), 256>>>(b_out, g, out);
}

// round 12
// speedup vs baseline: 2.8337x; 1.0898x over previous
#include <cuda_runtime.h>
#include <cuda_fp16.h>
#include <cstdint>
#include <cstddef>

// Problem constants
#define B_     16
#define C_     256
#define HID    128
#define NH     4
#define DH     32
#define NP     4096       // 64*64 spatial positions
#define QKV_CH 384

// Scratch (device globals: allocation-free rule)
__device__ float  g_qkv[(size_t)B_ * QKV_CH * NP];   // qkv = w_qkv @ x (fp32)
__device__ float  g_ctxp[4 * 64 * 1024];
__device__ float  g_ctx [64 * 1024];
__device__ __half g_wh [(size_t)QKV_CH * 512];       // w_qkv fp16 split: [hi(256)|lo(256)]
__device__ __half g_xh [(size_t)B_ * NP * 256];      // x^T fp16 hi (33MB)
__device__ __half g_woh[(size_t)C_ * 256];           // w_out fp16 split: [hi(128)|lo(128)]
__device__ __half g_keh[(size_t)B_ * HID * NP];      // softmax_n(k) fp16 (17MB)
__device__ __half g_vh [(size_t)B_ * HID * NP];      // v/4096 fp16 (17MB)

// ---------------------------------------------------------------------------
// Portable PTX helpers (sm_80+ only — harness lowers via compute_103 (non-'a'))
// ---------------------------------------------------------------------------
__device__ __forceinline__ uint32_t smem_u32(const void* p) {
    uint32_t a;
    asm("{ .reg .u64 t; cvta.to.shared.u64 t, %1; cvt.u32.u64 %0, t; }" : "=r"(a) : "l"(p));
    return a;
}
__device__ __forceinline__ void cp16(uint32_t s, const void* g) {
    asm volatile("cp.async.cg.shared.global [%0], [%1], 16;" :: "r"(s), "l"(g));
}
__device__ __forceinline__ void cp_commit() {
    asm volatile("cp.async.commit_group;" ::: "memory");
}
__device__ __forceinline__ void cp_wait1() {
    asm volatile("cp.async.wait_group 1;" ::: "memory");
}
__device__ __forceinline__ void ldmatrix_x4(uint32_t& r0, uint32_t& r1,
                                            uint32_t& r2, uint32_t& r3, uint32_t addr) {
    asm volatile("ldmatrix.sync.aligned.m8n8.x4.shared.b16 {%0,%1,%2,%3}, [%4];"
                 : "=r"(r0), "=r"(r1), "=r"(r2), "=r"(r3) : "r"(addr));
}
__device__ __forceinline__ void mma_f16(float* d, const uint32_t* a, const uint32_t* b) {
    asm volatile(
        "mma.sync.aligned.m16n8k16.row.col.f32.f16.f16.f32 "
        "{%0,%1,%2,%3}, {%4,%5,%6,%7}, {%8,%9}, {%0,%1,%2,%3};"
        : "+f"(d[0]), "+f"(d[1]), "+f"(d[2]), "+f"(d[3])
        : "r"(a[0]), "r"(a[1]), "r"(a[2]), "r"(a[3]), "r"(b[0]), "r"(b[1]));
}

// ---------------------------------------------------------------------------
// K0: ALL input conversions in one launch.
// ---------------------------------------------------------------------------
__global__ __launch_bounds__(256) void k_conv_all(
    const float* __restrict__ x, const float* __restrict__ wq, const float* __restrict__ wo)
{
    __shared__ float tile[32][33];
    const int bid = blockIdx.x;
    if (bid < 16384) {
        const int b  = bid >> 10;
        const int c0 = ((bid >> 7) & 7) * 32;
        const int p0 = (bid & 127) * 32;
        const int tp = threadIdx.x & 31, tc = threadIdx.x >> 5;
        #pragma unroll
        for (int j = 0; j < 4; j++) {
            const int c = tc + j * 8;
            tile[c][tp] = x[((size_t)b * C_ + c0 + c) * NP + p0 + tp];
        }
        __syncthreads();
        if (threadIdx.x < 128) {
            const int p = threadIdx.x >> 2, ch = threadIdx.x & 3;
            union { __half h[8]; uint4 u; } vb;
            #pragma unroll
            for (int j = 0; j < 8; j++) vb.h[j] = __float2half(tile[ch * 8 + j][p]);
            *(uint4*)(g_xh + ((size_t)b * NP + p0 + p) * 256 + c0 + ch * 8) = vb.u;
        }
    } else if (bid < 16768) {
        const int i = (bid - 16384) * 256 + threadIdx.x;
        const float v = wq[i];
        const int o = i >> 8, c = i & 255;
        const __half hi = __float2half(v);
        const __half lo = __float2half(v - __half2float(hi));
        g_wh[(size_t)o * 512 + c]       = hi;
        g_wh[(size_t)o * 512 + 256 + c] = lo;
    } else {
        const int i = (bid - 16768) * 256 + threadIdx.x;
        const float v = wo[i];
        const int o = i >> 7, c = i & 127;
        const __half hi = __float2half(v);
        const __half lo = __float2half(v - __half2float(hi));
        g_woh[(size_t)o * 256 + c]       = hi;
        g_woh[(size_t)o * 256 + 128 + c] = lo;
    }
}

// ---------------------------------------------------------------------------
// K1: qkv GEMM, fp16 2-term split. Epilogue now also emits the v block
// (m in [256,384)) as fp16 * (1/4096) into g_vh for the context GEMM.
// ---------------------------------------------------------------------------
__global__ __launch_bounds__(256) void k_qkv_mma()
{
    __shared__ __half sA[3][128][72];
    __shared__ __half sB[3][128][40];
    const int tid  = threadIdx.x;
    const int wid  = tid >> 5, lane = tid & 31;
    const int n0 = blockIdx.x * 128;
    const int m0 = blockIdx.y * 128;
    const int b  = blockIdx.z;
    const int warp_m = wid >> 1, warp_n = wid & 1;

    const __half* __restrict__ Ag = g_wh + (size_t)m0 * 512;
    const __half* __restrict__ Bg = g_xh + ((size_t)b * NP + n0) * 256;

    const uint32_t aBase = smem_u32(&sA[0][0][0]);
    const uint32_t bBase = smem_u32(&sB[0][0][0]);
    const uint32_t ABUF = 128 * 144;
    const uint32_t BBUF = 128 * 80;

    uint32_t aso[4]; uint32_t agi[4];
    #pragma unroll
    for (int i = 0; i < 4; i++) {
        const int slot = tid + i * 256;
        const int r = slot >> 3, ch = slot & 7;
        aso[i] = (uint32_t)r * 144 + ch * 16;
        agi[i] = (uint32_t)r * 512 + (ch < 4 ? ch * 8 : 256 + (ch - 4) * 8);
    }
    uint32_t bso[2]; uint32_t bgi[2];
    #pragma unroll
    for (int i = 0; i < 2; i++) {
        const int slot = tid + i * 256;
        const int r = slot >> 2, ch = slot & 3;
        bso[i] = (uint32_t)r * 80 + ch * 16;
        bgi[i] = (uint32_t)r * 256 + ch * 8;
    }

    const int aRowL = warp_m * 32 + (lane & 15);
    const uint32_t aCol16 = (uint32_t)(lane >> 4) * 16;
    const int bg = lane >> 3, blr = lane & 7;
    const int bRowL = warp_n * 64 + (bg >> 1) * 8 + blr;
    const uint32_t bCol16 = (uint32_t)(bg & 1) * 16;

    float d[2][8][4];
    #pragma unroll
    for (int mf = 0; mf < 2; mf++)
        #pragma unroll
        for (int nf = 0; nf < 8; nf++)
            #pragma unroll
            for (int r = 0; r < 4; r++) d[mf][nf][r] = 0.f;

    #pragma unroll
    for (int s = 0; s < 2; s++) {
        const int k0 = s * 32;
        #pragma unroll
        for (int i = 0; i < 4; i++) cp16(aBase + s * ABUF + aso[i], Ag + agi[i] + k0);
        #pragma unroll
        for (int i = 0; i < 2; i++) cp16(bBase + s * BBUF + bso[i], Bg + bgi[i] + k0);
        cp_commit();
    }

    int buf = 0;
    for (int it = 0; it < 8; it++) {
        cp_wait1();
        __syncthreads();
        if (it + 2 < 8) {
            int nb = buf + 2; if (nb >= 3) nb -= 3;
            const int k0 = (it + 2) * 32;
            #pragma unroll
            for (int i = 0; i < 4; i++) cp16(aBase + (uint32_t)nb * ABUF + aso[i], Ag + agi[i] + k0);
            #pragma unroll
            for (int i = 0; i < 2; i++) cp16(bBase + (uint32_t)nb * BBUF + bso[i], Bg + bgi[i] + k0);
        }
        cp_commit();
        const uint32_t ab = aBase + (uint32_t)buf * ABUF;
        const uint32_t bb = bBase + (uint32_t)buf * BBUF;
        #pragma unroll
        for (int ks = 0; ks < 2; ks++) {
            uint32_t rb[8][2];
            #pragma unroll
            for (int nf2 = 0; nf2 < 4; nf2++) {
                uint32_t r0, r1, r2, r3;
                const uint32_t addr = bb + (uint32_t)(bRowL + nf2 * 16) * 80 + ks * 32 + bCol16;
                ldmatrix_x4(r0, r1, r2, r3, addr);
                rb[nf2 * 2][0] = r0;     rb[nf2 * 2][1] = r1;
                rb[nf2 * 2 + 1][0] = r2; rb[nf2 * 2 + 1][1] = r3;
            }
            #pragma unroll
            for (int seg = 0; seg < 2; seg++) {
                uint32_t ra[2][4];
                #pragma unroll
                for (int mf = 0; mf < 2; mf++) {
                    const uint32_t addr = ab + (uint32_t)(aRowL + mf * 16) * 144
                                        + seg * 64 + ks * 32 + aCol16;
                    ldmatrix_x4(ra[mf][0], ra[mf][1], ra[mf][2], ra[mf][3], addr);
                }
                #pragma unroll
                for (int mf = 0; mf < 2; mf++)
                    #pragma unroll
                    for (int nf = 0; nf < 8; nf++)
                        mma_f16(d[mf][nf], ra[mf], rb[nf]);
            }
        }
        buf++; if (buf == 3) buf = 0;
    }

    const int mBase = m0 + warp_m * 32 + (lane >> 2);
    const int nBase = n0 + warp_n * 64 + (lane & 3) * 2;
    float* outb = g_qkv + (size_t)b * QKV_CH * NP;
    #pragma unroll
    for (int mf = 0; mf < 2; mf++) {
        #pragma unroll
        for (int nf = 0; nf < 8; nf++) {
            const int m = mBase + mf * 16;
            const int n = nBase + nf * 8;
            *(float2*)(outb + (size_t)m * NP + n)       = make_float2(d[mf][nf][0], d[mf][nf][1]);
            *(float2*)(outb + (size_t)(m + 8) * NP + n) = make_float2(d[mf][nf][2], d[mf][nf][3]);
        }
    }
    if (m0 == 256) {   // v block: also emit fp16 * (1/4096) for context GEMM
        const float sc = 1.f / 4096.f;
        __half* vb = g_vh + (size_t)b * HID * NP;
        #pragma unroll
        for (int mf = 0; mf < 2; mf++) {
            #pragma unroll
            for (int nf = 0; nf < 8; nf++) {
                const int vr = mBase - 256 + mf * 16;
                const int n = nBase + nf * 8;
                *(__half2*)(vb + (size_t)vr * NP + n) =
                    __floats2half2_rn(d[mf][nf][0] * sc, d[mf][nf][1] * sc);
                *(__half2*)(vb + (size_t)(vr + 8) * NP + n) =
                    __floats2half2_rn(d[mf][nf][2] * sc, d[mf][nf][3] * sc);
            }
        }
    }
}

// ---------------------------------------------------------------------------
// K2: per k-row (b, h*32+d): softmax over n=4096 computed ONCE and emitted
// as fp16 g_keh (exps kept in registers; no recompute downstream).
// ---------------------------------------------------------------------------
__global__ __launch_bounds__(256) void k_kstats()
{
    __shared__ float red[256];
    const int row = blockIdx.x;
    const int b = row >> 7, ko = row & 127;
    const float* base = g_qkv + (size_t)b * QKV_CH * NP + (size_t)(HID + ko) * NP;
    const int t = threadIdx.x;
    float vals[16];
    #pragma unroll
    for (int j = 0; j < 4; j++) {
        const float4 v = *(const float4*)(base + (j * 256 + t) * 4);
        vals[j * 4 + 0] = v.x; vals[j * 4 + 1] = v.y;
        vals[j * 4 + 2] = v.z; vals[j * 4 + 3] = v.w;
    }
    float m = vals[0];
    #pragma unroll
    for (int i = 1; i < 16; i++) m = fmaxf(m, vals[i]);
    red[t] = m; __syncthreads();
    for (int off = 128; off > 0; off >>= 1) {
        if (t < off) red[t] = fmaxf(red[t], red[t + off]);
        __syncthreads();
    }
    m = red[0];
    __syncthreads();
    float e16[16];
    float s = 0.f;
    #pragma unroll
    for (int i = 0; i < 16; i++) { e16[i] = __expf(vals[i] - m); s += e16[i]; }
    red[t] = s; __syncthreads();
    for (int off = 128; off > 0; off >>= 1) {
        if (t < off) red[t] += red[t + off];
        __syncthreads();
    }
    const float inv = 1.f / red[0];
    __half* krow = g_keh + (size_t)row * NP;
    #pragma unroll
    for (int j = 0; j < 4; j++) {
        union { __half h[4]; uint2 u; } pk;
        #pragma unroll
        for (int i = 0; i < 4; i++) pk.h[i] = __float2half(e16[j * 4 + i] * inv);
        *(uint2*)(krow + (j * 256 + t) * 4) = pk.u;
    }
}

// ---------------------------------------------------------------------------
// K3: context = kexp @ vh^T, pure fp16 HMMA. Grid (4 n-chunks of 1024, 64 z).
// 8 warps; per 128-n stage each warp owns k-step `wid` (16 n). Deterministic
// 8-way smem reduce of the 32x32 warp partials -> g_ctxp[ch].
// ---------------------------------------------------------------------------
__global__ __launch_bounds__(256) void k_context()
{
    __shared__ char cxs[34816];
    // sk [2][32][136] halfs at 0 (17408B); sv same at 17408. red f32[8][1024] reuses [0,32768).
    const uint32_t skB = smem_u32(cxs);
    const uint32_t svB = skB + 17408;
    float* red = (float*)cxs;

    const int ch = blockIdx.x;     // 0..3
    const int z  = blockIdx.y;     // b*4+h
    const int b = z >> 2, h = z & 3;
    const __half* __restrict__ kg = g_keh + ((size_t)b * HID + h * DH) * NP + ch * 1024;
    const __half* __restrict__ vg = g_vh  + ((size_t)b * HID + h * DH) * NP + ch * 1024;

    const int t = threadIdx.x;
    const int wid = t >> 5, lane = t & 31;

    // loader geometry: 1024 chunks/stage (512 k + 512 v), 4 per thread
    uint32_t lso[4]; uint32_t lgi[4]; bool lk[4];
    #pragma unroll
    for (int i = 0; i < 4; i++) {
        const int slot = t + i * 256;
        const int s = slot & 511;
        const int r = s >> 4, c = s & 15;
        lso[i] = (uint32_t)r * 272 + c * 16;
        lgi[i] = (uint32_t)r * NP + c * 8;
        lk[i] = slot < 512;
    }

    const int aRow = lane & 15;
    const uint32_t aCol16 = (uint32_t)(lane >> 4) * 16;
    const int bg = lane >> 3, blr = lane & 7;
    const int bRow = (bg >> 1) * 8 + blr;
    const uint32_t bCol16 = (uint32_t)(bg & 1) * 16;
    const uint32_t kbyte = (uint32_t)wid * 32;   // this warp's k-step offset (16 halfs)

    float d[2][4][4];
    #pragma unroll
    for (int mf = 0; mf < 2; mf++)
        #pragma unroll
        for (int nf = 0; nf < 4; nf++)
            #pragma unroll
            for (int r = 0; r < 4; r++) d[mf][nf][r] = 0.f;

    // prologue: stage 0 -> buf 0
    #pragma unroll
    for (int i = 0; i < 4; i++)
        cp16((lk[i] ? skB : svB) + lso[i], (lk[i] ? kg : vg) + lgi[i]);
    cp_commit();

    int buf = 0;
    for (int it = 0; it < 8; it++) {
        __syncthreads();            // buf^1 free to overwrite
        if (it + 1 < 8) {
            const uint32_t boff = (uint32_t)(buf ^ 1) * 8704;
            const int n0 = (it + 1) * 128;
            #pragma unroll
            for (int i = 0; i < 4; i++)
                cp16((lk[i] ? skB : svB) + boff + lso[i], (lk[i] ? kg : vg) + lgi[i] + n0);
        }
        cp_commit();
        cp_wait1();
        __syncthreads();
        const uint32_t boff = (uint32_t)buf * 8704;
        uint32_t ra[2][4];
        #pragma unroll
        for (int mf = 0; mf < 2; mf++) {
            const uint32_t addr = skB + boff + (uint32_t)(aRow + mf * 16) * 272 + kbyte + aCol16;
            ldmatrix_x4(ra[mf][0], ra[mf][1], ra[mf][2], ra[mf][3], addr);
        }
        uint32_t rb[4][2];
        #pragma unroll
        for (int nf2 = 0; nf2 < 2; nf2++) {
            uint32_t r0, r1, r2, r3;
            const uint32_t addr = svB + boff + (uint32_t)(bRow + nf2 * 16) * 272 + kbyte + bCol16;
            ldmatrix_x4(r0, r1, r2, r3, addr);
            rb[nf2 * 2][0] = r0;     rb[nf2 * 2][1] = r1;
            rb[nf2 * 2 + 1][0] = r2; rb[nf2 * 2 + 1][1] = r3;
        }
        #pragma unroll
        for (int mf = 0; mf < 2; mf++)
            #pragma unroll
            for (int nf = 0; nf < 4; nf++)
                mma_f16(d[mf][nf], ra[mf], rb[nf]);
        buf ^= 1;
    }
    __syncthreads();    // all smem reads done -> reuse as red

    #pragma unroll
    for (int mf = 0; mf < 2; mf++) {
        #pragma unroll
        for (int nf = 0; nf < 4; nf++) {
            const int m = mf * 16 + (lane >> 2);
            const int n = nf * 8 + (lane & 3) * 2;
            red[wid * 1024 + m * 32 + n]           = d[mf][nf][0];
            red[wid * 1024 + m * 32 + n + 1]       = d[mf][nf][1];
            red[wid * 1024 + (m + 8) * 32 + n]     = d[mf][nf][2];
            red[wid * 1024 + (m + 8) * 32 + n + 1] = d[mf][nf][3];
        }
    }
    __syncthreads();
    float* o = g_ctxp + ((size_t)ch * 64 + z) * 1024;
    #pragma unroll
    for (int i = 0; i < 4; i++) {
        const int idx = t * 4 + i;
        float s = 0.f;
        #pragma unroll
        for (int w = 0; w < 8; w++) s += red[w * 1024 + idx];
        o[idx] = s;
    }
}

__global__ void k_ctx_reduce()
{
    const int i = blockIdx.x * 256 + threadIdx.x;
    float s = 0.f;
    #pragma unroll
    for (int ch = 0; ch < 4; ch++) s += g_ctxp[(size_t)ch * 65536 + i];
    g_ctx[i] = s;
}

// ---------------------------------------------------------------------------
// K4: FUSED attn + out-conv + LayerNorm (unchanged from R11).
// ---------------------------------------------------------------------------
__global__ __launch_bounds__(256, 2) void k_attn_out(
    const float* __restrict__ b_out, const float* __restrict__ g, float* __restrict__ out)
{
    __shared__ alignas(128) char smem_raw[83456];
    const uint32_t aBase = smem_u32(smem_raw);
    const uint32_t bBase = aBase + 61440;
    float* sq   = (float*)smem_raw;                 // [128][68]
    float* sctx = (float*)(smem_raw + 34816);       // [4][32][36]
    __half* sbh = (__half*)(smem_raw + 61440);      // [64][136]
    float* ys   = (float*)smem_raw;                 // [256][66]
    float* redS = (float*)(smem_raw + 78848);
    float* redQ = (float*)(smem_raw + 80896);
    float* smu  = (float*)(smem_raw + 82944);
    float* srs  = (float*)(smem_raw + 83200);

    const int t  = threadIdx.x;
    const int p0 = blockIdx.x * 64;
    const int b  = blockIdx.y;

    {
        const float* qb = g_qkv + (size_t)b * QKV_CH * NP;
        const int row = t >> 1, hf = (t & 1) * 32;
        #pragma unroll
        for (int j = 0; j < 8; j++) {
            const float4 v = *(const float4*)(qb + (size_t)row * NP + p0 + hf + j * 4);
            const int c = hf + j * 4;
            sq[row * 68 + c] = v.x; sq[row * 68 + c + 1] = v.y;
            sq[row * 68 + c + 2] = v.z; sq[row * 68 + c + 3] = v.w;
        }
        const float* cb = g_ctx + (size_t)b * NH * 1024;
        #pragma unroll
        for (int i = 0; i < 16; i++) {
            const int idx = t + i * 256;
            sctx[(idx >> 10) * 1152 + ((idx >> 5) & 31) * 36 + (idx & 31)] = cb[idx];
        }
    }
    __syncthreads();

    const int h1 = t >> 6, p1 = t & 63;
    {
        float m = -3.402823e38f;
        #pragma unroll
        for (int d = 0; d < 32; d++) m = fmaxf(m, sq[(h1 * 32 + d) * 68 + p1]);
        float s = 0.f;
        #pragma unroll
        for (int d = 0; d < 32; d++) s += __expf(sq[(h1 * 32 + d) * 68 + p1] - m);
        const float inv = 0.17677669529663687f / s;
        #pragma unroll
        for (int d = 0; d < 32; d++)
            sq[(h1 * 32 + d) * 68 + p1] = __expf(sq[(h1 * 32 + d) * 68 + p1] - m) * inv;
    }
    __syncthreads();

    float acc[32];
    #pragma unroll
    for (int i = 0; i < 32; i++) acc[i] = 0.f;
    #pragma unroll
    for (int d = 0; d < 32; d++) {
        const float qv = sq[(h1 * 32 + d) * 68 + p1];
        const float* cr = sctx + h1 * 1152 + d * 36;
        #pragma unroll
        for (int e4 = 0; e4 < 8; e4++) {
            const float4 cv = *(const float4*)(cr + e4 * 4);
            acc[e4 * 4 + 0] += cv.x * qv;
            acc[e4 * 4 + 1] += cv.y * qv;
            acc[e4 * 4 + 2] += cv.z * qv;
            acc[e4 * 4 + 3] += cv.w * qv;
        }
    }
    __syncthreads();

    const uint32_t ABUF = 20480;
    const int a_r = t >> 2, a_ch = t & 3;
    #pragma unroll
    for (int s = 0; s < 2; s++) {
        const int k0 = s * 32;
        #pragma unroll
        for (int i = 0; i < 4; i++) {
            const int row = a_r + i * 64;
            cp16(aBase + (uint32_t)s * ABUF + (uint32_t)row * 80 + a_ch * 16,
                 g_woh + (size_t)row * 256 + k0 + a_ch * 8);
        }
        cp_commit();
    }
    {
        union { __half h[32]; uint4 u[4]; } hb;
        #pragma unroll
        for (int i = 0; i < 32; i++) hb.h[i] = __float2half(acc[i]);
        uint4* dst = (uint4*)(sbh + p1 * 136 + h1 * 32);
        dst[0] = hb.u[0]; dst[1] = hb.u[1]; dst[2] = hb.u[2]; dst[3] = hb.u[3];
    }

    const int wid = t >> 5, lane = t & 31;
    const int warp_m = wid >> 1, warp_n = wid & 1;
    const int aRowL = warp_m * 64 + (lane & 15);
    const uint32_t aCol16 = (uint32_t)(lane >> 4) * 16;
    const int bg = lane >> 3, blr = lane & 7;
    const int bRowL = warp_n * 32 + (bg >> 1) * 8 + blr;
    const uint32_t bCol16 = (uint32_t)(bg & 1) * 16;

    float d[4][4][4];
    #pragma unroll
    for (int mf = 0; mf < 4; mf++)
        #pragma unroll
        for (int nf = 0; nf < 4; nf++)
            #pragma unroll
            for (int r = 0; r < 4; r++) d[mf][nf][r] = 0.f;

    int buf = 0;
    for (int it = 0; it < 8; it++) {
        cp_wait1();
        __syncthreads();
        if (it + 2 < 8) {
            int nb = buf + 2; if (nb >= 3) nb -= 3;
            const int k0 = (it + 2) * 32;
            #pragma unroll
            for (int i = 0; i < 4; i++) {
                const int row = a_r + i * 64;
                cp16(aBase + (uint32_t)nb * ABUF + (uint32_t)row * 80 + a_ch * 16,
                     g_woh + (size_t)row * 256 + k0 + a_ch * 8);
            }
        }
        cp_commit();
        const uint32_t ab = aBase + (uint32_t)buf * ABUF;
        #pragma unroll
        for (int ks = 0; ks < 2; ks++) {
            const int kslot = (it * 2 + ks) & 7;
            uint32_t rb[4][2];
            #pragma unroll
            for (int nf2 = 0; nf2 < 2; nf2++) {
                uint32_t r0, r1, r2, r3;
                const uint32_t addr = bBase + (uint32_t)(bRowL + nf2 * 16) * 272
                                    + kslot * 32 + bCol16;
                ldmatrix_x4(r0, r1, r2, r3, addr);
                rb[nf2 * 2][0] = r0;     rb[nf2 * 2][1] = r1;
                rb[nf2 * 2 + 1][0] = r2; rb[nf2 * 2 + 1][1] = r3;
            }
            uint32_t ra[4][4];
            #pragma unroll
            for (int mf = 0; mf < 4; mf++) {
                const uint32_t addr = ab + (uint32_t)(aRowL + mf * 16) * 80 + ks * 32 + aCol16;
                ldmatrix_x4(ra[mf][0], ra[mf][1], ra[mf][2], ra[mf][3], addr);
            }
            #pragma unroll
            for (int mf = 0; mf < 4; mf++)
                #pragma unroll
                for (int nf = 0; nf < 4; nf++)
                    mma_f16(d[mf][nf], ra[mf], rb[nf]);
        }
        buf++; if (buf == 3) buf = 0;
    }
    __syncthreads();

    const int mB = warp_m * 64 + (lane >> 2);
    const int nB = warp_n * 32 + (lane & 3) * 2;
    #pragma unroll
    for (int mf = 0; mf < 4; mf++) {
        #pragma unroll
        for (int nf = 0; nf < 4; nf++) {
            const int m = mB + mf * 16;
            const int n = nB + nf * 8;
            const float bo0 = b_out[m], bo1 = b_out[m + 8];
            ys[m * 66 + n]           = d[mf][nf][0] + bo0;
            ys[m * 66 + n + 1]       = d[mf][nf][1] + bo0;
            ys[(m + 8) * 66 + n]     = d[mf][nf][2] + bo1;
            ys[(m + 8) * 66 + n + 1] = d[mf][nf][3] + bo1;
        }
    }
    __syncthreads();
    {
        float s0 = 0.f, q0 = 0.f, s1 = 0.f, q1 = 0.f;
        #pragma unroll
        for (int c = 0; c < 32; c++) {
            const float v0 = ys[(wid * 32 + c) * 66 + lane];
            const float v1 = ys[(wid * 32 + c) * 66 + lane + 32];
            s0 += v0; q0 += v0 * v0;
            s1 += v1; q1 += v1 * v1;
        }
        redS[wid * 64 + lane] = s0;      redQ[wid * 64 + lane] = q0;
        redS[wid * 64 + lane + 32] = s1; redQ[wid * 64 + lane + 32] = q1;
    }
    __syncthreads();
    if (t < 64) {
        float s = 0.f, q = 0.f;
        #pragma unroll
        for (int w = 0; w < 8; w++) { s += redS[w * 64 + t]; q += redQ[w * 64 + t]; }
        const float mu  = s * (1.f / 256.f);
        const float var = q * (1.f / 256.f) - mu * mu;
        smu[t] = mu;
        srs[t] = rsqrtf(var + 1e-5f);
    }
    __syncthreads();
    {
        const int n2 = t & 63;
        const float mu = smu[n2], rs = srs[n2];
        float* ob = out + (size_t)b * C_ * NP + p0 + n2;
        for (int o = t >> 6; o < C_; o += 4) {
            ob[(size_t)o * NP] = (ys[o * 66 + n2] - mu) * rs * g[o];
        }
    }
}

// ---------------------------------------------------------------------------
extern "C" void kernel_launch(void* const* d_in, const int* in_sizes, int n_in,
                              void* d_out, int out_size)
{
    const float* x     = (const float*)d_in[0];
    const float* w_qkv = (const float*)d_in[1];
    const float* w_out = (const float*)d_in[2];
    const float* b_out = (const float*)d_in[3];
    const float* g     = (const float*)d_in[4];
    float* out = (float*)d_out;
    (void)in_sizes; (void)n_in; (void)out_size;

    k_conv_all<<<16896, 256>>>(x, w_qkv, w_out);
    k_qkv_mma<<<dim3(32, 3, 16), 256>>>();
    k_kstats<<<2048, 256>>>();
    k_context<<<dim3(4, 64), 256>>>();
    k_ctx_reduce<<<256, 256>>>();
    k_attn_out<<<dim3(64, 16), 256>>>(b_out, g, out);
}

// round 13
// speedup vs baseline: 3.0623x; 1.0807x over previous
#include <cuda_runtime.h>
#include <cuda_fp16.h>
#include <cstdint>
#include <cstddef>

// Problem constants
#define B_     16
#define C_     256
#define HID    128
#define NH     4
#define DH     32
#define NP     4096       // 64*64 spatial positions
#define QKV_CH 384

// Scratch (device globals: allocation-free rule)
__device__ float  g_qkv[(size_t)B_ * HID * NP];      // q only, fp32 (33MB)
__device__ float  g_ctxp[4 * 64 * 1024];
__device__ __half g_wh [(size_t)QKV_CH * 512];       // w_qkv fp16 split: [hi(256)|lo(256)]
__device__ __half g_xh [(size_t)B_ * NP * 256];      // x^T fp16 hi (33MB)
__device__ __half g_woh[(size_t)C_ * 256];           // w_out fp16 split: [hi(128)|lo(128)]
__device__ __half g_kh [(size_t)B_ * HID * NP];      // k fp16 (17MB)
__device__ __half g_keh[(size_t)B_ * HID * NP];      // softmax_n(k) fp16 (17MB)
__device__ __half g_vh [(size_t)B_ * HID * NP];      // v/4096 fp16 (17MB)

// ---------------------------------------------------------------------------
// Portable PTX helpers (sm_80+ only — harness lowers via compute_103 (non-'a'))
// ---------------------------------------------------------------------------
__device__ __forceinline__ uint32_t smem_u32(const void* p) {
    uint32_t a;
    asm("{ .reg .u64 t; cvta.to.shared.u64 t, %1; cvt.u32.u64 %0, t; }" : "=r"(a) : "l"(p));
    return a;
}
__device__ __forceinline__ void cp16(uint32_t s, const void* g) {
    asm volatile("cp.async.cg.shared.global [%0], [%1], 16;" :: "r"(s), "l"(g));
}
__device__ __forceinline__ void cp_commit() {
    asm volatile("cp.async.commit_group;" ::: "memory");
}
__device__ __forceinline__ void cp_wait1() {
    asm volatile("cp.async.wait_group 1;" ::: "memory");
}
__device__ __forceinline__ void ldmatrix_x4(uint32_t& r0, uint32_t& r1,
                                            uint32_t& r2, uint32_t& r3, uint32_t addr) {
    asm volatile("ldmatrix.sync.aligned.m8n8.x4.shared.b16 {%0,%1,%2,%3}, [%4];"
                 : "=r"(r0), "=r"(r1), "=r"(r2), "=r"(r3) : "r"(addr));
}
__device__ __forceinline__ void mma_f16(float* d, const uint32_t* a, const uint32_t* b) {
    asm volatile(
        "mma.sync.aligned.m16n8k16.row.col.f32.f16.f16.f32 "
        "{%0,%1,%2,%3}, {%4,%5,%6,%7}, {%8,%9}, {%0,%1,%2,%3};"
        : "+f"(d[0]), "+f"(d[1]), "+f"(d[2]), "+f"(d[3])
        : "r"(a[0]), "r"(a[1]), "r"(a[2]), "r"(a[3]), "r"(b[0]), "r"(b[1]));
}

// ---------------------------------------------------------------------------
// K0: ALL input conversions in one launch.
// ---------------------------------------------------------------------------
__global__ __launch_bounds__(256) void k_conv_all(
    const float* __restrict__ x, const float* __restrict__ wq, const float* __restrict__ wo)
{
    __shared__ float tile[32][33];
    const int bid = blockIdx.x;
    if (bid < 16384) {
        const int b  = bid >> 10;
        const int c0 = ((bid >> 7) & 7) * 32;
        const int p0 = (bid & 127) * 32;
        const int tp = threadIdx.x & 31, tc = threadIdx.x >> 5;
        #pragma unroll
        for (int j = 0; j < 4; j++) {
            const int c = tc + j * 8;
            tile[c][tp] = x[((size_t)b * C_ + c0 + c) * NP + p0 + tp];
        }
        __syncthreads();
        if (threadIdx.x < 128) {
            const int p = threadIdx.x >> 2, ch = threadIdx.x & 3;
            union { __half h[8]; uint4 u; } vb;
            #pragma unroll
            for (int j = 0; j < 8; j++) vb.h[j] = __float2half(tile[ch * 8 + j][p]);
            *(uint4*)(g_xh + ((size_t)b * NP + p0 + p) * 256 + c0 + ch * 8) = vb.u;
        }
    } else if (bid < 16768) {
        const int i = (bid - 16384) * 256 + threadIdx.x;
        const float v = wq[i];
        const int o = i >> 8, c = i & 255;
        const __half hi = __float2half(v);
        const __half lo = __float2half(v - __half2float(hi));
        g_wh[(size_t)o * 512 + c]       = hi;
        g_wh[(size_t)o * 512 + 256 + c] = lo;
    } else {
        const int i = (bid - 16768) * 256 + threadIdx.x;
        const float v = wo[i];
        const int o = i >> 7, c = i & 127;
        const __half hi = __float2half(v);
        const __half lo = __float2half(v - __half2float(hi));
        g_woh[(size_t)o * 256 + c]       = hi;
        g_woh[(size_t)o * 256 + 128 + c] = lo;
    }
}

// ---------------------------------------------------------------------------
// K1: qkv GEMM. blockIdx.y == 0: q block (M=128, 2-term split K'=512,
// fp32 out -> g_qkv). blockIdx.y in {1,2}: k/v blocks (M=128 each,
// SINGLE-term fp16 K=256, fp16 out -> g_kh / g_vh). k/v GEMM error is
// benign: it averages over n=4096 in the context stage (measured R12).
// ---------------------------------------------------------------------------
__global__ __launch_bounds__(256) void k_qkv_mma()
{
    __shared__ __half sA[3][128][72];   // q path: [hi|lo] 144B rows; kv path uses 80B rows
    __shared__ __half sB[3][128][40];
    const int tid  = threadIdx.x;
    const int wid  = tid >> 5, lane = tid & 31;
    const int n0 = blockIdx.x * 128;
    const int b  = blockIdx.z;
    const int warp_m = wid >> 1, warp_n = wid & 1;

    const uint32_t aBase = smem_u32(&sA[0][0][0]);
    const uint32_t bBase = smem_u32(&sB[0][0][0]);
    const uint32_t BBUF = 128 * 80;

    const __half* __restrict__ Bg = g_xh + ((size_t)b * NP + n0) * 256;
    uint32_t bso[2]; uint32_t bgi[2];
    #pragma unroll
    for (int i = 0; i < 2; i++) {
        const int slot = tid + i * 256;
        const int r = slot >> 2, ch = slot & 3;
        bso[i] = (uint32_t)r * 80 + ch * 16;
        bgi[i] = (uint32_t)r * 256 + ch * 8;
    }
    const int aRowL = warp_m * 32 + (lane & 15);
    const uint32_t aCol16 = (uint32_t)(lane >> 4) * 16;
    const int bg = lane >> 3, blr = lane & 7;
    const int bRowL = warp_n * 64 + (bg >> 1) * 8 + blr;
    const uint32_t bCol16 = (uint32_t)(bg & 1) * 16;

    float d[2][8][4];
    #pragma unroll
    for (int mf = 0; mf < 2; mf++)
        #pragma unroll
        for (int nf = 0; nf < 8; nf++)
            #pragma unroll
            for (int r = 0; r < 4; r++) d[mf][nf][r] = 0.f;

    if (blockIdx.y == 0) {
        // ---------------- q path: 2-term split ----------------
        const uint32_t ABUF = 128 * 144;
        const __half* __restrict__ Ag = g_wh;   // rows 0..127
        uint32_t aso[4]; uint32_t agi[4];
        #pragma unroll
        for (int i = 0; i < 4; i++) {
            const int slot = tid + i * 256;
            const int r = slot >> 3, ch = slot & 7;
            aso[i] = (uint32_t)r * 144 + ch * 16;
            agi[i] = (uint32_t)r * 512 + (ch < 4 ? ch * 8 : 256 + (ch - 4) * 8);
        }
        #pragma unroll
        for (int s = 0; s < 2; s++) {
            const int k0 = s * 32;
            #pragma unroll
            for (int i = 0; i < 4; i++) cp16(aBase + s * ABUF + aso[i], Ag + agi[i] + k0);
            #pragma unroll
            for (int i = 0; i < 2; i++) cp16(bBase + s * BBUF + bso[i], Bg + bgi[i] + k0);
            cp_commit();
        }
        int buf = 0;
        for (int it = 0; it < 8; it++) {
            cp_wait1();
            __syncthreads();
            if (it + 2 < 8) {
                int nb = buf + 2; if (nb >= 3) nb -= 3;
                const int k0 = (it + 2) * 32;
                #pragma unroll
                for (int i = 0; i < 4; i++) cp16(aBase + (uint32_t)nb * ABUF + aso[i], Ag + agi[i] + k0);
                #pragma unroll
                for (int i = 0; i < 2; i++) cp16(bBase + (uint32_t)nb * BBUF + bso[i], Bg + bgi[i] + k0);
            }
            cp_commit();
            const uint32_t ab = aBase + (uint32_t)buf * ABUF;
            const uint32_t bb = bBase + (uint32_t)buf * BBUF;
            #pragma unroll
            for (int ks = 0; ks < 2; ks++) {
                uint32_t rb[8][2];
                #pragma unroll
                for (int nf2 = 0; nf2 < 4; nf2++) {
                    uint32_t r0, r1, r2, r3;
                    const uint32_t addr = bb + (uint32_t)(bRowL + nf2 * 16) * 80 + ks * 32 + bCol16;
                    ldmatrix_x4(r0, r1, r2, r3, addr);
                    rb[nf2 * 2][0] = r0;     rb[nf2 * 2][1] = r1;
                    rb[nf2 * 2 + 1][0] = r2; rb[nf2 * 2 + 1][1] = r3;
                }
                #pragma unroll
                for (int seg = 0; seg < 2; seg++) {
                    uint32_t ra[2][4];
                    #pragma unroll
                    for (int mf = 0; mf < 2; mf++) {
                        const uint32_t addr = ab + (uint32_t)(aRowL + mf * 16) * 144
                                            + seg * 64 + ks * 32 + aCol16;
                        ldmatrix_x4(ra[mf][0], ra[mf][1], ra[mf][2], ra[mf][3], addr);
                    }
                    #pragma unroll
                    for (int mf = 0; mf < 2; mf++)
                        #pragma unroll
                        for (int nf = 0; nf < 8; nf++)
                            mma_f16(d[mf][nf], ra[mf], rb[nf]);
                }
            }
            buf++; if (buf == 3) buf = 0;
        }
        const int mBase = warp_m * 32 + (lane >> 2);
        const int nBase = n0 + warp_n * 64 + (lane & 3) * 2;
        float* outb = g_qkv + (size_t)b * HID * NP;
        #pragma unroll
        for (int mf = 0; mf < 2; mf++) {
            #pragma unroll
            for (int nf = 0; nf < 8; nf++) {
                const int m = mBase + mf * 16;
                const int n = nBase + nf * 8;
                *(float2*)(outb + (size_t)m * NP + n)       = make_float2(d[mf][nf][0], d[mf][nf][1]);
                *(float2*)(outb + (size_t)(m + 8) * NP + n) = make_float2(d[mf][nf][2], d[mf][nf][3]);
            }
        }
    } else {
        // ---------------- k/v path: single-term fp16 ----------------
        const int mb = blockIdx.y - 1;           // 0 = k, 1 = v
        const uint32_t ABUF = 128 * 80;
        const __half* __restrict__ Ag = g_wh + (size_t)(HID + mb * HID) * 512;
        uint32_t aso[2]; uint32_t agi[2];
        #pragma unroll
        for (int i = 0; i < 2; i++) {
            const int slot = tid + i * 256;
            const int r = slot >> 2, ch = slot & 3;
            aso[i] = (uint32_t)r * 80 + ch * 16;
            agi[i] = (uint32_t)r * 512 + ch * 8;   // hi segment only
        }
        #pragma unroll
        for (int s = 0; s < 2; s++) {
            const int k0 = s * 32;
            #pragma unroll
            for (int i = 0; i < 2; i++) cp16(aBase + s * ABUF + aso[i], Ag + agi[i] + k0);
            #pragma unroll
            for (int i = 0; i < 2; i++) cp16(bBase + s * BBUF + bso[i], Bg + bgi[i] + k0);
            cp_commit();
        }
        int buf = 0;
        for (int it = 0; it < 8; it++) {
            cp_wait1();
            __syncthreads();
            if (it + 2 < 8) {
                int nb = buf + 2; if (nb >= 3) nb -= 3;
                const int k0 = (it + 2) * 32;
                #pragma unroll
                for (int i = 0; i < 2; i++) cp16(aBase + (uint32_t)nb * ABUF + aso[i], Ag + agi[i] + k0);
                #pragma unroll
                for (int i = 0; i < 2; i++) cp16(bBase + (uint32_t)nb * BBUF + bso[i], Bg + bgi[i] + k0);
            }
            cp_commit();
            const uint32_t ab = aBase + (uint32_t)buf * ABUF;
            const uint32_t bb = bBase + (uint32_t)buf * BBUF;
            #pragma unroll
            for (int ks = 0; ks < 2; ks++) {
                uint32_t rb[8][2];
                #pragma unroll
                for (int nf2 = 0; nf2 < 4; nf2++) {
                    uint32_t r0, r1, r2, r3;
                    const uint32_t addr = bb + (uint32_t)(bRowL + nf2 * 16) * 80 + ks * 32 + bCol16;
                    ldmatrix_x4(r0, r1, r2, r3, addr);
                    rb[nf2 * 2][0] = r0;     rb[nf2 * 2][1] = r1;
                    rb[nf2 * 2 + 1][0] = r2; rb[nf2 * 2 + 1][1] = r3;
                }
                uint32_t ra[2][4];
                #pragma unroll
                for (int mf = 0; mf < 2; mf++) {
                    const uint32_t addr = ab + (uint32_t)(aRowL + mf * 16) * 80 + ks * 32 + aCol16;
                    ldmatrix_x4(ra[mf][0], ra[mf][1], ra[mf][2], ra[mf][3], addr);
                }
                #pragma unroll
                for (int mf = 0; mf < 2; mf++)
                    #pragma unroll
                    for (int nf = 0; nf < 8; nf++)
                        mma_f16(d[mf][nf], ra[mf], rb[nf]);
            }
            buf++; if (buf == 3) buf = 0;
        }
        const int mBase = warp_m * 32 + (lane >> 2);
        const int nBase = n0 + warp_n * 64 + (lane & 3) * 2;
        const float sc = mb ? (1.f / 4096.f) : 1.f;
        __half* outb = (mb ? g_vh : g_kh) + (size_t)b * HID * NP;
        #pragma unroll
        for (int mf = 0; mf < 2; mf++) {
            #pragma unroll
            for (int nf = 0; nf < 8; nf++) {
                const int m = mBase + mf * 16;
                const int n = nBase + nf * 8;
                *(__half2*)(outb + (size_t)m * NP + n) =
                    __floats2half2_rn(d[mf][nf][0] * sc, d[mf][nf][1] * sc);
                *(__half2*)(outb + (size_t)(m + 8) * NP + n) =
                    __floats2half2_rn(d[mf][nf][2] * sc, d[mf][nf][3] * sc);
            }
        }
    }
}

// ---------------------------------------------------------------------------
// K2: per k-row softmax over n=4096 from fp16 g_kh -> fp16 g_keh.
// ---------------------------------------------------------------------------
__global__ __launch_bounds__(256) void k_kstats()
{
    __shared__ float red[256];
    const int row = blockIdx.x;                  // b*128 + d-channel
    const __half* base = g_kh + (size_t)row * NP;
    const int t = threadIdx.x;
    float vals[16];
    #pragma unroll
    for (int j = 0; j < 2; j++) {
        const uint4 raw = *(const uint4*)(base + (j * 256 + t) * 8);
        const __half2* hp = (const __half2*)&raw;
        #pragma unroll
        for (int w = 0; w < 4; w++) {
            const float2 f = __half22float2(hp[w]);
            vals[j * 8 + w * 2]     = f.x;
            vals[j * 8 + w * 2 + 1] = f.y;
        }
    }
    float m = vals[0];
    #pragma unroll
    for (int i = 1; i < 16; i++) m = fmaxf(m, vals[i]);
    red[t] = m; __syncthreads();
    for (int off = 128; off > 0; off >>= 1) {
        if (t < off) red[t] = fmaxf(red[t], red[t + off]);
        __syncthreads();
    }
    m = red[0];
    __syncthreads();
    float e16[16];
    float s = 0.f;
    #pragma unroll
    for (int i = 0; i < 16; i++) { e16[i] = __expf(vals[i] - m); s += e16[i]; }
    red[t] = s; __syncthreads();
    for (int off = 128; off > 0; off >>= 1) {
        if (t < off) red[t] += red[t + off];
        __syncthreads();
    }
    const float inv = 1.f / red[0];
    __half* krow = g_keh + (size_t)row * NP;
    #pragma unroll
    for (int j = 0; j < 2; j++) {
        union { __half h[8]; uint4 u; } pk;
        #pragma unroll
        for (int i = 0; i < 8; i++) pk.h[i] = __float2half(e16[j * 8 + i] * inv);
        *(uint4*)(krow + (j * 256 + t) * 8) = pk.u;
    }
}

// ---------------------------------------------------------------------------
// K3: context = kexp @ vh^T, pure fp16 HMMA (unchanged from R12).
// ---------------------------------------------------------------------------
__global__ __launch_bounds__(256) void k_context()
{
    __shared__ char cxs[34816];
    const uint32_t skB = smem_u32(cxs);
    const uint32_t svB = skB + 17408;
    float* red = (float*)cxs;

    const int ch = blockIdx.x;     // 0..3
    const int z  = blockIdx.y;     // b*4+h
    const int b = z >> 2, h = z & 3;
    const __half* __restrict__ kg = g_keh + ((size_t)b * HID + h * DH) * NP + ch * 1024;
    const __half* __restrict__ vg = g_vh  + ((size_t)b * HID + h * DH) * NP + ch * 1024;

    const int t = threadIdx.x;
    const int wid = t >> 5, lane = t & 31;

    uint32_t lso[4]; uint32_t lgi[4]; bool lk[4];
    #pragma unroll
    for (int i = 0; i < 4; i++) {
        const int slot = t + i * 256;
        const int s = slot & 511;
        const int r = s >> 4, c = s & 15;
        lso[i] = (uint32_t)r * 272 + c * 16;
        lgi[i] = (uint32_t)r * NP + c * 8;
        lk[i] = slot < 512;
    }

    const int aRow = lane & 15;
    const uint32_t aCol16 = (uint32_t)(lane >> 4) * 16;
    const int bg = lane >> 3, blr = lane & 7;
    const int bRow = (bg >> 1) * 8 + blr;
    const uint32_t bCol16 = (uint32_t)(bg & 1) * 16;
    const uint32_t kbyte = (uint32_t)wid * 32;

    float d[2][4][4];
    #pragma unroll
    for (int mf = 0; mf < 2; mf++)
        #pragma unroll
        for (int nf = 0; nf < 4; nf++)
            #pragma unroll
            for (int r = 0; r < 4; r++) d[mf][nf][r] = 0.f;

    #pragma unroll
    for (int i = 0; i < 4; i++)
        cp16((lk[i] ? skB : svB) + lso[i], (lk[i] ? kg : vg) + lgi[i]);
    cp_commit();

    int buf = 0;
    for (int it = 0; it < 8; it++) {
        __syncthreads();
        if (it + 1 < 8) {
            const uint32_t boff = (uint32_t)(buf ^ 1) * 8704;
            const int n0 = (it + 1) * 128;
            #pragma unroll
            for (int i = 0; i < 4; i++)
                cp16((lk[i] ? skB : svB) + boff + lso[i], (lk[i] ? kg : vg) + lgi[i] + n0);
        }
        cp_commit();
        cp_wait1();
        __syncthreads();
        const uint32_t boff = (uint32_t)buf * 8704;
        uint32_t ra[2][4];
        #pragma unroll
        for (int mf = 0; mf < 2; mf++) {
            const uint32_t addr = skB + boff + (uint32_t)(aRow + mf * 16) * 272 + kbyte + aCol16;
            ldmatrix_x4(ra[mf][0], ra[mf][1], ra[mf][2], ra[mf][3], addr);
        }
        uint32_t rb[4][2];
        #pragma unroll
        for (int nf2 = 0; nf2 < 2; nf2++) {
            uint32_t r0, r1, r2, r3;
            const uint32_t addr = svB + boff + (uint32_t)(bRow + nf2 * 16) * 272 + kbyte + bCol16;
            ldmatrix_x4(r0, r1, r2, r3, addr);
            rb[nf2 * 2][0] = r0;     rb[nf2 * 2][1] = r1;
            rb[nf2 * 2 + 1][0] = r2; rb[nf2 * 2 + 1][1] = r3;
        }
        #pragma unroll
        for (int mf = 0; mf < 2; mf++)
            #pragma unroll
            for (int nf = 0; nf < 4; nf++)
                mma_f16(d[mf][nf], ra[mf], rb[nf]);
        buf ^= 1;
    }
    __syncthreads();

    #pragma unroll
    for (int mf = 0; mf < 2; mf++) {
        #pragma unroll
        for (int nf = 0; nf < 4; nf++) {
            const int m = mf * 16 + (lane >> 2);
            const int n = nf * 8 + (lane & 3) * 2;
            red[wid * 1024 + m * 32 + n]           = d[mf][nf][0];
            red[wid * 1024 + m * 32 + n + 1]       = d[mf][nf][1];
            red[wid * 1024 + (m + 8) * 32 + n]     = d[mf][nf][2];
            red[wid * 1024 + (m + 8) * 32 + n + 1] = d[mf][nf][3];
        }
    }
    __syncthreads();
    float* o = g_ctxp + ((size_t)ch * 64 + z) * 1024;
    #pragma unroll
    for (int i = 0; i < 4; i++) {
        const int idx = t * 4 + i;
        float s = 0.f;
        #pragma unroll
        for (int w = 0; w < 8; w++) s += red[w * 1024 + idx];
        o[idx] = s;
    }
}

// ---------------------------------------------------------------------------
// K4: FUSED attn + out-conv + LayerNorm. ctx chunk-reduce inlined into the
// sctx load (g_ctxp is L2-resident) — k_ctx_reduce launch eliminated.
// ---------------------------------------------------------------------------
__global__ __launch_bounds__(256, 2) void k_attn_out(
    const float* __restrict__ b_out, const float* __restrict__ g, float* __restrict__ out)
{
    __shared__ alignas(128) char smem_raw[83456];
    const uint32_t aBase = smem_u32(smem_raw);
    const uint32_t bBase = aBase + 61440;
    float* sq   = (float*)smem_raw;                 // [128][68]
    float* sctx = (float*)(smem_raw + 34816);       // [4][32][36]
    __half* sbh = (__half*)(smem_raw + 61440);      // [64][136]
    float* ys   = (float*)smem_raw;                 // [256][66]
    float* redS = (float*)(smem_raw + 78848);
    float* redQ = (float*)(smem_raw + 80896);
    float* smu  = (float*)(smem_raw + 82944);
    float* srs  = (float*)(smem_raw + 83200);

    const int t  = threadIdx.x;
    const int p0 = blockIdx.x * 64;
    const int b  = blockIdx.y;

    {
        const float* qb = g_qkv + (size_t)b * HID * NP;
        const int row = t >> 1, hf = (t & 1) * 32;
        #pragma unroll
        for (int j = 0; j < 8; j++) {
            const float4 v = *(const float4*)(qb + (size_t)row * NP + p0 + hf + j * 4);
            const int c = hf + j * 4;
            sq[row * 68 + c] = v.x; sq[row * 68 + c + 1] = v.y;
            sq[row * 68 + c + 2] = v.z; sq[row * 68 + c + 3] = v.w;
        }
        #pragma unroll
        for (int i = 0; i < 16; i++) {
            const int idx = t + i * 256;
            const int h = idx >> 10, ii = idx & 1023;
            const size_t base = (size_t)(b * 4 + h) * 1024 + ii;
            float s = g_ctxp[base] + g_ctxp[65536 + base]
                    + g_ctxp[131072 + base] + g_ctxp[196608 + base];
            sctx[h * 1152 + (ii >> 5) * 36 + (ii & 31)] = s;
        }
    }
    __syncthreads();

    const int h1 = t >> 6, p1 = t & 63;
    {
        float m = -3.402823e38f;
        #pragma unroll
        for (int d = 0; d < 32; d++) m = fmaxf(m, sq[(h1 * 32 + d) * 68 + p1]);
        float s = 0.f;
        #pragma unroll
        for (int d = 0; d < 32; d++) s += __expf(sq[(h1 * 32 + d) * 68 + p1] - m);
        const float inv = 0.17677669529663687f / s;
        #pragma unroll
        for (int d = 0; d < 32; d++)
            sq[(h1 * 32 + d) * 68 + p1] = __expf(sq[(h1 * 32 + d) * 68 + p1] - m) * inv;
    }
    __syncthreads();

    float acc[32];
    #pragma unroll
    for (int i = 0; i < 32; i++) acc[i] = 0.f;
    #pragma unroll
    for (int d = 0; d < 32; d++) {
        const float qv = sq[(h1 * 32 + d) * 68 + p1];
        const float* cr = sctx + h1 * 1152 + d * 36;
        #pragma unroll
        for (int e4 = 0; e4 < 8; e4++) {
            const float4 cv = *(const float4*)(cr + e4 * 4);
            acc[e4 * 4 + 0] += cv.x * qv;
            acc[e4 * 4 + 1] += cv.y * qv;
            acc[e4 * 4 + 2] += cv.z * qv;
            acc[e4 * 4 + 3] += cv.w * qv;
        }
    }
    __syncthreads();

    const uint32_t ABUF = 20480;
    const int a_r = t >> 2, a_ch = t & 3;
    #pragma unroll
    for (int s = 0; s < 2; s++) {
        const int k0 = s * 32;
        #pragma unroll
        for (int i = 0; i < 4; i++) {
            const int row = a_r + i * 64;
            cp16(aBase + (uint32_t)s * ABUF + (uint32_t)row * 80 + a_ch * 16,
                 g_woh + (size_t)row * 256 + k0 + a_ch * 8);
        }
        cp_commit();
    }
    {
        union { __half h[32]; uint4 u[4]; } hb;
        #pragma unroll
        for (int i = 0; i < 32; i++) hb.h[i] = __float2half(acc[i]);
        uint4* dst = (uint4*)(sbh + p1 * 136 + h1 * 32);
        dst[0] = hb.u[0]; dst[1] = hb.u[1]; dst[2] = hb.u[2]; dst[3] = hb.u[3];
    }

    const int wid = t >> 5, lane = t & 31;
    const int warp_m = wid >> 1, warp_n = wid & 1;
    const int aRowL = warp_m * 64 + (lane & 15);
    const uint32_t aCol16 = (uint32_t)(lane >> 4) * 16;
    const int bg = lane >> 3, blr = lane & 7;
    const int bRowL = warp_n * 32 + (bg >> 1) * 8 + blr;
    const uint32_t bCol16 = (uint32_t)(bg & 1) * 16;

    float d[4][4][4];
    #pragma unroll
    for (int mf = 0; mf < 4; mf++)
        #pragma unroll
        for (int nf = 0; nf < 4; nf++)
            #pragma unroll
            for (int r = 0; r < 4; r++) d[mf][nf][r] = 0.f;

    int buf = 0;
    for (int it = 0; it < 8; it++) {
        cp_wait1();
        __syncthreads();
        if (it + 2 < 8) {
            int nb = buf + 2; if (nb >= 3) nb -= 3;
            const int k0 = (it + 2) * 32;
            #pragma unroll
            for (int i = 0; i < 4; i++) {
                const int row = a_r + i * 64;
                cp16(aBase + (uint32_t)nb * ABUF + (uint32_t)row * 80 + a_ch * 16,
                     g_woh + (size_t)row * 256 + k0 + a_ch * 8);
            }
        }
        cp_commit();
        const uint32_t ab = aBase + (uint32_t)buf * ABUF;
        #pragma unroll
        for (int ks = 0; ks < 2; ks++) {
            const int kslot = (it * 2 + ks) & 7;
            uint32_t rb[4][2];
            #pragma unroll
            for (int nf2 = 0; nf2 < 2; nf2++) {
                uint32_t r0, r1, r2, r3;
                const uint32_t addr = bBase + (uint32_t)(bRowL + nf2 * 16) * 272
                                    + kslot * 32 + bCol16;
                ldmatrix_x4(r0, r1, r2, r3, addr);
                rb[nf2 * 2][0] = r0;     rb[nf2 * 2][1] = r1;
                rb[nf2 * 2 + 1][0] = r2; rb[nf2 * 2 + 1][1] = r3;
            }
            uint32_t ra[4][4];
            #pragma unroll
            for (int mf = 0; mf < 4; mf++) {
                const uint32_t addr = ab + (uint32_t)(aRowL + mf * 16) * 80 + ks * 32 + aCol16;
                ldmatrix_x4(ra[mf][0], ra[mf][1], ra[mf][2], ra[mf][3], addr);
            }
            #pragma unroll
            for (int mf = 0; mf < 4; mf++)
                #pragma unroll
                for (int nf = 0; nf < 4; nf++)
                    mma_f16(d[mf][nf], ra[mf], rb[nf]);
        }
        buf++; if (buf == 3) buf = 0;
    }
    __syncthreads();

    const int mB = warp_m * 64 + (lane >> 2);
    const int nB = warp_n * 32 + (lane & 3) * 2;
    #pragma unroll
    for (int mf = 0; mf < 4; mf++) {
        #pragma unroll
        for (int nf = 0; nf < 4; nf++) {
            const int m = mB + mf * 16;
            const int n = nB + nf * 8;
            const float bo0 = b_out[m], bo1 = b_out[m + 8];
            ys[m * 66 + n]           = d[mf][nf][0] + bo0;
            ys[m * 66 + n + 1]       = d[mf][nf][1] + bo0;
            ys[(m + 8) * 66 + n]     = d[mf][nf][2] + bo1;
            ys[(m + 8) * 66 + n + 1] = d[mf][nf][3] + bo1;
        }
    }
    __syncthreads();
    {
        float s0 = 0.f, q0 = 0.f, s1 = 0.f, q1 = 0.f;
        #pragma unroll
        for (int c = 0; c < 32; c++) {
            const float v0 = ys[(wid * 32 + c) * 66 + lane];
            const float v1 = ys[(wid * 32 + c) * 66 + lane + 32];
            s0 += v0; q0 += v0 * v0;
            s1 += v1; q1 += v1 * v1;
        }
        redS[wid * 64 + lane] = s0;      redQ[wid * 64 + lane] = q0;
        redS[wid * 64 + lane + 32] = s1; redQ[wid * 64 + lane + 32] = q1;
    }
    __syncthreads();
    if (t < 64) {
        float s = 0.f, q = 0.f;
        #pragma unroll
        for (int w = 0; w < 8; w++) { s += redS[w * 64 + t]; q += redQ[w * 64 + t]; }
        const float mu  = s * (1.f / 256.f);
        const float var = q * (1.f / 256.f) - mu * mu;
        smu[t] = mu;
        srs[t] = rsqrtf(var + 1e-5f);
    }
    __syncthreads();
    {
        const int n2 = t & 63;
        const float mu = smu[n2], rs = srs[n2];
        float* ob = out + (size_t)b * C_ * NP + p0 + n2;
        for (int o = t >> 6; o < C_; o += 4) {
            ob[(size_t)o * NP] = (ys[o * 66 + n2] - mu) * rs * g[o];
        }
    }
}

// ---------------------------------------------------------------------------
extern "C" void kernel_launch(void* const* d_in, const int* in_sizes, int n_in,
                              void* d_out, int out_size)
{
    const float* x     = (const float*)d_in[0];
    const float* w_qkv = (const float*)d_in[1];
    const float* w_out = (const float*)d_in[2];
    const float* b_out = (const float*)d_in[3];
    const float* g     = (const float*)d_in[4];
    float* out = (float*)d_out;
    (void)in_sizes; (void)n_in; (void)out_size;

    k_conv_all<<<16896, 256>>>(x, w_qkv, w_out);
    k_qkv_mma<<<dim3(32, 3, 16), 256>>>();
    k_kstats<<<2048, 256>>>();
    k_context<<<dim3(4, 64), 256>>>();
    k_attn_out<<<dim3(64, 16), 256>>>(b_out, g, out);
}

// round 14
// speedup vs baseline: 3.4664x; 1.1319x over previous
#include <cuda_runtime.h>
#include <cuda_fp16.h>
#include <cstdint>
#include <cstddef>

// Problem constants
#define B_     16
#define C_     256
#define HID    128
#define NH     4
#define DH     32
#define NP     4096       // 64*64 spatial positions
#define QKV_CH 384

// Scratch (device globals: allocation-free rule)
__device__ float  g_qkv[(size_t)B_ * HID * NP];      // q only, fp32 (33MB)
__device__ float  g_ctxp[4 * 64 * 1024];
__device__ __half g_wh [(size_t)QKV_CH * 256];       // w_qkv fp16 (single-term)
__device__ __half g_xh [(size_t)B_ * NP * 256];      // x^T fp16 (33MB)
__device__ __half g_woh[(size_t)C_ * 128];           // w_out fp16 (single-term)
__device__ __half g_kh [(size_t)B_ * HID * NP];      // k fp16 (17MB)
__device__ __half g_keh[(size_t)B_ * HID * NP];      // softmax_n(k) fp16 (17MB)
__device__ __half g_vh [(size_t)B_ * HID * NP];      // v/4096 fp16 (17MB)

// ---------------------------------------------------------------------------
// Portable PTX helpers (sm_80+ only — harness lowers via compute_103 (non-'a'))
// ---------------------------------------------------------------------------
__device__ __forceinline__ uint32_t smem_u32(const void* p) {
    uint32_t a;
    asm("{ .reg .u64 t; cvta.to.shared.u64 t, %1; cvt.u32.u64 %0, t; }" : "=r"(a) : "l"(p));
    return a;
}
__device__ __forceinline__ void cp16(uint32_t s, const void* g) {
    asm volatile("cp.async.cg.shared.global [%0], [%1], 16;" :: "r"(s), "l"(g));
}
__device__ __forceinline__ void cp_commit() {
    asm volatile("cp.async.commit_group;" ::: "memory");
}
__device__ __forceinline__ void cp_wait1() {
    asm volatile("cp.async.wait_group 1;" ::: "memory");
}
__device__ __forceinline__ void ldmatrix_x4(uint32_t& r0, uint32_t& r1,
                                            uint32_t& r2, uint32_t& r3, uint32_t addr) {
    asm volatile("ldmatrix.sync.aligned.m8n8.x4.shared.b16 {%0,%1,%2,%3}, [%4];"
                 : "=r"(r0), "=r"(r1), "=r"(r2), "=r"(r3) : "r"(addr));
}
__device__ __forceinline__ void mma_f16(float* d, const uint32_t* a, const uint32_t* b) {
    asm volatile(
        "mma.sync.aligned.m16n8k16.row.col.f32.f16.f16.f32 "
        "{%0,%1,%2,%3}, {%4,%5,%6,%7}, {%8,%9}, {%0,%1,%2,%3};"
        : "+f"(d[0]), "+f"(d[1]), "+f"(d[2]), "+f"(d[3])
        : "r"(a[0]), "r"(a[1]), "r"(a[2]), "r"(a[3]), "r"(b[0]), "r"(b[1]));
}

// ---------------------------------------------------------------------------
// K0: ALL input conversions in one launch (single-term fp16 everywhere).
// ---------------------------------------------------------------------------
__global__ __launch_bounds__(256) void k_conv_all(
    const float* __restrict__ x, const float* __restrict__ wq, const float* __restrict__ wo)
{
    __shared__ float tile[32][33];
    const int bid = blockIdx.x;
    if (bid < 16384) {
        const int b  = bid >> 10;
        const int c0 = ((bid >> 7) & 7) * 32;
        const int p0 = (bid & 127) * 32;
        const int tp = threadIdx.x & 31, tc = threadIdx.x >> 5;
        #pragma unroll
        for (int j = 0; j < 4; j++) {
            const int c = tc + j * 8;
            tile[c][tp] = x[((size_t)b * C_ + c0 + c) * NP + p0 + tp];
        }
        __syncthreads();
        if (threadIdx.x < 128) {
            const int p = threadIdx.x >> 2, ch = threadIdx.x & 3;
            union { __half h[8]; uint4 u; } vb;
            #pragma unroll
            for (int j = 0; j < 8; j++) vb.h[j] = __float2half(tile[ch * 8 + j][p]);
            *(uint4*)(g_xh + ((size_t)b * NP + p0 + p) * 256 + c0 + ch * 8) = vb.u;
        }
    } else if (bid < 16768) {
        const int i = (bid - 16384) * 256 + threadIdx.x;    // < 98304
        g_wh[i] = __float2half(wq[i]);
    } else {
        const int i = (bid - 16768) * 256 + threadIdx.x;    // < 32768
        g_woh[i] = __float2half(wo[i]);
    }
}

// ---------------------------------------------------------------------------
// K1: qkv GEMM, UNIFIED single-term fp16 for all 3 blocks. Per CTA: M=128,
// N=128, K=256, BK=32, 8 iters, 3-stage ring. blockIdx.y: 0=q (fp32 out),
// 1=k (fp16 out), 2=v (fp16 * 1/4096 out).
// ---------------------------------------------------------------------------
__global__ __launch_bounds__(256) void k_qkv_mma()
{
    __shared__ __half sA[3][128][40];
    __shared__ __half sB[3][128][40];
    const int tid  = threadIdx.x;
    const int wid  = tid >> 5, lane = tid & 31;
    const int n0 = blockIdx.x * 128;
    const int my = blockIdx.y;
    const int b  = blockIdx.z;
    const int warp_m = wid >> 1, warp_n = wid & 1;

    const __half* __restrict__ Ag = g_wh + (size_t)my * 128 * 256;
    const __half* __restrict__ Bg = g_xh + ((size_t)b * NP + n0) * 256;

    const uint32_t aBase = smem_u32(&sA[0][0][0]);
    const uint32_t bBase = smem_u32(&sB[0][0][0]);
    const uint32_t BUFB = 128 * 80;

    // loaders: 512 16B-chunks/stage each for A and B, 2 per thread.
    uint32_t lso[2]; uint32_t lgi[2];
    #pragma unroll
    for (int i = 0; i < 2; i++) {
        const int slot = tid + i * 256;
        const int r = slot >> 2, ch = slot & 3;
        lso[i] = (uint32_t)r * 80 + ch * 16;
        lgi[i] = (uint32_t)r * 256 + ch * 8;
    }

    const int aRowL = warp_m * 32 + (lane & 15);
    const uint32_t aCol16 = (uint32_t)(lane >> 4) * 16;
    const int bg = lane >> 3, blr = lane & 7;
    const int bRowL = warp_n * 64 + (bg >> 1) * 8 + blr;
    const uint32_t bCol16 = (uint32_t)(bg & 1) * 16;

    float d[2][8][4];
    #pragma unroll
    for (int mf = 0; mf < 2; mf++)
        #pragma unroll
        for (int nf = 0; nf < 8; nf++)
            #pragma unroll
            for (int r = 0; r < 4; r++) d[mf][nf][r] = 0.f;

    #pragma unroll
    for (int s = 0; s < 2; s++) {
        const int k0 = s * 32;
        #pragma unroll
        for (int i = 0; i < 2; i++) {
            cp16(aBase + s * BUFB + lso[i], Ag + lgi[i] + k0);
            cp16(bBase + s * BUFB + lso[i], Bg + lgi[i] + k0);
        }
        cp_commit();
    }

    int buf = 0;
    for (int it = 0; it < 8; it++) {
        cp_wait1();
        __syncthreads();
        if (it + 2 < 8) {
            int nb = buf + 2; if (nb >= 3) nb -= 3;
            const int k0 = (it + 2) * 32;
            #pragma unroll
            for (int i = 0; i < 2; i++) {
                cp16(aBase + (uint32_t)nb * BUFB + lso[i], Ag + lgi[i] + k0);
                cp16(bBase + (uint32_t)nb * BUFB + lso[i], Bg + lgi[i] + k0);
            }
        }
        cp_commit();
        const uint32_t ab = aBase + (uint32_t)buf * BUFB;
        const uint32_t bb = bBase + (uint32_t)buf * BUFB;
        #pragma unroll
        for (int ks = 0; ks < 2; ks++) {
            uint32_t rb[8][2];
            #pragma unroll
            for (int nf2 = 0; nf2 < 4; nf2++) {
                uint32_t r0, r1, r2, r3;
                const uint32_t addr = bb + (uint32_t)(bRowL + nf2 * 16) * 80 + ks * 32 + bCol16;
                ldmatrix_x4(r0, r1, r2, r3, addr);
                rb[nf2 * 2][0] = r0;     rb[nf2 * 2][1] = r1;
                rb[nf2 * 2 + 1][0] = r2; rb[nf2 * 2 + 1][1] = r3;
            }
            uint32_t ra[2][4];
            #pragma unroll
            for (int mf = 0; mf < 2; mf++) {
                const uint32_t addr = ab + (uint32_t)(aRowL + mf * 16) * 80 + ks * 32 + aCol16;
                ldmatrix_x4(ra[mf][0], ra[mf][1], ra[mf][2], ra[mf][3], addr);
            }
            #pragma unroll
            for (int mf = 0; mf < 2; mf++)
                #pragma unroll
                for (int nf = 0; nf < 8; nf++)
                    mma_f16(d[mf][nf], ra[mf], rb[nf]);
        }
        buf++; if (buf == 3) buf = 0;
    }

    const int mBase = warp_m * 32 + (lane >> 2);
    const int nBase = n0 + warp_n * 64 + (lane & 3) * 2;
    if (my == 0) {
        float* outb = g_qkv + (size_t)b * HID * NP;
        #pragma unroll
        for (int mf = 0; mf < 2; mf++) {
            #pragma unroll
            for (int nf = 0; nf < 8; nf++) {
                const int m = mBase + mf * 16;
                const int n = nBase + nf * 8;
                *(float2*)(outb + (size_t)m * NP + n)       = make_float2(d[mf][nf][0], d[mf][nf][1]);
                *(float2*)(outb + (size_t)(m + 8) * NP + n) = make_float2(d[mf][nf][2], d[mf][nf][3]);
            }
        }
    } else {
        const float sc = (my == 2) ? (1.f / 4096.f) : 1.f;
        __half* outb = ((my == 2) ? g_vh : g_kh) + (size_t)b * HID * NP;
        #pragma unroll
        for (int mf = 0; mf < 2; mf++) {
            #pragma unroll
            for (int nf = 0; nf < 8; nf++) {
                const int m = mBase + mf * 16;
                const int n = nBase + nf * 8;
                *(__half2*)(outb + (size_t)m * NP + n) =
                    __floats2half2_rn(d[mf][nf][0] * sc, d[mf][nf][1] * sc);
                *(__half2*)(outb + (size_t)(m + 8) * NP + n) =
                    __floats2half2_rn(d[mf][nf][2] * sc, d[mf][nf][3] * sc);
            }
        }
    }
}

// ---------------------------------------------------------------------------
// K2: per k-row softmax over n=4096 from fp16 g_kh -> fp16 g_keh.
// ---------------------------------------------------------------------------
__global__ __launch_bounds__(256) void k_kstats()
{
    __shared__ float red[256];
    const int row = blockIdx.x;
    const __half* base = g_kh + (size_t)row * NP;
    const int t = threadIdx.x;
    float vals[16];
    #pragma unroll
    for (int j = 0; j < 2; j++) {
        const uint4 raw = *(const uint4*)(base + (j * 256 + t) * 8);
        const __half2* hp = (const __half2*)&raw;
        #pragma unroll
        for (int w = 0; w < 4; w++) {
            const float2 f = __half22float2(hp[w]);
            vals[j * 8 + w * 2]     = f.x;
            vals[j * 8 + w * 2 + 1] = f.y;
        }
    }
    float m = vals[0];
    #pragma unroll
    for (int i = 1; i < 16; i++) m = fmaxf(m, vals[i]);
    red[t] = m; __syncthreads();
    for (int off = 128; off > 0; off >>= 1) {
        if (t < off) red[t] = fmaxf(red[t], red[t + off]);
        __syncthreads();
    }
    m = red[0];
    __syncthreads();
    float e16[16];
    float s = 0.f;
    #pragma unroll
    for (int i = 0; i < 16; i++) { e16[i] = __expf(vals[i] - m); s += e16[i]; }
    red[t] = s; __syncthreads();
    for (int off = 128; off > 0; off >>= 1) {
        if (t < off) red[t] += red[t + off];
        __syncthreads();
    }
    const float inv = 1.f / red[0];
    __half* krow = g_keh + (size_t)row * NP;
    #pragma unroll
    for (int j = 0; j < 2; j++) {
        union { __half h[8]; uint4 u; } pk;
        #pragma unroll
        for (int i = 0; i < 8; i++) pk.h[i] = __float2half(e16[j * 8 + i] * inv);
        *(uint4*)(krow + (j * 256 + t) * 8) = pk.u;
    }
}

// ---------------------------------------------------------------------------
// K3: context = kexp @ vh^T, pure fp16 HMMA (unchanged).
// ---------------------------------------------------------------------------
__global__ __launch_bounds__(256) void k_context()
{
    __shared__ char cxs[34816];
    const uint32_t skB = smem_u32(cxs);
    const uint32_t svB = skB + 17408;
    float* red = (float*)cxs;

    const int ch = blockIdx.x;     // 0..3
    const int z  = blockIdx.y;     // b*4+h
    const int b = z >> 2, h = z & 3;
    const __half* __restrict__ kg = g_keh + ((size_t)b * HID + h * DH) * NP + ch * 1024;
    const __half* __restrict__ vg = g_vh  + ((size_t)b * HID + h * DH) * NP + ch * 1024;

    const int t = threadIdx.x;
    const int wid = t >> 5, lane = t & 31;

    uint32_t lso[4]; uint32_t lgi[4]; bool lk[4];
    #pragma unroll
    for (int i = 0; i < 4; i++) {
        const int slot = t + i * 256;
        const int s = slot & 511;
        const int r = s >> 4, c = s & 15;
        lso[i] = (uint32_t)r * 272 + c * 16;
        lgi[i] = (uint32_t)r * NP + c * 8;
        lk[i] = slot < 512;
    }

    const int aRow = lane & 15;
    const uint32_t aCol16 = (uint32_t)(lane >> 4) * 16;
    const int bg = lane >> 3, blr = lane & 7;
    const int bRow = (bg >> 1) * 8 + blr;
    const uint32_t bCol16 = (uint32_t)(bg & 1) * 16;
    const uint32_t kbyte = (uint32_t)wid * 32;

    float d[2][4][4];
    #pragma unroll
    for (int mf = 0; mf < 2; mf++)
        #pragma unroll
        for (int nf = 0; nf < 4; nf++)
            #pragma unroll
            for (int r = 0; r < 4; r++) d[mf][nf][r] = 0.f;

    #pragma unroll
    for (int i = 0; i < 4; i++)
        cp16((lk[i] ? skB : svB) + lso[i], (lk[i] ? kg : vg) + lgi[i]);
    cp_commit();

    int buf = 0;
    for (int it = 0; it < 8; it++) {
        __syncthreads();
        if (it + 1 < 8) {
            const uint32_t boff = (uint32_t)(buf ^ 1) * 8704;
            const int n0 = (it + 1) * 128;
            #pragma unroll
            for (int i = 0; i < 4; i++)
                cp16((lk[i] ? skB : svB) + boff + lso[i], (lk[i] ? kg : vg) + lgi[i] + n0);
        }
        cp_commit();
        cp_wait1();
        __syncthreads();
        const uint32_t boff = (uint32_t)buf * 8704;
        uint32_t ra[2][4];
        #pragma unroll
        for (int mf = 0; mf < 2; mf++) {
            const uint32_t addr = skB + boff + (uint32_t)(aRow + mf * 16) * 272 + kbyte + aCol16;
            ldmatrix_x4(ra[mf][0], ra[mf][1], ra[mf][2], ra[mf][3], addr);
        }
        uint32_t rb[4][2];
        #pragma unroll
        for (int nf2 = 0; nf2 < 2; nf2++) {
            uint32_t r0, r1, r2, r3;
            const uint32_t addr = svB + boff + (uint32_t)(bRow + nf2 * 16) * 272 + kbyte + bCol16;
            ldmatrix_x4(r0, r1, r2, r3, addr);
            rb[nf2 * 2][0] = r0;     rb[nf2 * 2][1] = r1;
            rb[nf2 * 2 + 1][0] = r2; rb[nf2 * 2 + 1][1] = r3;
        }
        #pragma unroll
        for (int mf = 0; mf < 2; mf++)
            #pragma unroll
            for (int nf = 0; nf < 4; nf++)
                mma_f16(d[mf][nf], ra[mf], rb[nf]);
        buf ^= 1;
    }
    __syncthreads();

    #pragma unroll
    for (int mf = 0; mf < 2; mf++) {
        #pragma unroll
        for (int nf = 0; nf < 4; nf++) {
            const int m = mf * 16 + (lane >> 2);
            const int n = nf * 8 + (lane & 3) * 2;
            red[wid * 1024 + m * 32 + n]           = d[mf][nf][0];
            red[wid * 1024 + m * 32 + n + 1]       = d[mf][nf][1];
            red[wid * 1024 + (m + 8) * 32 + n]     = d[mf][nf][2];
            red[wid * 1024 + (m + 8) * 32 + n + 1] = d[mf][nf][3];
        }
    }
    __syncthreads();
    float* o = g_ctxp + ((size_t)ch * 64 + z) * 1024;
    #pragma unroll
    for (int i = 0; i < 4; i++) {
        const int idx = t * 4 + i;
        float s = 0.f;
        #pragma unroll
        for (int w = 0; w < 8; w++) s += red[w * 1024 + idx];
        o[idx] = s;
    }
}

// ---------------------------------------------------------------------------
// K4: FUSED attn + out-conv + LayerNorm. w_out single-term -> GEMM K=128,
// 4 iters. ctx chunk-reduce inlined into sctx load.
// ---------------------------------------------------------------------------
__global__ __launch_bounds__(256, 2) void k_attn_out(
    const float* __restrict__ b_out, const float* __restrict__ g, float* __restrict__ out)
{
    __shared__ alignas(128) char smem_raw[83456];
    const uint32_t aBase = smem_u32(smem_raw);
    const uint32_t bBase = aBase + 61440;
    float* sq   = (float*)smem_raw;                 // [128][68]
    float* sctx = (float*)(smem_raw + 34816);       // [4][32][36]
    __half* sbh = (__half*)(smem_raw + 61440);      // [64][136]
    float* ys   = (float*)smem_raw;                 // [256][66]
    float* redS = (float*)(smem_raw + 78848);
    float* redQ = (float*)(smem_raw + 80896);
    float* smu  = (float*)(smem_raw + 82944);
    float* srs  = (float*)(smem_raw + 83200);

    const int t  = threadIdx.x;
    const int p0 = blockIdx.x * 64;
    const int b  = blockIdx.y;

    {
        const float* qb = g_qkv + (size_t)b * HID * NP;
        const int row = t >> 1, hf = (t & 1) * 32;
        #pragma unroll
        for (int j = 0; j < 8; j++) {
            const float4 v = *(const float4*)(qb + (size_t)row * NP + p0 + hf + j * 4);
            const int c = hf + j * 4;
            sq[row * 68 + c] = v.x; sq[row * 68 + c + 1] = v.y;
            sq[row * 68 + c + 2] = v.z; sq[row * 68 + c + 3] = v.w;
        }
        #pragma unroll
        for (int i = 0; i < 16; i++) {
            const int idx = t + i * 256;
            const int h = idx >> 10, ii = idx & 1023;
            const size_t base = (size_t)(b * 4 + h) * 1024 + ii;
            float s = g_ctxp[base] + g_ctxp[65536 + base]
                    + g_ctxp[131072 + base] + g_ctxp[196608 + base];
            sctx[h * 1152 + (ii >> 5) * 36 + (ii & 31)] = s;
        }
    }
    __syncthreads();

    const int h1 = t >> 6, p1 = t & 63;
    {
        float m = -3.402823e38f;
        #pragma unroll
        for (int d = 0; d < 32; d++) m = fmaxf(m, sq[(h1 * 32 + d) * 68 + p1]);
        float s = 0.f;
        #pragma unroll
        for (int d = 0; d < 32; d++) s += __expf(sq[(h1 * 32 + d) * 68 + p1] - m);
        const float inv = 0.17677669529663687f / s;
        #pragma unroll
        for (int d = 0; d < 32; d++)
            sq[(h1 * 32 + d) * 68 + p1] = __expf(sq[(h1 * 32 + d) * 68 + p1] - m) * inv;
    }
    __syncthreads();

    float acc[32];
    #pragma unroll
    for (int i = 0; i < 32; i++) acc[i] = 0.f;
    #pragma unroll
    for (int d = 0; d < 32; d++) {
        const float qv = sq[(h1 * 32 + d) * 68 + p1];
        const float* cr = sctx + h1 * 1152 + d * 36;
        #pragma unroll
        for (int e4 = 0; e4 < 8; e4++) {
            const float4 cv = *(const float4*)(cr + e4 * 4);
            acc[e4 * 4 + 0] += cv.x * qv;
            acc[e4 * 4 + 1] += cv.y * qv;
            acc[e4 * 4 + 2] += cv.z * qv;
            acc[e4 * 4 + 3] += cv.w * qv;
        }
    }
    __syncthreads();

    // A prologue: w_out [256][128] fp16, 4 BK=32 stages, ring of 3.
    const uint32_t ABUF = 20480;
    const int a_r = t >> 2, a_ch = t & 3;
    #pragma unroll
    for (int s = 0; s < 2; s++) {
        const int k0 = s * 32;
        #pragma unroll
        for (int i = 0; i < 4; i++) {
            const int row = a_r + i * 64;
            cp16(aBase + (uint32_t)s * ABUF + (uint32_t)row * 80 + a_ch * 16,
                 g_woh + (size_t)row * 128 + k0 + a_ch * 8);
        }
        cp_commit();
    }
    {
        union { __half h[32]; uint4 u[4]; } hb;
        #pragma unroll
        for (int i = 0; i < 32; i++) hb.h[i] = __float2half(acc[i]);
        uint4* dst = (uint4*)(sbh + p1 * 136 + h1 * 32);
        dst[0] = hb.u[0]; dst[1] = hb.u[1]; dst[2] = hb.u[2]; dst[3] = hb.u[3];
    }

    const int wid = t >> 5, lane = t & 31;
    const int warp_m = wid >> 1, warp_n = wid & 1;
    const int aRowL = warp_m * 64 + (lane & 15);
    const uint32_t aCol16 = (uint32_t)(lane >> 4) * 16;
    const int bg = lane >> 3, blr = lane & 7;
    const int bRowL = warp_n * 32 + (bg >> 1) * 8 + blr;
    const uint32_t bCol16 = (uint32_t)(bg & 1) * 16;

    float d[4][4][4];
    #pragma unroll
    for (int mf = 0; mf < 4; mf++)
        #pragma unroll
        for (int nf = 0; nf < 4; nf++)
            #pragma unroll
            for (int r = 0; r < 4; r++) d[mf][nf][r] = 0.f;

    int buf = 0;
    for (int it = 0; it < 4; it++) {
        cp_wait1();
        __syncthreads();    // also publishes sbh on it==0
        if (it + 2 < 4) {
            int nb = buf + 2; if (nb >= 3) nb -= 3;
            const int k0 = (it + 2) * 32;
            #pragma unroll
            for (int i = 0; i < 4; i++) {
                const int row = a_r + i * 64;
                cp16(aBase + (uint32_t)nb * ABUF + (uint32_t)row * 80 + a_ch * 16,
                     g_woh + (size_t)row * 128 + k0 + a_ch * 8);
            }
        }
        cp_commit();
        const uint32_t ab = aBase + (uint32_t)buf * ABUF;
        #pragma unroll
        for (int ks = 0; ks < 2; ks++) {
            const int kslot = it * 2 + ks;           // B col chunk 0..7 (K=128)
            uint32_t rb[4][2];
            #pragma unroll
            for (int nf2 = 0; nf2 < 2; nf2++) {
                uint32_t r0, r1, r2, r3;
                const uint32_t addr = bBase + (uint32_t)(bRowL + nf2 * 16) * 272
                                    + kslot * 32 + bCol16;
                ldmatrix_x4(r0, r1, r2, r3, addr);
                rb[nf2 * 2][0] = r0;     rb[nf2 * 2][1] = r1;
                rb[nf2 * 2 + 1][0] = r2; rb[nf2 * 2 + 1][1] = r3;
            }
            uint32_t ra[4][4];
            #pragma unroll
            for (int mf = 0; mf < 4; mf++) {
                const uint32_t addr = ab + (uint32_t)(aRowL + mf * 16) * 80 + ks * 32 + aCol16;
                ldmatrix_x4(ra[mf][0], ra[mf][1], ra[mf][2], ra[mf][3], addr);
            }
            #pragma unroll
            for (int mf = 0; mf < 4; mf++)
                #pragma unroll
                for (int nf = 0; nf < 4; nf++)
                    mma_f16(d[mf][nf], ra[mf], rb[nf]);
        }
        buf++; if (buf == 3) buf = 0;
    }
    __syncthreads();

    const int mB = warp_m * 64 + (lane >> 2);
    const int nB = warp_n * 32 + (lane & 3) * 2;
    #pragma unroll
    for (int mf = 0; mf < 4; mf++) {
        #pragma unroll
        for (int nf = 0; nf < 4; nf++) {
            const int m = mB + mf * 16;
            const int n = nB + nf * 8;
            const float bo0 = b_out[m], bo1 = b_out[m + 8];
            ys[m * 66 + n]           = d[mf][nf][0] + bo0;
            ys[m * 66 + n + 1]       = d[mf][nf][1] + bo0;
            ys[(m + 8) * 66 + n]     = d[mf][nf][2] + bo1;
            ys[(m + 8) * 66 + n + 1] = d[mf][nf][3] + bo1;
        }
    }
    __syncthreads();
    {
        float s0 = 0.f, q0 = 0.f, s1 = 0.f, q1 = 0.f;
        #pragma unroll
        for (int c = 0; c < 32; c++) {
            const float v0 = ys[(wid * 32 + c) * 66 + lane];
            const float v1 = ys[(wid * 32 + c) * 66 + lane + 32];
            s0 += v0; q0 += v0 * v0;
            s1 += v1; q1 += v1 * v1;
        }
        redS[wid * 64 + lane] = s0;      redQ[wid * 64 + lane] = q0;
        redS[wid * 64 + lane + 32] = s1; redQ[wid * 64 + lane + 32] = q1;
    }
    __syncthreads();
    if (t < 64) {
        float s = 0.f, q = 0.f;
        #pragma unroll
        for (int w = 0; w < 8; w++) { s += redS[w * 64 + t]; q += redQ[w * 64 + t]; }
        const float mu  = s * (1.f / 256.f);
        const float var = q * (1.f / 256.f) - mu * mu;
        smu[t] = mu;
        srs[t] = rsqrtf(var + 1e-5f);
    }
    __syncthreads();
    {
        const int n2 = t & 63;
        const float mu = smu[n2], rs = srs[n2];
        float* ob = out + (size_t)b * C_ * NP + p0 + n2;
        for (int o = t >> 6; o < C_; o += 4) {
            ob[(size_t)o * NP] = (ys[o * 66 + n2] - mu) * rs * g[o];
        }
    }
}

// ---------------------------------------------------------------------------
extern "C" void kernel_launch(void* const* d_in, const int* in_sizes, int n_in,
                              void* d_out, int out_size)
{
    const float* x     = (const float*)d_in[0];
    const float* w_qkv = (const float*)d_in[1];
    const float* w_out = (const float*)d_in[2];
    const float* b_out = (const float*)d_in[3];
    const float* g     = (const float*)d_in[4];
    float* out = (float*)d_out;
    (void)in_sizes; (void)n_in; (void)out_size;

    k_conv_all<<<16896, 256>>>(x, w_qkv, w_out);
    k_qkv_mma<<<dim3(32, 3, 16), 256>>>();
    k_kstats<<<2048, 256>>>();
    k_context<<<dim3(4, 64), 256>>>();
    k_attn_out<<<dim3(64, 16), 256>>>(b_out, g, out);
}

// round 15
// speedup vs baseline: 3.4992x; 1.0095x over previous
#include <cuda_runtime.h>
#include <cuda_fp16.h>
#include <cstdint>
#include <cstddef>

// Problem constants
#define B_     16
#define C_     256
#define HID    128
#define NH     4
#define DH     32
#define NP     4096       // 64*64 spatial positions
#define QKV_CH 384

// Scratch (device globals: allocation-free rule)
__device__ float  g_qkv[(size_t)B_ * HID * NP];      // q only, fp32 (33MB)
__device__ float  g_ctxp[8 * 64 * 1024];
__device__ __half g_wh [(size_t)QKV_CH * 256];       // w_qkv fp16 (single-term)
__device__ __half g_xh [(size_t)B_ * NP * 256];      // x^T fp16 (33MB)
__device__ __half g_woh[(size_t)C_ * 128];           // w_out fp16 (single-term)
__device__ __half g_kh [(size_t)B_ * HID * NP];      // k fp16 (17MB)
__device__ __half g_keh[(size_t)B_ * HID * NP];      // softmax_n(k) fp16 (17MB)
__device__ __half g_vh [(size_t)B_ * HID * NP];      // v/4096 fp16 (17MB)

// ---------------------------------------------------------------------------
// Portable PTX helpers (sm_80+ only — harness lowers via compute_103 (non-'a'))
// ---------------------------------------------------------------------------
__device__ __forceinline__ uint32_t smem_u32(const void* p) {
    uint32_t a;
    asm("{ .reg .u64 t; cvta.to.shared.u64 t, %1; cvt.u32.u64 %0, t; }" : "=r"(a) : "l"(p));
    return a;
}
__device__ __forceinline__ void cp16(uint32_t s, const void* g) {
    asm volatile("cp.async.cg.shared.global [%0], [%1], 16;" :: "r"(s), "l"(g));
}
__device__ __forceinline__ void cp_commit() {
    asm volatile("cp.async.commit_group;" ::: "memory");
}
__device__ __forceinline__ void cp_wait1() {
    asm volatile("cp.async.wait_group 1;" ::: "memory");
}
__device__ __forceinline__ void ldmatrix_x4(uint32_t& r0, uint32_t& r1,
                                            uint32_t& r2, uint32_t& r3, uint32_t addr) {
    asm volatile("ldmatrix.sync.aligned.m8n8.x4.shared.b16 {%0,%1,%2,%3}, [%4];"
                 : "=r"(r0), "=r"(r1), "=r"(r2), "=r"(r3) : "r"(addr));
}
__device__ __forceinline__ void mma_f16(float* d, const uint32_t* a, const uint32_t* b) {
    asm volatile(
        "mma.sync.aligned.m16n8k16.row.col.f32.f16.f16.f32 "
        "{%0,%1,%2,%3}, {%4,%5,%6,%7}, {%8,%9}, {%0,%1,%2,%3};"
        : "+f"(d[0]), "+f"(d[1]), "+f"(d[2]), "+f"(d[3])
        : "r"(a[0]), "r"(a[1]), "r"(a[2]), "r"(a[3]), "r"(b[0]), "r"(b[1]));
}

// ---------------------------------------------------------------------------
// K0: ALL input conversions in one launch.
// blocks [0,4096): x transpose-convert, 128p x 32c tiles (vectorized).
// blocks [4096,4480): w_qkv fp16. blocks [4480,4608): w_out fp16.
// ---------------------------------------------------------------------------
__global__ __launch_bounds__(256) void k_conv_all(
    const float* __restrict__ x, const float* __restrict__ wq, const float* __restrict__ wo)
{
    __shared__ float tile[32][132];     // [c][p], 132-pad (2-way conflicts max)
    const int bid = blockIdx.x;
    const int t = threadIdx.x;
    if (bid < 4096) {
        const int b  = bid >> 8;                 // 16
        const int c0 = ((bid >> 5) & 7) * 32;    // 8
        const int p0 = (bid & 31) * 128;         // 32
        // load 32 c-rows x 128 p (16KB) with float4
        #pragma unroll
        for (int i = 0; i < 4; i++) {
            const int slot = t + i * 256;        // 1024 chunks of 16B
            const int row = slot >> 5, ch = slot & 31;
            const float4 v = *(const float4*)(x + ((size_t)b * C_ + c0 + row) * NP + p0 + ch * 4);
            *(float4*)&tile[row][ch * 4] = v;
        }
        __syncthreads();
        // write: thread -> (p = t>>1, 16-channel half), 32B contiguous
        const int p = t >> 1, chalf = (t & 1) * 16;
        union { __half h[16]; uint4 u[2]; } hb;
        #pragma unroll
        for (int j = 0; j < 16; j++) hb.h[j] = __float2half(tile[chalf + j][p]);
        __half* row = g_xh + ((size_t)b * NP + p0 + p) * 256 + c0 + chalf;
        ((uint4*)row)[0] = hb.u[0];
        ((uint4*)row)[1] = hb.u[1];
    } else if (bid < 4480) {
        const int i = (bid - 4096) * 256 + t;    // < 98304
        g_wh[i] = __float2half(wq[i]);
    } else {
        const int i = (bid - 4480) * 256 + t;    // < 32768
        g_woh[i] = __float2half(wo[i]);
    }
}

// ---------------------------------------------------------------------------
// K1: qkv GEMM, unified single-term fp16 (unchanged from R14 — at the
// mma.sync issue ceiling). blockIdx.y: 0=q (fp32), 1=k (fp16), 2=v (fp16/4096).
// ---------------------------------------------------------------------------
__global__ __launch_bounds__(256) void k_qkv_mma()
{
    __shared__ __half sA[3][128][40];
    __shared__ __half sB[3][128][40];
    const int tid  = threadIdx.x;
    const int wid  = tid >> 5, lane = tid & 31;
    const int n0 = blockIdx.x * 128;
    const int my = blockIdx.y;
    const int b  = blockIdx.z;
    const int warp_m = wid >> 1, warp_n = wid & 1;

    const __half* __restrict__ Ag = g_wh + (size_t)my * 128 * 256;
    const __half* __restrict__ Bg = g_xh + ((size_t)b * NP + n0) * 256;

    const uint32_t aBase = smem_u32(&sA[0][0][0]);
    const uint32_t bBase = smem_u32(&sB[0][0][0]);
    const uint32_t BUFB = 128 * 80;

    uint32_t lso[2]; uint32_t lgi[2];
    #pragma unroll
    for (int i = 0; i < 2; i++) {
        const int slot = tid + i * 256;
        const int r = slot >> 2, ch = slot & 3;
        lso[i] = (uint32_t)r * 80 + ch * 16;
        lgi[i] = (uint32_t)r * 256 + ch * 8;
    }

    const int aRowL = warp_m * 32 + (lane & 15);
    const uint32_t aCol16 = (uint32_t)(lane >> 4) * 16;
    const int bg = lane >> 3, blr = lane & 7;
    const int bRowL = warp_n * 64 + (bg >> 1) * 8 + blr;
    const uint32_t bCol16 = (uint32_t)(bg & 1) * 16;

    float d[2][8][4];
    #pragma unroll
    for (int mf = 0; mf < 2; mf++)
        #pragma unroll
        for (int nf = 0; nf < 8; nf++)
            #pragma unroll
            for (int r = 0; r < 4; r++) d[mf][nf][r] = 0.f;

    #pragma unroll
    for (int s = 0; s < 2; s++) {
        const int k0 = s * 32;
        #pragma unroll
        for (int i = 0; i < 2; i++) {
            cp16(aBase + s * BUFB + lso[i], Ag + lgi[i] + k0);
            cp16(bBase + s * BUFB + lso[i], Bg + lgi[i] + k0);
        }
        cp_commit();
    }

    int buf = 0;
    for (int it = 0; it < 8; it++) {
        cp_wait1();
        __syncthreads();
        if (it + 2 < 8) {
            int nb = buf + 2; if (nb >= 3) nb -= 3;
            const int k0 = (it + 2) * 32;
            #pragma unroll
            for (int i = 0; i < 2; i++) {
                cp16(aBase + (uint32_t)nb * BUFB + lso[i], Ag + lgi[i] + k0);
                cp16(bBase + (uint32_t)nb * BUFB + lso[i], Bg + lgi[i] + k0);
            }
        }
        cp_commit();
        const uint32_t ab = aBase + (uint32_t)buf * BUFB;
        const uint32_t bb = bBase + (uint32_t)buf * BUFB;
        #pragma unroll
        for (int ks = 0; ks < 2; ks++) {
            uint32_t rb[8][2];
            #pragma unroll
            for (int nf2 = 0; nf2 < 4; nf2++) {
                uint32_t r0, r1, r2, r3;
                const uint32_t addr = bb + (uint32_t)(bRowL + nf2 * 16) * 80 + ks * 32 + bCol16;
                ldmatrix_x4(r0, r1, r2, r3, addr);
                rb[nf2 * 2][0] = r0;     rb[nf2 * 2][1] = r1;
                rb[nf2 * 2 + 1][0] = r2; rb[nf2 * 2 + 1][1] = r3;
            }
            uint32_t ra[2][4];
            #pragma unroll
            for (int mf = 0; mf < 2; mf++) {
                const uint32_t addr = ab + (uint32_t)(aRowL + mf * 16) * 80 + ks * 32 + aCol16;
                ldmatrix_x4(ra[mf][0], ra[mf][1], ra[mf][2], ra[mf][3], addr);
            }
            #pragma unroll
            for (int mf = 0; mf < 2; mf++)
                #pragma unroll
                for (int nf = 0; nf < 8; nf++)
                    mma_f16(d[mf][nf], ra[mf], rb[nf]);
        }
        buf++; if (buf == 3) buf = 0;
    }

    const int mBase = warp_m * 32 + (lane >> 2);
    const int nBase = n0 + warp_n * 64 + (lane & 3) * 2;
    if (my == 0) {
        float* outb = g_qkv + (size_t)b * HID * NP;
        #pragma unroll
        for (int mf = 0; mf < 2; mf++) {
            #pragma unroll
            for (int nf = 0; nf < 8; nf++) {
                const int m = mBase + mf * 16;
                const int n = nBase + nf * 8;
                *(float2*)(outb + (size_t)m * NP + n)       = make_float2(d[mf][nf][0], d[mf][nf][1]);
                *(float2*)(outb + (size_t)(m + 8) * NP + n) = make_float2(d[mf][nf][2], d[mf][nf][3]);
            }
        }
    } else {
        const float sc = (my == 2) ? (1.f / 4096.f) : 1.f;
        __half* outb = ((my == 2) ? g_vh : g_kh) + (size_t)b * HID * NP;
        #pragma unroll
        for (int mf = 0; mf < 2; mf++) {
            #pragma unroll
            for (int nf = 0; nf < 8; nf++) {
                const int m = mBase + mf * 16;
                const int n = nBase + nf * 8;
                *(__half2*)(outb + (size_t)m * NP + n) =
                    __floats2half2_rn(d[mf][nf][0] * sc, d[mf][nf][1] * sc);
                *(__half2*)(outb + (size_t)(m + 8) * NP + n) =
                    __floats2half2_rn(d[mf][nf][2] * sc, d[mf][nf][3] * sc);
            }
        }
    }
}

// ---------------------------------------------------------------------------
// K2: per k-row softmax over n=4096 from fp16 g_kh -> fp16 g_keh.
// ---------------------------------------------------------------------------
__global__ __launch_bounds__(256) void k_kstats()
{
    __shared__ float red[256];
    const int row = blockIdx.x;
    const __half* base = g_kh + (size_t)row * NP;
    const int t = threadIdx.x;
    float vals[16];
    #pragma unroll
    for (int j = 0; j < 2; j++) {
        const uint4 raw = *(const uint4*)(base + (j * 256 + t) * 8);
        const __half2* hp = (const __half2*)&raw;
        #pragma unroll
        for (int w = 0; w < 4; w++) {
            const float2 f = __half22float2(hp[w]);
            vals[j * 8 + w * 2]     = f.x;
            vals[j * 8 + w * 2 + 1] = f.y;
        }
    }
    float m = vals[0];
    #pragma unroll
    for (int i = 1; i < 16; i++) m = fmaxf(m, vals[i]);
    red[t] = m; __syncthreads();
    for (int off = 128; off > 0; off >>= 1) {
        if (t < off) red[t] = fmaxf(red[t], red[t + off]);
        __syncthreads();
    }
    m = red[0];
    __syncthreads();
    float e16[16];
    float s = 0.f;
    #pragma unroll
    for (int i = 0; i < 16; i++) { e16[i] = __expf(vals[i] - m); s += e16[i]; }
    red[t] = s; __syncthreads();
    for (int off = 128; off > 0; off >>= 1) {
        if (t < off) red[t] += red[t + off];
        __syncthreads();
    }
    const float inv = 1.f / red[0];
    __half* krow = g_keh + (size_t)row * NP;
    #pragma unroll
    for (int j = 0; j < 2; j++) {
        union { __half h[8]; uint4 u; } pk;
        #pragma unroll
        for (int i = 0; i < 8; i++) pk.h[i] = __float2half(e16[j * 8 + i] * inv);
        *(uint4*)(krow + (j * 256 + t) * 8) = pk.u;
    }
}

// ---------------------------------------------------------------------------
// K3: context = kexp @ vh^T, fp16 HMMA. Grid (8 n-chunks of 512, 64 z) —
// 512 CTAs fixes the grid-limited occupancy measured in R14 (occ 21%).
// ---------------------------------------------------------------------------
__global__ __launch_bounds__(256) void k_context()
{
    __shared__ char cxs[34816];
    const uint32_t skB = smem_u32(cxs);
    const uint32_t svB = skB + 17408;
    float* red = (float*)cxs;

    const int ch = blockIdx.x;     // 0..7
    const int z  = blockIdx.y;     // b*4+h
    const int b = z >> 2, h = z & 3;
    const __half* __restrict__ kg = g_keh + ((size_t)b * HID + h * DH) * NP + ch * 512;
    const __half* __restrict__ vg = g_vh  + ((size_t)b * HID + h * DH) * NP + ch * 512;

    const int t = threadIdx.x;
    const int wid = t >> 5, lane = t & 31;

    uint32_t lso[4]; uint32_t lgi[4]; bool lk[4];
    #pragma unroll
    for (int i = 0; i < 4; i++) {
        const int slot = t + i * 256;
        const int s = slot & 511;
        const int r = s >> 4, c = s & 15;
        lso[i] = (uint32_t)r * 272 + c * 16;
        lgi[i] = (uint32_t)r * NP + c * 8;
        lk[i] = slot < 512;
    }

    const int aRow = lane & 15;
    const uint32_t aCol16 = (uint32_t)(lane >> 4) * 16;
    const int bg = lane >> 3, blr = lane & 7;
    const int bRow = (bg >> 1) * 8 + blr;
    const uint32_t bCol16 = (uint32_t)(bg & 1) * 16;
    const uint32_t kbyte = (uint32_t)wid * 32;

    float d[2][4][4];
    #pragma unroll
    for (int mf = 0; mf < 2; mf++)
        #pragma unroll
        for (int nf = 0; nf < 4; nf++)
            #pragma unroll
            for (int r = 0; r < 4; r++) d[mf][nf][r] = 0.f;

    #pragma unroll
    for (int i = 0; i < 4; i++)
        cp16((lk[i] ? skB : svB) + lso[i], (lk[i] ? kg : vg) + lgi[i]);
    cp_commit();

    int buf = 0;
    for (int it = 0; it < 4; it++) {
        __syncthreads();
        if (it + 1 < 4) {
            const uint32_t boff = (uint32_t)(buf ^ 1) * 8704;
            const int n0 = (it + 1) * 128;
            #pragma unroll
            for (int i = 0; i < 4; i++)
                cp16((lk[i] ? skB : svB) + boff + lso[i], (lk[i] ? kg : vg) + lgi[i] + n0);
        }
        cp_commit();
        cp_wait1();
        __syncthreads();
        const uint32_t boff = (uint32_t)buf * 8704;
        uint32_t ra[2][4];
        #pragma unroll
        for (int mf = 0; mf < 2; mf++) {
            const uint32_t addr = skB + boff + (uint32_t)(aRow + mf * 16) * 272 + kbyte + aCol16;
            ldmatrix_x4(ra[mf][0], ra[mf][1], ra[mf][2], ra[mf][3], addr);
        }
        uint32_t rb[4][2];
        #pragma unroll
        for (int nf2 = 0; nf2 < 2; nf2++) {
            uint32_t r0, r1, r2, r3;
            const uint32_t addr = svB + boff + (uint32_t)(bRow + nf2 * 16) * 272 + kbyte + bCol16;
            ldmatrix_x4(r0, r1, r2, r3, addr);
            rb[nf2 * 2][0] = r0;     rb[nf2 * 2][1] = r1;
            rb[nf2 * 2 + 1][0] = r2; rb[nf2 * 2 + 1][1] = r3;
        }
        #pragma unroll
        for (int mf = 0; mf < 2; mf++)
            #pragma unroll
            for (int nf = 0; nf < 4; nf++)
                mma_f16(d[mf][nf], ra[mf], rb[nf]);
        buf ^= 1;
    }
    __syncthreads();

    #pragma unroll
    for (int mf = 0; mf < 2; mf++) {
        #pragma unroll
        for (int nf = 0; nf < 4; nf++) {
            const int m = mf * 16 + (lane >> 2);
            const int n = nf * 8 + (lane & 3) * 2;
            red[wid * 1024 + m * 32 + n]           = d[mf][nf][0];
            red[wid * 1024 + m * 32 + n + 1]       = d[mf][nf][1];
            red[wid * 1024 + (m + 8) * 32 + n]     = d[mf][nf][2];
            red[wid * 1024 + (m + 8) * 32 + n + 1] = d[mf][nf][3];
        }
    }
    __syncthreads();
    float* o = g_ctxp + ((size_t)ch * 64 + z) * 1024;
    #pragma unroll
    for (int i = 0; i < 4; i++) {
        const int idx = t * 4 + i;
        float s = 0.f;
        #pragma unroll
        for (int w = 0; w < 8; w++) s += red[w * 1024 + idx];
        o[idx] = s;
    }
}

// ---------------------------------------------------------------------------
// K4: FUSED attn + out-conv + LayerNorm. ctx 8-chunk reduce inlined into the
// sctx load (g_ctxp is L2-resident).
// ---------------------------------------------------------------------------
__global__ __launch_bounds__(256, 2) void k_attn_out(
    const float* __restrict__ b_out, const float* __restrict__ g, float* __restrict__ out)
{
    __shared__ alignas(128) char smem_raw[83456];
    const uint32_t aBase = smem_u32(smem_raw);
    const uint32_t bBase = aBase + 61440;
    float* sq   = (float*)smem_raw;                 // [128][68]
    float* sctx = (float*)(smem_raw + 34816);       // [4][32][36]
    __half* sbh = (__half*)(smem_raw + 61440);      // [64][136]
    float* ys   = (float*)smem_raw;                 // [256][66]
    float* redS = (float*)(smem_raw + 78848);
    float* redQ = (float*)(smem_raw + 80896);
    float* smu  = (float*)(smem_raw + 82944);
    float* srs  = (float*)(smem_raw + 83200);

    const int t  = threadIdx.x;
    const int p0 = blockIdx.x * 64;
    const int b  = blockIdx.y;

    {
        const float* qb = g_qkv + (size_t)b * HID * NP;
        const int row = t >> 1, hf = (t & 1) * 32;
        #pragma unroll
        for (int j = 0; j < 8; j++) {
            const float4 v = *(const float4*)(qb + (size_t)row * NP + p0 + hf + j * 4);
            const int c = hf + j * 4;
            sq[row * 68 + c] = v.x; sq[row * 68 + c + 1] = v.y;
            sq[row * 68 + c + 2] = v.z; sq[row * 68 + c + 3] = v.w;
        }
        #pragma unroll
        for (int i = 0; i < 16; i++) {
            const int idx = t + i * 256;
            const int h = idx >> 10, ii = idx & 1023;
            const size_t base = (size_t)(b * 4 + h) * 1024 + ii;
            float s = 0.f;
            #pragma unroll
            for (int c = 0; c < 8; c++) s += g_ctxp[(size_t)c * 65536 + base];
            sctx[h * 1152 + (ii >> 5) * 36 + (ii & 31)] = s;
        }
    }
    __syncthreads();

    const int h1 = t >> 6, p1 = t & 63;
    {
        float m = -3.402823e38f;
        #pragma unroll
        for (int d = 0; d < 32; d++) m = fmaxf(m, sq[(h1 * 32 + d) * 68 + p1]);
        float s = 0.f;
        #pragma unroll
        for (int d = 0; d < 32; d++) s += __expf(sq[(h1 * 32 + d) * 68 + p1] - m);
        const float inv = 0.17677669529663687f / s;
        #pragma unroll
        for (int d = 0; d < 32; d++)
            sq[(h1 * 32 + d) * 68 + p1] = __expf(sq[(h1 * 32 + d) * 68 + p1] - m) * inv;
    }
    __syncthreads();

    float acc[32];
    #pragma unroll
    for (int i = 0; i < 32; i++) acc[i] = 0.f;
    #pragma unroll
    for (int d = 0; d < 32; d++) {
        const float qv = sq[(h1 * 32 + d) * 68 + p1];
        const float* cr = sctx + h1 * 1152 + d * 36;
        #pragma unroll
        for (int e4 = 0; e4 < 8; e4++) {
            const float4 cv = *(const float4*)(cr + e4 * 4);
            acc[e4 * 4 + 0] += cv.x * qv;
            acc[e4 * 4 + 1] += cv.y * qv;
            acc[e4 * 4 + 2] += cv.z * qv;
            acc[e4 * 4 + 3] += cv.w * qv;
        }
    }
    __syncthreads();

    const uint32_t ABUF = 20480;
    const int a_r = t >> 2, a_ch = t & 3;
    #pragma unroll
    for (int s = 0; s < 2; s++) {
        const int k0 = s * 32;
        #pragma unroll
        for (int i = 0; i < 4; i++) {
            const int row = a_r + i * 64;
            cp16(aBase + (uint32_t)s * ABUF + (uint32_t)row * 80 + a_ch * 16,
                 g_woh + (size_t)row * 128 + k0 + a_ch * 8);
        }
        cp_commit();
    }
    {
        union { __half h[32]; uint4 u[4]; } hb;
        #pragma unroll
        for (int i = 0; i < 32; i++) hb.h[i] = __float2half(acc[i]);
        uint4* dst = (uint4*)(sbh + p1 * 136 + h1 * 32);
        dst[0] = hb.u[0]; dst[1] = hb.u[1]; dst[2] = hb.u[2]; dst[3] = hb.u[3];
    }

    const int wid = t >> 5, lane = t & 31;
    const int warp_m = wid >> 1, warp_n = wid & 1;
    const int aRowL = warp_m * 64 + (lane & 15);
    const uint32_t aCol16 = (uint32_t)(lane >> 4) * 16;
    const int bg = lane >> 3, blr = lane & 7;
    const int bRowL = warp_n * 32 + (bg >> 1) * 8 + blr;
    const uint32_t bCol16 = (uint32_t)(bg & 1) * 16;

    float d[4][4][4];
    #pragma unroll
    for (int mf = 0; mf < 4; mf++)
        #pragma unroll
        for (int nf = 0; nf < 4; nf++)
            #pragma unroll
            for (int r = 0; r < 4; r++) d[mf][nf][r] = 0.f;

    int buf = 0;
    for (int it = 0; it < 4; it++) {
        cp_wait1();
        __syncthreads();
        if (it + 2 < 4) {
            int nb = buf + 2; if (nb >= 3) nb -= 3;
            const int k0 = (it + 2) * 32;
            #pragma unroll
            for (int i = 0; i < 4; i++) {
                const int row = a_r + i * 64;
                cp16(aBase + (uint32_t)nb * ABUF + (uint32_t)row * 80 + a_ch * 16,
                     g_woh + (size_t)row * 128 + k0 + a_ch * 8);
            }
        }
        cp_commit();
        const uint32_t ab = aBase + (uint32_t)buf * ABUF;
        #pragma unroll
        for (int ks = 0; ks < 2; ks++) {
            const int kslot = it * 2 + ks;
            uint32_t rb[4][2];
            #pragma unroll
            for (int nf2 = 0; nf2 < 2; nf2++) {
                uint32_t r0, r1, r2, r3;
                const uint32_t addr = bBase + (uint32_t)(bRowL + nf2 * 16) * 272
                                    + kslot * 32 + bCol16;
                ldmatrix_x4(r0, r1, r2, r3, addr);
                rb[nf2 * 2][0] = r0;     rb[nf2 * 2][1] = r1;
                rb[nf2 * 2 + 1][0] = r2; rb[nf2 * 2 + 1][1] = r3;
            }
            uint32_t ra[4][4];
            #pragma unroll
            for (int mf = 0; mf < 4; mf++) {
                const uint32_t addr = ab + (uint32_t)(aRowL + mf * 16) * 80 + ks * 32 + aCol16;
                ldmatrix_x4(ra[mf][0], ra[mf][1], ra[mf][2], ra[mf][3], addr);
            }
            #pragma unroll
            for (int mf = 0; mf < 4; mf++)
                #pragma unroll
                for (int nf = 0; nf < 4; nf++)
                    mma_f16(d[mf][nf], ra[mf], rb[nf]);
        }
        buf++; if (buf == 3) buf = 0;
    }
    __syncthreads();

    const int mB = warp_m * 64 + (lane >> 2);
    const int nB = warp_n * 32 + (lane & 3) * 2;
    #pragma unroll
    for (int mf = 0; mf < 4; mf++) {
        #pragma unroll
        for (int nf = 0; nf < 4; nf++) {
            const int m = mB + mf * 16;
            const int n = nB + nf * 8;
            const float bo0 = b_out[m], bo1 = b_out[m + 8];
            ys[m * 66 + n]           = d[mf][nf][0] + bo0;
            ys[m * 66 + n + 1]       = d[mf][nf][1] + bo0;
            ys[(m + 8) * 66 + n]     = d[mf][nf][2] + bo1;
            ys[(m + 8) * 66 + n + 1] = d[mf][nf][3] + bo1;
        }
    }
    __syncthreads();
    {
        float s0 = 0.f, q0 = 0.f, s1 = 0.f, q1 = 0.f;
        #pragma unroll
        for (int c = 0; c < 32; c++) {
            const float v0 = ys[(wid * 32 + c) * 66 + lane];
            const float v1 = ys[(wid * 32 + c) * 66 + lane + 32];
            s0 += v0; q0 += v0 * v0;
            s1 += v1; q1 += v1 * v1;
        }
        redS[wid * 64 + lane] = s0;      redQ[wid * 64 + lane] = q0;
        redS[wid * 64 + lane + 32] = s1; redQ[wid * 64 + lane + 32] = q1;
    }
    __syncthreads();
    if (t < 64) {
        float s = 0.f, q = 0.f;
        #pragma unroll
        for (int w = 0; w < 8; w++) { s += redS[w * 64 + t]; q += redQ[w * 64 + t]; }
        const float mu  = s * (1.f / 256.f);
        const float var = q * (1.f / 256.f) - mu * mu;
        smu[t] = mu;
        srs[t] = rsqrtf(var + 1e-5f);
    }
    __syncthreads();
    {
        const int n2 = t & 63;
        const float mu = smu[n2], rs = srs[n2];
        float* ob = out + (size_t)b * C_ * NP + p0 + n2;
        for (int o = t >> 6; o < C_; o += 4) {
            ob[(size_t)o * NP] = (ys[o * 66 + n2] - mu) * rs * g[o];
        }
    }
}

// ---------------------------------------------------------------------------
extern "C" void kernel_launch(void* const* d_in, const int* in_sizes, int n_in,
                              void* d_out, int out_size)
{
    const float* x     = (const float*)d_in[0];
    const float* w_qkv = (const float*)d_in[1];
    const float* w_out = (const float*)d_in[2];
    const float* b_out = (const float*)d_in[3];
    const float* g     = (const float*)d_in[4];
    float* out = (float*)d_out;
    (void)in_sizes; (void)n_in; (void)out_size;

    k_conv_all<<<4608, 256>>>(x, w_qkv, w_out);
    k_qkv_mma<<<dim3(32, 3, 16), 256>>>();
    k_kstats<<<2048, 256>>>();
    k_context<<<dim3(8, 64), 256>>>();
    k_attn_out<<<dim3(64, 16), 256>>>(b_out, g, out);
}